// round 2
// baseline (speedup 1.0000x reference)
#include <cuda_runtime.h>
#include <math.h>

#define NTN   65536
#define NBATCH 32
#define NPERG 2048
#define NFEAT 128
#define NCLS  10
#define NEGV  (-1e9f)
#define ETOTMAX (NTN * 16 + NTN)   // 1,114,112 edges incl self loops

// ---------------- scratch (device globals; no allocation allowed) ----------
__device__ float g_x0[NTN * NFEAT];   // normalized input
__device__ float g_h [NTN * 48];      // per-conv linear output (max HC=48)
__device__ float g_oa[NTN * 48];      // ping buffer
__device__ float g_ob[NTN * 48];      // pong buffer
__device__ float g_als[NTN * 3];      // attention logits (src side), max H=3
__device__ float g_ald[NTN * 3];      // attention logits (dst side)
__device__ float g_m  [NTN * 3];      // segment max per (node, head)
__device__ float g_den[NTN * 3];      // segment sum of exp per (node, head)
__device__ float g_e  [ETOTMAX * 3];  // per-(edge,head) logit, then exp value
__device__ float g_score[NTN];        // topk raw scores
__device__ int   g_nmask[NTN];        // node mask
__device__ float g_sum  [NFEAT];      // BN stats
__device__ float g_sumsq[NFEAT];

// ---------------- helpers ----------------
__device__ __forceinline__ float lrelu(float v) { return v > 0.f ? v : 0.2f * v; }

__device__ __forceinline__ void atomicMaxF(float* addr, float v) {
    int old = __float_as_int(*addr);
    while (__int_as_float(old) < v) {
        int assumed = old;
        old = atomicCAS((int*)addr, assumed, __float_as_int(v));
        if (old == assumed) break;
    }
}

__device__ __forceinline__ void red_add_v4(float* p, float4 v) {
    asm volatile("red.global.add.v4.f32 [%0], {%1,%2,%3,%4};"
                 :: "l"(p), "f"(v.x), "f"(v.y), "f"(v.z), "f"(v.w) : "memory");
}
__device__ __forceinline__ void red_add_v2(float* p, float2 v) {
    asm volatile("red.global.add.v2.f32 [%0], {%1,%2};"
                 :: "l"(p), "f"(v.x), "f"(v.y) : "memory");
}

// ---------------- BatchNorm ----------------
__global__ void k_zero_stats() {
    int t = threadIdx.x;
    g_sum[t] = 0.f; g_sumsq[t] = 0.f;
}

__global__ void k_stats(const float* __restrict__ x) {
    int f = threadIdx.x;                      // 128 threads = 128 features
    int rows = NTN / gridDim.x;
    int r0 = blockIdx.x * rows;
    float s = 0.f, s2 = 0.f;
    for (int r = r0; r < r0 + rows; ++r) {
        float v = x[r * NFEAT + f];
        s += v; s2 += v * v;
    }
    atomicAdd(&g_sum[f], s);
    atomicAdd(&g_sumsq[f], s2);
}

__global__ void k_bn(const float* __restrict__ x, const float* __restrict__ gamma,
                     const float* __restrict__ beta) {
    int idx = blockIdx.x * blockDim.x + threadIdx.x;
    if (idx >= NTN * NFEAT) return;
    int f = idx & (NFEAT - 1);
    float mu  = g_sum[f]   * (1.f / NTN);
    float var = g_sumsq[f] * (1.f / NTN) - mu * mu;
    g_x0[idx] = (x[idx] - mu) * rsqrtf(var + 1e-5f) * gamma[f] + beta[f];
}

__global__ void k_initmask() {
    int i = blockIdx.x * blockDim.x + threadIdx.x;
    if (i < NTN) g_nmask[i] = 1;
}

// ---------------- GAT conv pieces ----------------
// h = x @ W   (W staged in shared memory)
__global__ void k_linear(const float* __restrict__ xin, const float* __restrict__ W,
                         float* __restrict__ h, int Fin, int HC) {
    extern __shared__ float Ws[];
    int tot = Fin * HC;
    for (int i = threadIdx.x; i < tot; i += blockDim.x) Ws[i] = W[i];
    __syncthreads();
    int idx = blockIdx.x * blockDim.x + threadIdx.x;
    if (idx >= NTN * HC) return;
    int row = idx / HC, j = idx % HC;
    const float* xr = xin + row * Fin;
    float acc = 0.f;
    for (int i = 0; i < Fin; ++i) acc += xr[i] * Ws[i * HC + j];
    h[idx] = acc;
}

// al_s[n,h] = sum_c h[n,h,c]*a_src[h,c]; similarly al_d
__global__ void k_alogits(const float* __restrict__ h, const float* __restrict__ as_,
                          const float* __restrict__ ad_, int H, int C) {
    int idx = blockIdx.x * blockDim.x + threadIdx.x;
    if (idx >= NTN * H) return;
    int n = idx / H, hh = idx % H;
    const float* hp = h + n * H * C + hh * C;
    float s = 0.f, d = 0.f;
    for (int c = 0; c < C; ++c) {
        float v = hp[c];
        s += v * as_[hh * C + c];
        d += v * ad_[hh * C + c];
    }
    g_als[idx] = s;
    g_ald[idx] = d;
}

__global__ void k_initout(float* __restrict__ out, const float* __restrict__ b, int HC) {
    int idx = blockIdx.x * blockDim.x + threadIdx.x;
    if (idx < NTN * HC) out[idx] = b[idx % HC];
}

__global__ void k_initmden(int H) {
    int idx = blockIdx.x * blockDim.x + threadIdx.x;
    if (idx < NTN * H) { g_m[idx] = NEGV; g_den[idx] = 0.f; }
}

// pass 1: per-(edge,head) logit; cache in g_e; segment max over dst
__global__ void k_emax(const int* __restrict__ src, const int* __restrict__ dst,
                       int E, int Etot, int H) {
    int idx = blockIdx.x * blockDim.x + threadIdx.x;
    if (idx >= Etot * H) return;
    int e = idx / H, hh = idx - e * H;
    int s, d;
    if (e < E) { s = src[e]; d = dst[e]; } else { s = e - E; d = s; }
    if (!(g_nmask[s] && g_nmask[d])) { g_e[idx] = NEGV; return; }
    float v = lrelu(g_als[s * H + hh] + g_ald[d * H + hh]);
    g_e[idx] = v;
    atomicMaxF(&g_m[d * H + hh], v);
}

// pass 2: ex = exp(e - m[d]); cache ex in g_e; den[d] += ex
__global__ void k_eden(const int* __restrict__ dst, int E, int Etot, int H) {
    int idx = blockIdx.x * blockDim.x + threadIdx.x;
    if (idx >= Etot * H) return;
    float v = g_e[idx];
    if (v == NEGV) { g_e[idx] = 0.f; return; }
    int e = idx / H, hh = idx - e * H;
    int d = (e < E) ? dst[e] : (e - E);
    float ex = __expf(v - g_m[d * H + hh]);
    g_e[idx] = ex;
    atomicAdd(&g_den[d * H + hh], ex);
}

// pass 3 (vectorized, C%4==0): out[dst, c0..c0+3] += alpha * h[src, c0..c0+3]
__global__ void k_eagg4(const int* __restrict__ src, const int* __restrict__ dst,
                        int E, int Etot, int H, int C,
                        const float* __restrict__ h, float* __restrict__ out) {
    int HC = H * C;
    int V = HC >> 2;                         // float4 vectors per edge
    int idx = blockIdx.x * blockDim.x + threadIdx.x;
    if (idx >= Etot * V) return;
    int e = idx / V, vi = idx - e * V;
    int c0 = vi << 2;
    int hh = c0 / C;
    float ex = g_e[e * H + hh];
    if (ex == 0.f) return;
    int s, d;
    if (e < E) { s = src[e]; d = dst[e]; } else { s = e - E; d = s; }
    float alpha = ex / fmaxf(g_den[d * H + hh], 1e-16f);
    float4 hv = *(const float4*)(h + s * HC + c0);
    hv.x *= alpha; hv.y *= alpha; hv.z *= alpha; hv.w *= alpha;
    red_add_v4(out + d * HC + c0, hv);
}

// pass 3 (float2 variant for HC=10)
__global__ void k_eagg2(const int* __restrict__ src, const int* __restrict__ dst,
                        int E, int Etot, int H, int C,
                        const float* __restrict__ h, float* __restrict__ out) {
    int HC = H * C;
    int V = HC >> 1;                         // float2 vectors per edge
    int idx = blockIdx.x * blockDim.x + threadIdx.x;
    if (idx >= Etot * V) return;
    int e = idx / V, vi = idx - e * V;
    int c0 = vi << 1;
    int hh = c0 / C;
    float ex = g_e[e * H + hh];
    if (ex == 0.f) return;
    int s, d;
    if (e < E) { s = src[e]; d = dst[e]; } else { s = e - E; d = s; }
    float alpha = ex / fmaxf(g_den[d * H + hh], 1e-16f);
    float2 hv = *(const float2*)(h + s * HC + c0);
    hv.x *= alpha; hv.y *= alpha;
    red_add_v2(out + d * HC + c0, hv);
}

// ---------------- TopK pooling ----------------
// one block per graph; bitonic sort of masked scores; exact top-k with
// index-order tie handling (matches jax.lax.top_k semantics)
__global__ void k_topk(float* __restrict__ x, const float* __restrict__ p,
                       int F, int kkeep) {
    __shared__ float ss[NPERG];
    __shared__ int   skeep[NPERG];
    __shared__ int   s_gt;
    int g = blockIdx.x;
    int base = g * NPERG;

    float nrm = 0.f;
    for (int i = 0; i < F; ++i) { float pv = p[i]; nrm += pv * pv; }
    nrm = sqrtf(nrm);

    for (int n = threadIdx.x; n < NPERG; n += blockDim.x) {
        int node = base + n;
        const float* xr = x + node * F;
        float sc = 0.f;
        for (int i = 0; i < F; ++i) sc += xr[i] * p[i];
        sc /= nrm;
        g_score[node] = sc;
        ss[n] = g_nmask[node] ? sc : NEGV;
    }
    __syncthreads();

    // bitonic sort ascending over NPERG elements
    for (int kk = 2; kk <= NPERG; kk <<= 1) {
        for (int j = kk >> 1; j > 0; j >>= 1) {
            for (int i = threadIdx.x; i < NPERG; i += blockDim.x) {
                int ixj = i ^ j;
                if (ixj > i) {
                    float a = ss[i], b = ss[ixj];
                    bool up = ((i & kk) == 0);
                    if ((a > b) == up) { ss[i] = b; ss[ixj] = a; }
                }
            }
            __syncthreads();
        }
    }

    float thr = ss[NPERG - kkeep];
    if (threadIdx.x == 0) {
        int gt = 0;
        for (int i = NPERG - kkeep; i < NPERG; ++i) gt += (ss[i] > thr);
        s_gt = gt;
    }
    __syncthreads();

    if (threadIdx.x == 0) {
        int need_eq = kkeep - s_gt;
        int eq = 0;
        for (int n = 0; n < NPERG; ++n) {
            int node = base + n;
            float sc = g_nmask[node] ? g_score[node] : NEGV;
            int keep = 0;
            if (sc > thr) keep = 1;
            else if (sc == thr && eq < need_eq) { keep = 1; ++eq; }
            skeep[n] = keep;
            g_nmask[node] = keep;
        }
    }
    __syncthreads();

    for (int n = threadIdx.x; n < NPERG; n += blockDim.x) {
        int node = base + n;
        float f = skeep[n] ? tanhf(g_score[node]) : 0.f;
        float* xr = x + node * F;
        for (int i = 0; i < F; ++i) xr[i] *= f;
    }
}

// ---------------- final mean + log_softmax ----------------
__global__ void k_final(const float* __restrict__ x, float* __restrict__ out) {
    __shared__ float red[NCLS][9];   // up to 8 warps
    int g = blockIdx.x;
    int base = g * NPERG;
    float acc[NCLS];
    for (int c = 0; c < NCLS; ++c) acc[c] = 0.f;
    for (int n = threadIdx.x; n < NPERG; n += blockDim.x) {
        const float* xr = x + (base + n) * NCLS;
        for (int c = 0; c < NCLS; ++c) acc[c] += xr[c];
    }
    for (int off = 16; off; off >>= 1)
        for (int c = 0; c < NCLS; ++c)
            acc[c] += __shfl_down_sync(0xffffffffu, acc[c], off);
    int lane = threadIdx.x & 31, wid = threadIdx.x >> 5;
    if (lane == 0)
        for (int c = 0; c < NCLS; ++c) red[c][wid] = acc[c];
    __syncthreads();
    if (threadIdx.x == 0) {
        int nw = blockDim.x / 32;
        float z[NCLS];
        for (int c = 0; c < NCLS; ++c) {
            float s = 0.f;
            for (int w = 0; w < nw; ++w) s += red[c][w];
            z[c] = s * (1.f / (NPERG / 4));
        }
        float mx = z[0];
        for (int c = 1; c < NCLS; ++c) mx = fmaxf(mx, z[c]);
        float se = 0.f;
        for (int c = 0; c < NCLS; ++c) se += expf(z[c] - mx);
        float lse = logf(se) + mx;
        for (int c = 0; c < NCLS; ++c) out[g * NCLS + c] = z[c] - lse;
    }
}

// ---------------- host orchestration ----------------
static void run_conv(const float* xin, int Fin, int H, int C,
                     const float* W, const float* as_, const float* ad_, const float* b,
                     float* out, float* h,
                     const int* src, const int* dst, int E, int Etot) {
    int HC = H * C;
    k_linear<<<(NTN * HC + 255) / 256, 256, Fin * HC * (int)sizeof(float)>>>(xin, W, h, Fin, HC);
    k_alogits<<<(NTN * H + 255) / 256, 256>>>(h, as_, ad_, H, C);
    k_initout<<<(NTN * HC + 255) / 256, 256>>>(out, b, HC);
    k_initmden<<<(NTN * H + 255) / 256, 256>>>(H);
    int ehb = (Etot * H + 255) / 256;
    k_emax<<<ehb, 256>>>(src, dst, E, Etot, H);
    k_eden<<<ehb, 256>>>(dst, E, Etot, H);
    if ((C & 3) == 0) {
        int V = HC >> 2;
        k_eagg4<<<((long long)Etot * V + 255) / 256, 256>>>(src, dst, E, Etot, H, C, h, out);
    } else {
        int V = HC >> 1;
        k_eagg2<<<((long long)Etot * V + 255) / 256, 256>>>(src, dst, E, Etot, H, C, h, out);
    }
}

extern "C" void kernel_launch(void* const* d_in, const int* in_sizes, int n_in,
                              void* d_out, int out_size) {
    const float* x     = (const float*)d_in[0];
    const int*   ei    = (const int*)  d_in[1];
    // d_in[2] = batch (unused: nodes are contiguous per graph)
    const float* gamma = (const float*)d_in[3];
    const float* beta  = (const float*)d_in[4];
    const float* W1  = (const float*)d_in[5];
    const float* as1 = (const float*)d_in[6];
    const float* ad1 = (const float*)d_in[7];
    const float* b1  = (const float*)d_in[8];
    const float* W2  = (const float*)d_in[9];
    const float* as2 = (const float*)d_in[10];
    const float* ad2 = (const float*)d_in[11];
    const float* b2  = (const float*)d_in[12];
    const float* W3  = (const float*)d_in[13];
    const float* as3 = (const float*)d_in[14];
    const float* ad3 = (const float*)d_in[15];
    const float* b3  = (const float*)d_in[16];
    const float* W4  = (const float*)d_in[17];
    const float* as4 = (const float*)d_in[18];
    const float* ad4 = (const float*)d_in[19];
    const float* b4  = (const float*)d_in[20];
    const float* p1  = (const float*)d_in[21];
    const float* p2  = (const float*)d_in[22];

    int E = in_sizes[1] / 2;
    const int* src = ei;
    const int* dst = ei + E;
    int Etot = E + NTN;

    float *x0, *h, *oa, *ob;
    cudaGetSymbolAddress((void**)&x0, g_x0);
    cudaGetSymbolAddress((void**)&h,  g_h);
    cudaGetSymbolAddress((void**)&oa, g_oa);
    cudaGetSymbolAddress((void**)&ob, g_ob);

    // BatchNorm (training-mode batch stats) + mask init
    k_zero_stats<<<1, 128>>>();
    k_stats<<<64, 128>>>(x);
    k_bn<<<(NTN * NFEAT) / 256, 256>>>(x, gamma, beta);
    k_initmask<<<NTN / 256, 256>>>();

    // conv1: 128 -> 3x16
    run_conv(x0, NFEAT, 3, 16, W1, as1, ad1, b1, oa, h, src, dst, E, Etot);
    // conv2: 48 -> 3x16
    run_conv(oa, 48, 3, 16, W2, as2, ad2, b2, ob, h, src, dst, E, Etot);
    // pool1: keep 1024/graph
    k_topk<<<NBATCH, 1024>>>(ob, p1, 48, NPERG / 2);
    // conv3: 48 -> 2x16
    run_conv(ob, 48, 2, 16, W3, as3, ad3, b3, oa, h, src, dst, E, Etot);
    // conv4: 32 -> 1x10
    run_conv(oa, 32, 1, 10, W4, as4, ad4, b4, ob, h, src, dst, E, Etot);
    // pool2: keep 512/graph
    k_topk<<<NBATCH, 1024>>>(ob, p2, 10, NPERG / 4);
    // mean pool + log_softmax
    k_final<<<NBATCH, 256>>>(ob, (float*)d_out);
}

// round 3
// speedup vs baseline: 1.1992x; 1.1992x over previous
#include <cuda_runtime.h>
#include <math.h>

#define NTN   65536
#define NBATCH 32
#define NPERG 2048
#define NFEAT 128
#define NCLS  10
#define NEGV  (-1e9f)
#define ETOTMAX (NTN * 16 + NTN)   // 1,114,112 edges incl self loops

// ---------------- scratch (device globals; no allocation allowed) ----------
__device__ float g_x0[NTN * NFEAT];   // normalized input
__device__ float g_h [NTN * 48];      // per-conv linear output (max HC=48)
__device__ float g_oa[NTN * 48];      // ping buffer
__device__ float g_ob[NTN * 48];      // pong buffer
__device__ float g_als[NTN * 3];      // attention logits (src side), max H=3
__device__ float g_ald[NTN * 3];      // attention logits (dst side)
__device__ float g_score[NTN];        // topk raw scores
__device__ int   g_nmask[NTN];        // node mask
__device__ float g_sum  [NFEAT];      // BN stats
__device__ float g_sumsq[NFEAT];
// CSR (built once per launch)
__device__ int g_deg [NTN];
__device__ int g_off [NTN + 1];
__device__ int g_cur [NTN];
__device__ int g_bsum[256];
__device__ int g_bsex[256];
__device__ int g_csrc[ETOTMAX];

// ---------------- helpers ----------------
__device__ __forceinline__ float lrelu(float v) { return v > 0.f ? v : 0.2f * v; }

// ---------------- BatchNorm ----------------
__global__ void k_zero_stats() {
    int t = threadIdx.x;
    g_sum[t] = 0.f; g_sumsq[t] = 0.f;
}

__global__ void k_stats(const float* __restrict__ x) {
    int f = threadIdx.x;                      // 128 threads = 128 features
    int rows = NTN / gridDim.x;
    int r0 = blockIdx.x * rows;
    float s = 0.f, s2 = 0.f;
    for (int r = r0; r < r0 + rows; ++r) {
        float v = x[r * NFEAT + f];
        s += v; s2 += v * v;
    }
    atomicAdd(&g_sum[f], s);
    atomicAdd(&g_sumsq[f], s2);
}

__global__ void k_bn(const float* __restrict__ x, const float* __restrict__ gamma,
                     const float* __restrict__ beta) {
    int idx = blockIdx.x * blockDim.x + threadIdx.x;
    if (idx >= NTN * NFEAT) return;
    int f = idx & (NFEAT - 1);
    float mu  = g_sum[f]   * (1.f / NTN);
    float var = g_sumsq[f] * (1.f / NTN) - mu * mu;
    g_x0[idx] = (x[idx] - mu) * rsqrtf(var + 1e-5f) * gamma[f] + beta[f];
}

__global__ void k_initmask() {
    int i = blockIdx.x * blockDim.x + threadIdx.x;
    if (i < NTN) g_nmask[i] = 1;
}

// ---------------- CSR build (counting sort by dst) ----------------
__global__ void k_deg_zero() {
    int i = blockIdx.x * blockDim.x + threadIdx.x;
    if (i < NTN) g_deg[i] = 0;
}

__global__ void k_deg_count(const int* __restrict__ dst, int E, int Etot) {
    int e = blockIdx.x * blockDim.x + threadIdx.x;
    if (e >= Etot) return;
    int d = (e < E) ? dst[e] : (e - E);
    atomicAdd(&g_deg[d], 1);
}

__global__ void k_scan_block() {            // 256 blocks x 256 threads
    __shared__ int sh[256];
    int n = blockIdx.x * 256 + threadIdx.x;
    int v = g_deg[n];
    sh[threadIdx.x] = v;
    __syncthreads();
    for (int o = 1; o < 256; o <<= 1) {
        int t = (threadIdx.x >= o) ? sh[threadIdx.x - o] : 0;
        __syncthreads();
        sh[threadIdx.x] += t;
        __syncthreads();
    }
    g_off[n] = sh[threadIdx.x] - v;         // exclusive within block
    if (threadIdx.x == 255) g_bsum[blockIdx.x] = sh[255];
}

__global__ void k_scan_top() {              // 1 block x 256 threads
    __shared__ int sh[256];
    int v = g_bsum[threadIdx.x];
    sh[threadIdx.x] = v;
    __syncthreads();
    for (int o = 1; o < 256; o <<= 1) {
        int t = (threadIdx.x >= o) ? sh[threadIdx.x - o] : 0;
        __syncthreads();
        sh[threadIdx.x] += t;
        __syncthreads();
    }
    g_bsex[threadIdx.x] = sh[threadIdx.x] - v;
}

__global__ void k_scan_add(int Etot) {      // 256 blocks x 256 threads
    int n = blockIdx.x * 256 + threadIdx.x;
    int o = g_off[n] + g_bsex[blockIdx.x];
    g_off[n] = o;
    g_cur[n] = o;
    if (n == 0) g_off[NTN] = Etot;
}

__global__ void k_scatter(const int* __restrict__ src, const int* __restrict__ dst,
                          int E, int Etot) {
    int e = blockIdx.x * blockDim.x + threadIdx.x;
    if (e >= Etot) return;
    int s, d;
    if (e < E) { s = src[e]; d = dst[e]; } else { s = e - E; d = s; }
    int pos = atomicAdd(&g_cur[d], 1);
    g_csrc[pos] = s;
}

// ---------------- GAT conv pieces ----------------
// h = x @ W   (W staged in shared memory)
__global__ void k_linear(const float* __restrict__ xin, const float* __restrict__ W,
                         float* __restrict__ h, int Fin, int HC) {
    extern __shared__ float Ws[];
    int tot = Fin * HC;
    for (int i = threadIdx.x; i < tot; i += blockDim.x) Ws[i] = W[i];
    __syncthreads();
    int idx = blockIdx.x * blockDim.x + threadIdx.x;
    if (idx >= NTN * HC) return;
    int row = idx / HC, j = idx % HC;
    const float* xr = xin + row * Fin;
    float acc = 0.f;
    for (int i = 0; i < Fin; ++i) acc += xr[i] * Ws[i * HC + j];
    h[idx] = acc;
}

// al_s[n,h] = sum_c h[n,h,c]*a_src[h,c]; similarly al_d
__global__ void k_alogits(const float* __restrict__ h, const float* __restrict__ as_,
                          const float* __restrict__ ad_, int H, int C) {
    int idx = blockIdx.x * blockDim.x + threadIdx.x;
    if (idx >= NTN * H) return;
    int n = idx / H, hh = idx % H;
    const float* hp = h + n * H * C + hh * C;
    float s = 0.f, d = 0.f;
    for (int c = 0; c < C; ++c) {
        float v = hp[c];
        s += v * as_[hh * C + c];
        d += v * ad_[hh * C + c];
    }
    g_als[idx] = s;
    g_ald[idx] = d;
}

// Fused attention softmax + aggregation: one warp per dst node, no atomics.
// LPC = channels per lane (ceil(HC/32)).
template <int H, int C, int LPC>
__global__ void k_gat(const float* __restrict__ h, const float* __restrict__ b,
                      float* __restrict__ out) {
    constexpr int HC = H * C;
    int w = (blockIdx.x * blockDim.x + threadIdx.x) >> 5;
    if (w >= NTN) return;
    int lane = threadIdx.x & 31;
    int d = w;
    int beg = g_off[d], end = g_off[d + 1];
    bool dmask = g_nmask[d] != 0;

    float m[H], den[H], ald_d[H];
    #pragma unroll
    for (int hh = 0; hh < H; ++hh) {
        m[hh] = NEGV; den[hh] = 0.f;
        ald_d[hh] = g_ald[d * H + hh];
    }

    if (dmask) {
        // phase A: online softmax stats per head, lanes stride edges
        for (int i = beg + lane; i < end; i += 32) {
            int s = g_csrc[i];
            if (!g_nmask[s]) continue;
            #pragma unroll
            for (int hh = 0; hh < H; ++hh) {
                float v = lrelu(g_als[s * H + hh] + ald_d[hh]);
                if (v <= m[hh]) {
                    den[hh] += __expf(v - m[hh]);
                } else {
                    den[hh] = den[hh] * __expf(m[hh] - v) + 1.f;
                    m[hh] = v;
                }
            }
        }
        // butterfly combine across warp
        #pragma unroll
        for (int o = 16; o; o >>= 1) {
            #pragma unroll
            for (int hh = 0; hh < H; ++hh) {
                float mo = __shfl_xor_sync(0xffffffffu, m[hh], o);
                float eo = __shfl_xor_sync(0xffffffffu, den[hh], o);
                float nm = fmaxf(m[hh], mo);
                den[hh] = den[hh] * __expf(m[hh] - nm) + eo * __expf(mo - nm);
                m[hh] = nm;
            }
        }
    }

    float invden[H];
    #pragma unroll
    for (int hh = 0; hh < H; ++hh) invden[hh] = 1.f / fmaxf(den[hh], 1e-16f);

    // phase B: accumulate channels; lanes own channels, edges serial
    float acc[LPC];
    #pragma unroll
    for (int q = 0; q < LPC; ++q) acc[q] = 0.f;

    if (dmask) {
        for (int i = beg; i < end; ++i) {
            int s = g_csrc[i];                 // broadcast
            if (!g_nmask[s]) continue;
            #pragma unroll
            for (int q = 0; q < LPC; ++q) {
                int c = lane + q * 32;
                if (HC % 32 != 0 && c >= HC) continue;
                int hh = c / C;
                float v = lrelu(g_als[s * H + hh] + ald_d[hh]);
                float alpha = __expf(v - m[hh]) * invden[hh];
                acc[q] += alpha * h[s * HC + c];
            }
        }
    }

    #pragma unroll
    for (int q = 0; q < LPC; ++q) {
        int c = lane + q * 32;
        if (c < HC) out[d * HC + c] = acc[q] + b[c];
    }
}

// ---------------- TopK pooling ----------------
// one block per graph (1024 threads); bitonic sort; binary-search threshold;
// parallel prefix-scan for index-ordered tie handling (jax.lax.top_k semantics)
__global__ void k_topk(float* __restrict__ x, const float* __restrict__ p,
                       int F, int kkeep) {
    __shared__ float ss[NPERG];
    __shared__ int   wsum[32];
    __shared__ int   wsex[32];
    __shared__ float s_thr;
    __shared__ int   s_need;
    int g = blockIdx.x;
    int base = g * NPERG;
    int tid = threadIdx.x;
    int lane = tid & 31, wid = tid >> 5;

    float nrm = 0.f;
    for (int i = 0; i < F; ++i) { float pv = p[i]; nrm += pv * pv; }
    nrm = rsqrtf(nrm);

    for (int n = tid; n < NPERG; n += blockDim.x) {
        int node = base + n;
        const float* xr = x + node * F;
        float sc = 0.f;
        for (int i = 0; i < F; ++i) sc += xr[i] * p[i];
        sc *= nrm;
        g_score[node] = sc;
        ss[n] = g_nmask[node] ? sc : NEGV;
    }
    __syncthreads();

    // bitonic sort ascending
    for (int kk = 2; kk <= NPERG; kk <<= 1) {
        for (int j = kk >> 1; j > 0; j >>= 1) {
            for (int i = tid; i < NPERG; i += blockDim.x) {
                int ixj = i ^ j;
                if (ixj > i) {
                    float a = ss[i], bb = ss[ixj];
                    bool up = ((i & kk) == 0);
                    if ((a > bb) == up) { ss[i] = bb; ss[ixj] = a; }
                }
            }
            __syncthreads();
        }
    }

    if (tid == 0) {
        float thr = ss[NPERG - kkeep];
        // first index in [NPERG-kkeep, NPERG) with ss[i] > thr
        int lo = NPERG - kkeep, hi = NPERG;
        while (lo < hi) {
            int mid = (lo + hi) >> 1;
            if (ss[mid] > thr) hi = mid; else lo = mid + 1;
        }
        s_thr = thr;
        s_need = kkeep - (NPERG - lo);   // ties to keep (by lowest index)
    }
    __syncthreads();
    float thr = s_thr;
    int need_eq = s_need;

    // per-thread: 2 consecutive elements; block scan of tie flags
    int n0 = tid * 2, n1 = n0 + 1;
    float sc0 = g_nmask[base + n0] ? g_score[base + n0] : NEGV;
    float sc1 = g_nmask[base + n1] ? g_score[base + n1] : NEGV;
    int f0 = (sc0 == thr) ? 1 : 0;
    int f1 = (sc1 == thr) ? 1 : 0;
    int lsum = f0 + f1;
    int incl = lsum;
    #pragma unroll
    for (int o = 1; o < 32; o <<= 1) {
        int t = __shfl_up_sync(0xffffffffu, incl, o);
        if (lane >= o) incl += t;
    }
    if (lane == 31) wsum[wid] = incl;
    __syncthreads();
    if (wid == 0) {
        int v = wsum[lane];
        int inc2 = v;
        #pragma unroll
        for (int o = 1; o < 32; o <<= 1) {
            int t = __shfl_up_sync(0xffffffffu, inc2, o);
            if (lane >= o) inc2 += t;
        }
        wsex[lane] = inc2 - v;
    }
    __syncthreads();
    int rank0 = wsex[wid] + (incl - lsum);
    int rank1 = rank0 + f0;

    int keep0 = (sc0 > thr) || (f0 && rank0 < need_eq);
    int keep1 = (sc1 > thr) || (f1 && rank1 < need_eq);

    g_nmask[base + n0] = keep0;
    g_nmask[base + n1] = keep1;
    float t0 = keep0 ? tanhf(g_score[base + n0]) : 0.f;
    float t1 = keep1 ? tanhf(g_score[base + n1]) : 0.f;
    float* xr0 = x + (base + n0) * F;
    float* xr1 = x + (base + n1) * F;
    for (int i = 0; i < F; ++i) xr0[i] *= t0;
    for (int i = 0; i < F; ++i) xr1[i] *= t1;
}

// ---------------- final mean + log_softmax ----------------
__global__ void k_final(const float* __restrict__ x, float* __restrict__ out) {
    __shared__ float red[NCLS][9];   // up to 8 warps
    int g = blockIdx.x;
    int base = g * NPERG;
    float acc[NCLS];
    for (int c = 0; c < NCLS; ++c) acc[c] = 0.f;
    for (int n = threadIdx.x; n < NPERG; n += blockDim.x) {
        const float* xr = x + (base + n) * NCLS;
        for (int c = 0; c < NCLS; ++c) acc[c] += xr[c];
    }
    for (int off = 16; off; off >>= 1)
        for (int c = 0; c < NCLS; ++c)
            acc[c] += __shfl_down_sync(0xffffffffu, acc[c], off);
    int lane = threadIdx.x & 31, wid = threadIdx.x >> 5;
    if (lane == 0)
        for (int c = 0; c < NCLS; ++c) red[c][wid] = acc[c];
    __syncthreads();
    if (threadIdx.x == 0) {
        int nw = blockDim.x / 32;
        float z[NCLS];
        for (int c = 0; c < NCLS; ++c) {
            float s = 0.f;
            for (int w = 0; w < nw; ++w) s += red[c][w];
            z[c] = s * (1.f / (NPERG / 4));
        }
        float mx = z[0];
        for (int c = 1; c < NCLS; ++c) mx = fmaxf(mx, z[c]);
        float se = 0.f;
        for (int c = 0; c < NCLS; ++c) se += expf(z[c] - mx);
        float lse = logf(se) + mx;
        for (int c = 0; c < NCLS; ++c) out[g * NCLS + c] = z[c] - lse;
    }
}

// ---------------- host orchestration ----------------
extern "C" void kernel_launch(void* const* d_in, const int* in_sizes, int n_in,
                              void* d_out, int out_size) {
    const float* x     = (const float*)d_in[0];
    const int*   ei    = (const int*)  d_in[1];
    // d_in[2] = batch (unused: nodes are contiguous per graph)
    const float* gamma = (const float*)d_in[3];
    const float* beta  = (const float*)d_in[4];
    const float* W1  = (const float*)d_in[5];
    const float* as1 = (const float*)d_in[6];
    const float* ad1 = (const float*)d_in[7];
    const float* b1  = (const float*)d_in[8];
    const float* W2  = (const float*)d_in[9];
    const float* as2 = (const float*)d_in[10];
    const float* ad2 = (const float*)d_in[11];
    const float* b2  = (const float*)d_in[12];
    const float* W3  = (const float*)d_in[13];
    const float* as3 = (const float*)d_in[14];
    const float* ad3 = (const float*)d_in[15];
    const float* b3  = (const float*)d_in[16];
    const float* W4  = (const float*)d_in[17];
    const float* as4 = (const float*)d_in[18];
    const float* ad4 = (const float*)d_in[19];
    const float* b4  = (const float*)d_in[20];
    const float* p1  = (const float*)d_in[21];
    const float* p2  = (const float*)d_in[22];

    int E = in_sizes[1] / 2;
    const int* src = ei;
    const int* dst = ei + E;
    int Etot = E + NTN;

    float *x0, *h, *oa, *ob;
    cudaGetSymbolAddress((void**)&x0, g_x0);
    cudaGetSymbolAddress((void**)&h,  g_h);
    cudaGetSymbolAddress((void**)&oa, g_oa);
    cudaGetSymbolAddress((void**)&ob, g_ob);

    // BatchNorm (training-mode batch stats) + mask init
    k_zero_stats<<<1, 128>>>();
    k_stats<<<256, 128>>>(x);
    k_bn<<<(NTN * NFEAT) / 256, 256>>>(x, gamma, beta);
    k_initmask<<<NTN / 256, 256>>>();

    // CSR build
    int eb = (Etot + 255) / 256;
    k_deg_zero<<<NTN / 256, 256>>>();
    k_deg_count<<<eb, 256>>>(dst, E, Etot);
    k_scan_block<<<256, 256>>>();
    k_scan_top<<<1, 256>>>();
    k_scan_add<<<256, 256>>>(Etot);
    k_scatter<<<eb, 256>>>(src, dst, E, Etot);

    int gatgrid = NTN * 32 / 256;   // one warp per dst node

    // conv1: 128 -> 3x16
    k_linear<<<(NTN * 48 + 255) / 256, 256, NFEAT * 48 * sizeof(float)>>>(x0, W1, h, NFEAT, 48);
    k_alogits<<<(NTN * 3 + 255) / 256, 256>>>(h, as1, ad1, 3, 16);
    k_gat<3, 16, 2><<<gatgrid, 256>>>(h, b1, oa);

    // conv2: 48 -> 3x16
    k_linear<<<(NTN * 48 + 255) / 256, 256, 48 * 48 * sizeof(float)>>>(oa, W2, h, 48, 48);
    k_alogits<<<(NTN * 3 + 255) / 256, 256>>>(h, as2, ad2, 3, 16);
    k_gat<3, 16, 2><<<gatgrid, 256>>>(h, b2, ob);

    // pool1: keep 1024/graph
    k_topk<<<NBATCH, 1024>>>(ob, p1, 48, NPERG / 2);

    // conv3: 48 -> 2x16
    k_linear<<<(NTN * 32 + 255) / 256, 256, 48 * 32 * sizeof(float)>>>(ob, W3, h, 48, 32);
    k_alogits<<<(NTN * 2 + 255) / 256, 256>>>(h, as3, ad3, 2, 16);
    k_gat<2, 16, 1><<<gatgrid, 256>>>(h, b3, oa);

    // conv4: 32 -> 1x10
    k_linear<<<(NTN * 10 + 255) / 256, 256, 32 * 10 * sizeof(float)>>>(oa, W4, h, 32, 10);
    k_alogits<<<(NTN * 1 + 255) / 256, 256>>>(h, as4, ad4, 1, 10);
    k_gat<1, 10, 1><<<gatgrid, 256>>>(h, b4, ob);

    // pool2: keep 512/graph
    k_topk<<<NBATCH, 1024>>>(ob, p2, 10, NPERG / 4);
    // mean pool + log_softmax
    k_final<<<NBATCH, 256>>>(ob, (float*)d_out);
}

// round 4
// speedup vs baseline: 1.3919x; 1.1607x over previous
#include <cuda_runtime.h>
#include <math.h>

#define NTN   65536
#define NBATCH 32
#define NPERG 2048
#define NFEAT 128
#define NCLS  10
#define NEGV  (-1e9f)
#define MASKV (-1e30f)
#define ETOTMAX (NTN * 16 + NTN)   // 1,114,112 edges incl self loops

// ---------------- scratch (device globals; no allocation allowed) ----------
__device__ float g_x0[NTN * NFEAT];   // normalized input
__device__ float g_h [NTN * 48];      // per-conv linear output (max HC=48)
__device__ float g_oa[NTN * 48];      // ping buffer
__device__ float g_ob[NTN * 48];      // pong buffer
__device__ float g_als[NTN * 3];      // attention logits (src side), max H=3
__device__ float g_ald[NTN * 3];      // attention logits (dst side)
__device__ float g_e  [ETOTMAX * 3];  // per-(edge,head) logit cache
__device__ float g_score[NTN];        // topk raw scores
__device__ int   g_nmask[NTN];        // node mask
__device__ float g_psum [128 * NFEAT];  // BN partial sums
__device__ float g_psq  [128 * NFEAT];
// CSR (built once per launch)
__device__ int g_deg [NTN];
__device__ int g_off [NTN + 1];
__device__ int g_cur [NTN];
__device__ int g_csrc[ETOTMAX];

__device__ __forceinline__ float lrelu(float v) { return v > 0.f ? v : 0.2f * v; }

// ---------------- 0: BN partial stats + zero degrees ----------------
__global__ void k_stats(const float* __restrict__ x) {
    int f = threadIdx.x;                       // 128 threads
    int b = blockIdx.x;                        // 128 blocks
    int r0 = b * (NTN / 128);
    float s = 0.f, s2 = 0.f;
    for (int r = r0; r < r0 + NTN / 128; ++r) {
        float v = x[r * NFEAT + f];
        s += v; s2 += v * v;
    }
    g_psum[b * NFEAT + f] = s;
    g_psq [b * NFEAT + f] = s2;
    int gid = b * 128 + f;
    for (int i = gid; i < NTN; i += 128 * 128) g_deg[i] = 0;
}

// ---------------- 1: degree count ----------------
__global__ void k_deg_count(const int* __restrict__ dst, int E, int Etot) {
    int e = blockIdx.x * blockDim.x + threadIdx.x;
    if (e >= Etot) return;
    int d = (e < E) ? dst[e] : (e - E);
    atomicAdd(&g_deg[d], 1);
}

// ---------------- 2: BN normalize + mask init ----------------
__global__ void k_bn(const float* __restrict__ x, const float* __restrict__ gamma,
                     const float* __restrict__ beta) {
    __shared__ float sg[NFEAT], sb[NFEAT];
    int tid = threadIdx.x;
    if (tid < NFEAT) {
        float s = 0.f, s2 = 0.f;
        for (int b = 0; b < 128; ++b) {
            s  += g_psum[b * NFEAT + tid];
            s2 += g_psq [b * NFEAT + tid];
        }
        float mu  = s  * (1.f / NTN);
        float var = s2 * (1.f / NTN) - mu * mu;
        float rstd = rsqrtf(var + 1e-5f);
        float ga = gamma[tid];
        sg[tid] = ga * rstd;
        sb[tid] = beta[tid] - mu * ga * rstd;
    }
    __syncthreads();
    const float4* x4 = (const float4*)x;
    float4* o4 = (float4*)g_x0;
    int nv = NTN * NFEAT / 4;
    for (int vi = blockIdx.x * blockDim.x + tid; vi < nv; vi += gridDim.x * blockDim.x) {
        float4 v = x4[vi];
        int f0 = (vi * 4) & (NFEAT - 1);
        v.x = v.x * sg[f0]     + sb[f0];
        v.y = v.y * sg[f0 + 1] + sb[f0 + 1];
        v.z = v.z * sg[f0 + 2] + sb[f0 + 2];
        v.w = v.w * sg[f0 + 3] + sb[f0 + 3];
        o4[vi] = v;
    }
    for (int i = blockIdx.x * blockDim.x + tid; i < NTN; i += gridDim.x * blockDim.x)
        g_nmask[i] = 1;
}

// ---------------- 3: single-block scan of degrees ----------------
__global__ void k_scan(int Etot) {
    __shared__ int sh[1024];
    int t = threadIdx.x;
    int base = t * (NTN / 1024);
    int s = 0;
    for (int j = 0; j < NTN / 1024; ++j) s += g_deg[base + j];
    sh[t] = s;
    __syncthreads();
    for (int o = 1; o < 1024; o <<= 1) {
        int v = (t >= o) ? sh[t - o] : 0;
        __syncthreads();
        sh[t] += v;
        __syncthreads();
    }
    int run = sh[t] - s;     // exclusive
    for (int j = 0; j < NTN / 1024; ++j) {
        int dg = g_deg[base + j];
        g_off[base + j] = run;
        g_cur[base + j] = run;
        run += dg;
    }
    if (t == 1023) g_off[NTN] = Etot;
}

// ---------------- 4: scatter edges into CSR ----------------
__global__ void k_scatter(const int* __restrict__ src, const int* __restrict__ dst,
                          int E, int Etot) {
    int e = blockIdx.x * blockDim.x + threadIdx.x;
    if (e >= Etot) return;
    int s, d;
    if (e < E) { s = src[e]; d = dst[e]; } else { s = e - E; d = s; }
    int pos = atomicAdd(&g_cur[d], 1);
    g_csrc[pos] = s;
}

// ---------------- fused linear + attention logits ----------------
// warp per row; lane owns channel pair (2l, 2l+1); x row staged in smem;
// als/ald via segmented shuffle reduction; node mask folded into als sentinel.
template <int Fin, int H, int C>
__global__ __launch_bounds__(256) void k_lin(const float* __restrict__ xin,
                                             const float* __restrict__ W,
                                             const float* __restrict__ a_s,
                                             const float* __restrict__ a_d,
                                             float* __restrict__ h) {
    constexpr int HC = H * C;
    constexpr int RW = 4;
    __shared__ float Ws[Fin * HC];
    __shared__ float xs[8][Fin];
    __shared__ float asv[HC], adv[HC];
    int tid = threadIdx.x, lane = tid & 31, wid = tid >> 5;
    for (int i = tid; i < Fin * HC; i += 256) Ws[i] = W[i];
    if (tid < HC) { asv[tid] = a_s[tid]; adv[tid] = a_d[tid]; }
    __syncthreads();

    int rbase = (blockIdx.x * 8 + wid) * RW;
    int c0 = 2 * lane;
    bool act = (c0 < HC);

    for (int rr = 0; rr < RW; ++rr) {
        int r = rbase + rr;
        if (lane < Fin / 4) {
            float4 v = *(const float4*)(xin + r * Fin + lane * 4);
            *(float4*)&xs[wid][lane * 4] = v;
        }
        __syncwarp();

        float ax = 0.f, ay = 0.f;
        if (act) {
            #pragma unroll 4
            for (int i0 = 0; i0 < Fin; i0 += 4) {
                float4 xv = *(const float4*)&xs[wid][i0];
                float2 w0 = *(const float2*)&Ws[(i0 + 0) * HC + c0];
                float2 w1 = *(const float2*)&Ws[(i0 + 1) * HC + c0];
                float2 w2 = *(const float2*)&Ws[(i0 + 2) * HC + c0];
                float2 w3 = *(const float2*)&Ws[(i0 + 3) * HC + c0];
                ax += xv.x * w0.x; ay += xv.x * w0.y;
                ax += xv.y * w1.x; ay += xv.y * w1.y;
                ax += xv.z * w2.x; ay += xv.z * w2.y;
                ax += xv.w * w3.x; ay += xv.w * w3.y;
            }
            *(float2*)(h + r * HC + c0) = make_float2(ax, ay);
        }

        float ps = 0.f, pd = 0.f;
        if (act) {
            ps = ax * asv[c0] + ay * asv[c0 + 1];
            pd = ax * adv[c0] + ay * adv[c0 + 1];
        }
        int msk = g_nmask[r];
        if (C == 16) {
            // channel pair stays within one head; 8-lane head groups
            #pragma unroll
            for (int o = 4; o; o >>= 1) {
                ps += __shfl_xor_sync(0xffffffffu, ps, o);
                pd += __shfl_xor_sync(0xffffffffu, pd, o);
            }
            if ((lane & 7) == 0 && act) {
                int hh = lane >> 3;
                g_als[r * H + hh] = msk ? ps : MASKV;
                g_ald[r * H + hh] = pd;
            }
        } else {
            // H == 1: full warp reduce
            #pragma unroll
            for (int o = 16; o; o >>= 1) {
                ps += __shfl_xor_sync(0xffffffffu, ps, o);
                pd += __shfl_xor_sync(0xffffffffu, pd, o);
            }
            if (lane == 0) {
                g_als[r] = msk ? ps : MASKV;
                g_ald[r] = pd;
            }
        }
        __syncwarp();
    }
}

// ---------------- fused attention softmax + aggregation ----------------
// warp per dst node; phase A caches per-edge logits in g_e (coalesced),
// online softmax in registers; phase B reads g_e + coalesced h-row gather.
template <int H, int C>
__global__ __launch_bounds__(256) void k_gat(const float* __restrict__ h,
                                             const float* __restrict__ b,
                                             float* __restrict__ out) {
    constexpr int HC = H * C;
    int d = (blockIdx.x * blockDim.x + threadIdx.x) >> 5;
    if (d >= NTN) return;
    int lane = threadIdx.x & 31;
    int c0 = 2 * lane;
    bool act = (c0 < HC);

    if (!g_nmask[d]) {
        if (act) *(float2*)(out + d * HC + c0) = make_float2(b[c0], b[c0 + 1]);
        return;
    }

    int beg = g_off[d], end = g_off[d + 1];
    float ald_d[H], m[H], den[H];
    #pragma unroll
    for (int hh = 0; hh < H; ++hh) {
        ald_d[hh] = g_ald[d * H + hh];
        m[hh] = NEGV; den[hh] = 0.f;
    }

    // phase A: logit compute + cache + online softmax (lanes stride edges)
    for (int i = beg + lane; i < end; i += 32) {
        int s = g_csrc[i];
        #pragma unroll
        for (int hh = 0; hh < H; ++hh) {
            float v = lrelu(g_als[s * H + hh] + ald_d[hh]);
            g_e[i * H + hh] = v;
            if (v <= m[hh]) {
                den[hh] += __expf(v - m[hh]);
            } else {
                den[hh] = den[hh] * __expf(m[hh] - v) + 1.f;
                m[hh] = v;
            }
        }
    }
    #pragma unroll
    for (int o = 16; o; o >>= 1) {
        #pragma unroll
        for (int hh = 0; hh < H; ++hh) {
            float mo = __shfl_xor_sync(0xffffffffu, m[hh], o);
            float eo = __shfl_xor_sync(0xffffffffu, den[hh], o);
            float nm = fmaxf(m[hh], mo);
            den[hh] = den[hh] * __expf(m[hh] - nm) + eo * __expf(mo - nm);
            m[hh] = nm;
        }
    }
    __syncwarp();   // g_e writes visible to whole warp

    int hh0 = c0 / C;
    float m_my = m[0], den_my = den[0];
    #pragma unroll
    for (int hh = 1; hh < H; ++hh)
        if (hh == hh0) { m_my = m[hh]; den_my = den[hh]; }
    float inv_my = 1.f / fmaxf(den_my, 1e-16f);

    // phase B: serial edges, lanes own channel pairs
    float accx = 0.f, accy = 0.f;
    for (int i = beg; i < end; ++i) {
        float ev0 = g_e[i * H];
        if (ev0 < -1e20f) continue;        // masked src (warp-uniform)
        int s = g_csrc[i];
        float ev = (H == 1) ? ev0 : g_e[i * H + hh0];
        float alpha = __expf(ev - m_my) * inv_my;
        if (act) {
            float2 hv = *(const float2*)(h + s * HC + c0);
            accx += alpha * hv.x;
            accy += alpha * hv.y;
        }
    }
    if (act) *(float2*)(out + d * HC + c0) = make_float2(accx + b[c0], accy + b[c0 + 1]);
}

// ---------------- TopK pooling ----------------
__global__ void k_topk(float* __restrict__ x, const float* __restrict__ p,
                       int F, int kkeep) {
    __shared__ float ss[NPERG];
    __shared__ int   wsum[32];
    __shared__ int   wsex[32];
    __shared__ float s_thr;
    __shared__ int   s_need;
    int g = blockIdx.x;
    int base = g * NPERG;
    int tid = threadIdx.x;
    int lane = tid & 31, wid = tid >> 5;

    float nrm = 0.f;
    for (int i = 0; i < F; ++i) { float pv = p[i]; nrm += pv * pv; }
    nrm = rsqrtf(nrm);

    for (int n = tid; n < NPERG; n += blockDim.x) {
        int node = base + n;
        const float* xr = x + node * F;
        float sc = 0.f;
        for (int i = 0; i < F; ++i) sc += xr[i] * p[i];
        sc *= nrm;
        g_score[node] = sc;
        ss[n] = g_nmask[node] ? sc : NEGV;
    }
    __syncthreads();

    for (int kk = 2; kk <= NPERG; kk <<= 1) {
        for (int j = kk >> 1; j > 0; j >>= 1) {
            for (int i = tid; i < NPERG; i += blockDim.x) {
                int ixj = i ^ j;
                if (ixj > i) {
                    float a = ss[i], bb = ss[ixj];
                    bool up = ((i & kk) == 0);
                    if ((a > bb) == up) { ss[i] = bb; ss[ixj] = a; }
                }
            }
            __syncthreads();
        }
    }

    if (tid == 0) {
        float thr = ss[NPERG - kkeep];
        int lo = NPERG - kkeep, hi = NPERG;
        while (lo < hi) {
            int mid = (lo + hi) >> 1;
            if (ss[mid] > thr) hi = mid; else lo = mid + 1;
        }
        s_thr = thr;
        s_need = kkeep - (NPERG - lo);
    }
    __syncthreads();
    float thr = s_thr;
    int need_eq = s_need;

    int n0 = tid * 2, n1 = n0 + 1;
    float sc0 = g_nmask[base + n0] ? g_score[base + n0] : NEGV;
    float sc1 = g_nmask[base + n1] ? g_score[base + n1] : NEGV;
    int f0 = (sc0 == thr) ? 1 : 0;
    int f1 = (sc1 == thr) ? 1 : 0;
    int lsum = f0 + f1;
    int incl = lsum;
    #pragma unroll
    for (int o = 1; o < 32; o <<= 1) {
        int t = __shfl_up_sync(0xffffffffu, incl, o);
        if (lane >= o) incl += t;
    }
    if (lane == 31) wsum[wid] = incl;
    __syncthreads();
    if (wid == 0) {
        int v = wsum[lane];
        int inc2 = v;
        #pragma unroll
        for (int o = 1; o < 32; o <<= 1) {
            int t = __shfl_up_sync(0xffffffffu, inc2, o);
            if (lane >= o) inc2 += t;
        }
        wsex[lane] = inc2 - v;
    }
    __syncthreads();
    int rank0 = wsex[wid] + (incl - lsum);
    int rank1 = rank0 + f0;

    int keep0 = (sc0 > thr) || (f0 && rank0 < need_eq);
    int keep1 = (sc1 > thr) || (f1 && rank1 < need_eq);

    g_nmask[base + n0] = keep0;
    g_nmask[base + n1] = keep1;
    float t0 = keep0 ? tanhf(g_score[base + n0]) : 0.f;
    float t1 = keep1 ? tanhf(g_score[base + n1]) : 0.f;
    float* xr0 = x + (base + n0) * F;
    float* xr1 = x + (base + n1) * F;
    for (int i = 0; i < F; ++i) xr0[i] *= t0;
    for (int i = 0; i < F; ++i) xr1[i] *= t1;
}

// ---------------- final mean + log_softmax ----------------
__global__ void k_final(const float* __restrict__ x, float* __restrict__ out) {
    __shared__ float red[NCLS][9];
    int g = blockIdx.x;
    int base = g * NPERG;
    float acc[NCLS];
    for (int c = 0; c < NCLS; ++c) acc[c] = 0.f;
    for (int n = threadIdx.x; n < NPERG; n += blockDim.x) {
        const float* xr = x + (base + n) * NCLS;
        for (int c = 0; c < NCLS; ++c) acc[c] += xr[c];
    }
    for (int off = 16; off; off >>= 1)
        for (int c = 0; c < NCLS; ++c)
            acc[c] += __shfl_down_sync(0xffffffffu, acc[c], off);
    int lane = threadIdx.x & 31, wid = threadIdx.x >> 5;
    if (lane == 0)
        for (int c = 0; c < NCLS; ++c) red[c][wid] = acc[c];
    __syncthreads();
    if (threadIdx.x == 0) {
        int nw = blockDim.x / 32;
        float z[NCLS];
        for (int c = 0; c < NCLS; ++c) {
            float s = 0.f;
            for (int w = 0; w < nw; ++w) s += red[c][w];
            z[c] = s * (1.f / (NPERG / 4));
        }
        float mx = z[0];
        for (int c = 1; c < NCLS; ++c) mx = fmaxf(mx, z[c]);
        float se = 0.f;
        for (int c = 0; c < NCLS; ++c) se += expf(z[c] - mx);
        float lse = logf(se) + mx;
        for (int c = 0; c < NCLS; ++c) out[g * NCLS + c] = z[c] - lse;
    }
}

// ---------------- host orchestration ----------------
extern "C" void kernel_launch(void* const* d_in, const int* in_sizes, int n_in,
                              void* d_out, int out_size) {
    const float* x     = (const float*)d_in[0];
    const int*   ei    = (const int*)  d_in[1];
    const float* gamma = (const float*)d_in[3];
    const float* beta  = (const float*)d_in[4];
    const float* W1  = (const float*)d_in[5];
    const float* as1 = (const float*)d_in[6];
    const float* ad1 = (const float*)d_in[7];
    const float* b1  = (const float*)d_in[8];
    const float* W2  = (const float*)d_in[9];
    const float* as2 = (const float*)d_in[10];
    const float* ad2 = (const float*)d_in[11];
    const float* b2  = (const float*)d_in[12];
    const float* W3  = (const float*)d_in[13];
    const float* as3 = (const float*)d_in[14];
    const float* ad3 = (const float*)d_in[15];
    const float* b3  = (const float*)d_in[16];
    const float* W4  = (const float*)d_in[17];
    const float* as4 = (const float*)d_in[18];
    const float* ad4 = (const float*)d_in[19];
    const float* b4  = (const float*)d_in[20];
    const float* p1  = (const float*)d_in[21];
    const float* p2  = (const float*)d_in[22];

    int E = in_sizes[1] / 2;
    const int* src = ei;
    const int* dst = ei + E;
    int Etot = E + NTN;
    int eb = (Etot + 255) / 256;

    float *x0, *h, *oa, *ob;
    cudaGetSymbolAddress((void**)&x0, g_x0);
    cudaGetSymbolAddress((void**)&h,  g_h);
    cudaGetSymbolAddress((void**)&oa, g_oa);
    cudaGetSymbolAddress((void**)&ob, g_ob);

    int lingrid = NTN / 32;         // warp per row, RW=4, 8 warps/block
    int gatgrid = NTN * 32 / 256;   // warp per dst node

    k_stats<<<128, 128>>>(x);                          // 0
    k_deg_count<<<eb, 256>>>(dst, E, Etot);            // 1
    k_bn<<<128, 256>>>(x, gamma, beta);                // 2
    k_scan<<<1, 1024>>>(Etot);                         // 3
    k_scatter<<<eb, 256>>>(src, dst, E, Etot);         // 4

    k_lin<NFEAT, 3, 16><<<lingrid, 256>>>(x0, W1, as1, ad1, h);   // 5
    k_gat<3, 16><<<gatgrid, 256>>>(h, b1, oa);                    // 6
    k_lin<48, 3, 16><<<lingrid, 256>>>(oa, W2, as2, ad2, h);      // 7
    k_gat<3, 16><<<gatgrid, 256>>>(h, b2, ob);                    // 8
    k_topk<<<NBATCH, 1024>>>(ob, p1, 48, NPERG / 2);              // 9
    k_lin<48, 2, 16><<<lingrid, 256>>>(ob, W3, as3, ad3, h);      // 10
    k_gat<2, 16><<<gatgrid, 256>>>(h, b3, oa);                    // 11
    k_lin<32, 1, 10><<<lingrid, 256>>>(oa, W4, as4, ad4, h);      // 12
    k_gat<1, 10><<<gatgrid, 256>>>(h, b4, ob);                    // 13
    k_topk<<<NBATCH, 1024>>>(ob, p2, 10, NPERG / 4);              // 14
    k_final<<<NBATCH, 256>>>(ob, (float*)d_out);                  // 15
}

// round 5
// speedup vs baseline: 1.7064x; 1.2259x over previous
#include <cuda_runtime.h>
#include <math.h>

#define NTN   65536
#define NBATCH 32
#define NPERG 2048
#define NFEAT 128
#define NCLS  10
#define NEGV  (-1e9f)
#define MASKV (-1e30f)
#define ETOTMAX (NTN * 16 + NTN)   // 1,114,112 edges incl self loops

// ---------------- scratch (device globals; no allocation allowed) ----------
__device__ float g_x0[NTN * NFEAT];   // normalized input
__device__ float g_h [NTN * 48];      // per-conv linear output (max HC=48)
__device__ float g_oa[NTN * 48];      // ping buffer
__device__ float g_ob[NTN * 48];      // pong buffer
__device__ float g_als[NTN * 3];      // attention logits (src side), max H=3
__device__ float g_ald[NTN * 3];      // attention logits (dst side)
__device__ float g_e  [ETOTMAX * 3];  // per-(edge,head) logit -> alpha cache
__device__ float g_score[NTN];        // topk raw scores
__device__ int   g_nmask[NTN];        // node mask
__device__ float g_psum [128 * NFEAT];  // BN partial sums
__device__ float g_psq  [128 * NFEAT];
// CSR (built once per launch)
__device__ int g_deg [NTN];
__device__ int g_off [NTN + 1];
__device__ int g_cur [NTN];
__device__ int g_bsum[256];
__device__ int g_bsex[256];
__device__ int g_csrc[ETOTMAX];

__device__ __forceinline__ float lrelu(float v) { return v > 0.f ? v : 0.2f * v; }

// ---------------- 0: BN partial stats + zero degrees ----------------
__global__ void k_stats(const float* __restrict__ x) {
    int f = threadIdx.x;                       // 128 threads
    int b = blockIdx.x;                        // 128 blocks
    int r0 = b * (NTN / 128);
    float s = 0.f, s2 = 0.f;
    for (int r = r0; r < r0 + NTN / 128; ++r) {
        float v = x[r * NFEAT + f];
        s += v; s2 += v * v;
    }
    g_psum[b * NFEAT + f] = s;
    g_psq [b * NFEAT + f] = s2;
    int gid = b * 128 + f;
    for (int i = gid; i < NTN; i += 128 * 128) g_deg[i] = 0;
}

// ---------------- 1: degree count ----------------
__global__ void k_deg_count(const int* __restrict__ dst, int E, int Etot) {
    int e = blockIdx.x * blockDim.x + threadIdx.x;
    if (e >= Etot) return;
    int d = (e < E) ? dst[e] : (e - E);
    atomicAdd(&g_deg[d], 1);
}

// ---------------- 2: BN normalize + mask init ----------------
__global__ void k_bn(const float* __restrict__ x, const float* __restrict__ gamma,
                     const float* __restrict__ beta) {
    __shared__ float sg[NFEAT], sb[NFEAT];
    int tid = threadIdx.x;
    if (tid < NFEAT) {
        float s = 0.f, s2 = 0.f;
        for (int b = 0; b < 128; ++b) {
            s  += g_psum[b * NFEAT + tid];
            s2 += g_psq [b * NFEAT + tid];
        }
        float mu  = s  * (1.f / NTN);
        float var = s2 * (1.f / NTN) - mu * mu;
        float rstd = rsqrtf(var + 1e-5f);
        float ga = gamma[tid];
        sg[tid] = ga * rstd;
        sb[tid] = beta[tid] - mu * ga * rstd;
    }
    __syncthreads();
    const float4* x4 = (const float4*)x;
    float4* o4 = (float4*)g_x0;
    int nv = NTN * NFEAT / 4;
    for (int vi = blockIdx.x * blockDim.x + tid; vi < nv; vi += gridDim.x * blockDim.x) {
        float4 v = x4[vi];
        int f0 = (vi * 4) & (NFEAT - 1);
        v.x = v.x * sg[f0]     + sb[f0];
        v.y = v.y * sg[f0 + 1] + sb[f0 + 1];
        v.z = v.z * sg[f0 + 2] + sb[f0 + 2];
        v.w = v.w * sg[f0 + 3] + sb[f0 + 3];
        o4[vi] = v;
    }
    for (int i = blockIdx.x * blockDim.x + tid; i < NTN; i += gridDim.x * blockDim.x)
        g_nmask[i] = 1;
}

// ---------------- 3-5: hierarchical scan of degrees ----------------
__global__ void k_scan_block() {            // 256 blocks x 256 threads
    __shared__ int sh[256];
    int n = blockIdx.x * 256 + threadIdx.x;
    int v = g_deg[n];
    sh[threadIdx.x] = v;
    __syncthreads();
    for (int o = 1; o < 256; o <<= 1) {
        int t = (threadIdx.x >= o) ? sh[threadIdx.x - o] : 0;
        __syncthreads();
        sh[threadIdx.x] += t;
        __syncthreads();
    }
    g_off[n] = sh[threadIdx.x] - v;         // exclusive within block
    if (threadIdx.x == 255) g_bsum[blockIdx.x] = sh[255];
}

__global__ void k_scan_top() {              // 1 block x 256 threads
    __shared__ int sh[256];
    int v = g_bsum[threadIdx.x];
    sh[threadIdx.x] = v;
    __syncthreads();
    for (int o = 1; o < 256; o <<= 1) {
        int t = (threadIdx.x >= o) ? sh[threadIdx.x - o] : 0;
        __syncthreads();
        sh[threadIdx.x] += t;
        __syncthreads();
    }
    g_bsex[threadIdx.x] = sh[threadIdx.x] - v;
}

__global__ void k_scan_add(int Etot) {      // 256 blocks x 256 threads
    int n = blockIdx.x * 256 + threadIdx.x;
    int o = g_off[n] + g_bsex[blockIdx.x];
    g_off[n] = o;
    g_cur[n] = o;
    if (n == 0) g_off[NTN] = Etot;
}

// ---------------- 6: scatter edges into CSR ----------------
__global__ void k_scatter(const int* __restrict__ src, const int* __restrict__ dst,
                          int E, int Etot) {
    int e = blockIdx.x * blockDim.x + threadIdx.x;
    if (e >= Etot) return;
    int s, d;
    if (e < E) { s = src[e]; d = dst[e]; } else { s = e - E; d = s; }
    int pos = atomicAdd(&g_cur[d], 1);
    g_csrc[pos] = s;
}

// ---------------- fused linear + attention logits ----------------
// warp per row; lane owns channel pair (2l, 2l+1); x row staged in smem;
// als/ald via segmented shuffle reduction; node mask folded into als sentinel;
// masked rows skip the matmul entirely (h never read for masked src).
template <int Fin, int H, int C>
__global__ __launch_bounds__(256) void k_lin(const float* __restrict__ xin,
                                             const float* __restrict__ W,
                                             const float* __restrict__ a_s,
                                             const float* __restrict__ a_d,
                                             float* __restrict__ h) {
    constexpr int HC = H * C;
    constexpr int RW = 4;
    __shared__ float Ws[Fin * HC];
    __shared__ float xs[8][Fin];
    __shared__ float asv[HC], adv[HC];
    int tid = threadIdx.x, lane = tid & 31, wid = tid >> 5;
    for (int i = tid; i < Fin * HC; i += 256) Ws[i] = W[i];
    if (tid < HC) { asv[tid] = a_s[tid]; adv[tid] = a_d[tid]; }
    __syncthreads();

    int rbase = (blockIdx.x * 8 + wid) * RW;
    int c0 = 2 * lane;
    bool act = (c0 < HC);

    for (int rr = 0; rr < RW; ++rr) {
        int r = rbase + rr;
        int msk = g_nmask[r];
        if (!msk) {   // warp-uniform: dead row, only sentinel logits needed
            if (C == 16) {
                if ((lane & 7) == 0 && act) {
                    int hh = lane >> 3;
                    g_als[r * H + hh] = MASKV;
                    g_ald[r * H + hh] = 0.f;
                }
            } else {
                if (lane == 0) { g_als[r] = MASKV; g_ald[r] = 0.f; }
            }
            continue;
        }
        if (lane < Fin / 4) {
            float4 v = *(const float4*)(xin + r * Fin + lane * 4);
            *(float4*)&xs[wid][lane * 4] = v;
        }
        __syncwarp();

        float ax = 0.f, ay = 0.f;
        if (act) {
            #pragma unroll 4
            for (int i0 = 0; i0 < Fin; i0 += 4) {
                float4 xv = *(const float4*)&xs[wid][i0];
                float2 w0 = *(const float2*)&Ws[(i0 + 0) * HC + c0];
                float2 w1 = *(const float2*)&Ws[(i0 + 1) * HC + c0];
                float2 w2 = *(const float2*)&Ws[(i0 + 2) * HC + c0];
                float2 w3 = *(const float2*)&Ws[(i0 + 3) * HC + c0];
                ax += xv.x * w0.x; ay += xv.x * w0.y;
                ax += xv.y * w1.x; ay += xv.y * w1.y;
                ax += xv.z * w2.x; ay += xv.z * w2.y;
                ax += xv.w * w3.x; ay += xv.w * w3.y;
            }
            *(float2*)(h + r * HC + c0) = make_float2(ax, ay);
        }

        float ps = 0.f, pd = 0.f;
        if (act) {
            ps = ax * asv[c0] + ay * asv[c0 + 1];
            pd = ax * adv[c0] + ay * adv[c0 + 1];
        }
        if (C == 16) {
            #pragma unroll
            for (int o = 4; o; o >>= 1) {
                ps += __shfl_xor_sync(0xffffffffu, ps, o);
                pd += __shfl_xor_sync(0xffffffffu, pd, o);
            }
            if ((lane & 7) == 0 && act) {
                int hh = lane >> 3;
                g_als[r * H + hh] = ps;
                g_ald[r * H + hh] = pd;
            }
        } else {
            #pragma unroll
            for (int o = 16; o; o >>= 1) {
                ps += __shfl_xor_sync(0xffffffffu, ps, o);
                pd += __shfl_xor_sync(0xffffffffu, pd, o);
            }
            if (lane == 0) { g_als[r] = ps; g_ald[r] = pd; }
        }
        __syncwarp();
    }
}

// ---------------- fused attention softmax + aggregation ----------------
// warp per dst node; phase A computes logits, caches to g_e, online softmax;
// then converts g_e in place to alpha (0 for masked); phase B is a pure
// alpha*h[src] accumulation with predicated gathers.
template <int H, int C>
__global__ __launch_bounds__(256) void k_gat(const float* __restrict__ h,
                                             const float* __restrict__ b,
                                             float* __restrict__ out) {
    constexpr int HC = H * C;
    int d = (blockIdx.x * blockDim.x + threadIdx.x) >> 5;
    if (d >= NTN) return;
    int lane = threadIdx.x & 31;
    int c0 = 2 * lane;
    bool act = (c0 < HC);

    if (!g_nmask[d]) {
        if (act) *(float2*)(out + d * HC + c0) = make_float2(b[c0], b[c0 + 1]);
        return;
    }

    int beg = g_off[d], end = g_off[d + 1];
    float ald_d[H], m[H], den[H];
    #pragma unroll
    for (int hh = 0; hh < H; ++hh) {
        ald_d[hh] = g_ald[d * H + hh];
        m[hh] = NEGV; den[hh] = 0.f;
    }

    // phase A: logit compute + cache + online softmax (lanes stride edges)
    for (int i = beg + lane; i < end; i += 32) {
        int s = g_csrc[i];
        #pragma unroll
        for (int hh = 0; hh < H; ++hh) {
            float v = lrelu(g_als[s * H + hh] + ald_d[hh]);
            g_e[i * H + hh] = v;
            if (v <= m[hh]) {
                den[hh] += __expf(v - m[hh]);
            } else {
                den[hh] = den[hh] * __expf(m[hh] - v) + 1.f;
                m[hh] = v;
            }
        }
    }
    #pragma unroll
    for (int o = 16; o; o >>= 1) {
        #pragma unroll
        for (int hh = 0; hh < H; ++hh) {
            float mo = __shfl_xor_sync(0xffffffffu, m[hh], o);
            float eo = __shfl_xor_sync(0xffffffffu, den[hh], o);
            float nm = fmaxf(m[hh], mo);
            den[hh] = den[hh] * __expf(m[hh] - nm) + eo * __expf(mo - nm);
            m[hh] = nm;
        }
    }
    float inv[H];
    #pragma unroll
    for (int hh = 0; hh < H; ++hh) inv[hh] = 1.f / fmaxf(den[hh], 1e-16f);

    // convert cached logits to alpha in place (masked edges -> 0)
    for (int i = beg + lane; i < end; i += 32) {
        #pragma unroll
        for (int hh = 0; hh < H; ++hh) {
            float v = g_e[i * H + hh];
            g_e[i * H + hh] = (v < -1e20f) ? 0.f : __expf(v - m[hh]) * inv[hh];
        }
    }
    __syncwarp();

    int hh0 = c0 / C;

    // phase B: serial edges, lanes own channel pairs; predicated gather
    float accx = 0.f, accy = 0.f;
    #pragma unroll 4
    for (int i = beg; i < end; ++i) {
        float a = act ? g_e[i * H + hh0] : 0.f;
        int s = g_csrc[i];
        if (a > 0.f) {
            float2 hv = *(const float2*)(h + s * HC + c0);
            accx += a * hv.x;
            accy += a * hv.y;
        }
    }
    if (act) *(float2*)(out + d * HC + c0) = make_float2(accx + b[c0], accy + b[c0 + 1]);
}

// ---------------- TopK pooling ----------------
__global__ void k_topk(float* __restrict__ x, const float* __restrict__ p,
                       int F, int kkeep) {
    __shared__ float ss[NPERG];
    __shared__ int   wsum[32];
    __shared__ int   wsex[32];
    __shared__ float s_thr;
    __shared__ int   s_need;
    int g = blockIdx.x;
    int base = g * NPERG;
    int tid = threadIdx.x;
    int lane = tid & 31, wid = tid >> 5;

    float nrm = 0.f;
    for (int i = 0; i < F; ++i) { float pv = p[i]; nrm += pv * pv; }
    nrm = rsqrtf(nrm);

    for (int n = tid; n < NPERG; n += blockDim.x) {
        int node = base + n;
        const float* xr = x + node * F;
        float sc = 0.f;
        for (int i = 0; i < F; ++i) sc += xr[i] * p[i];
        sc *= nrm;
        g_score[node] = sc;
        ss[n] = g_nmask[node] ? sc : NEGV;
    }
    __syncthreads();

    for (int kk = 2; kk <= NPERG; kk <<= 1) {
        for (int j = kk >> 1; j > 0; j >>= 1) {
            for (int i = tid; i < NPERG; i += blockDim.x) {
                int ixj = i ^ j;
                if (ixj > i) {
                    float a = ss[i], bb = ss[ixj];
                    bool up = ((i & kk) == 0);
                    if ((a > bb) == up) { ss[i] = bb; ss[ixj] = a; }
                }
            }
            __syncthreads();
        }
    }

    if (tid == 0) {
        float thr = ss[NPERG - kkeep];
        int lo = NPERG - kkeep, hi = NPERG;
        while (lo < hi) {
            int mid = (lo + hi) >> 1;
            if (ss[mid] > thr) hi = mid; else lo = mid + 1;
        }
        s_thr = thr;
        s_need = kkeep - (NPERG - lo);
    }
    __syncthreads();
    float thr = s_thr;
    int need_eq = s_need;

    int n0 = tid * 2, n1 = n0 + 1;
    float sc0 = g_nmask[base + n0] ? g_score[base + n0] : NEGV;
    float sc1 = g_nmask[base + n1] ? g_score[base + n1] : NEGV;
    int f0 = (sc0 == thr) ? 1 : 0;
    int f1 = (sc1 == thr) ? 1 : 0;
    int lsum = f0 + f1;
    int incl = lsum;
    #pragma unroll
    for (int o = 1; o < 32; o <<= 1) {
        int t = __shfl_up_sync(0xffffffffu, incl, o);
        if (lane >= o) incl += t;
    }
    if (lane == 31) wsum[wid] = incl;
    __syncthreads();
    if (wid == 0) {
        int v = wsum[lane];
        int inc2 = v;
        #pragma unroll
        for (int o = 1; o < 32; o <<= 1) {
            int t = __shfl_up_sync(0xffffffffu, inc2, o);
            if (lane >= o) inc2 += t;
        }
        wsex[lane] = inc2 - v;
    }
    __syncthreads();
    int rank0 = wsex[wid] + (incl - lsum);
    int rank1 = rank0 + f0;

    int keep0 = (sc0 > thr) || (f0 && rank0 < need_eq);
    int keep1 = (sc1 > thr) || (f1 && rank1 < need_eq);

    g_nmask[base + n0] = keep0;
    g_nmask[base + n1] = keep1;
    float t0 = keep0 ? tanhf(g_score[base + n0]) : 0.f;
    float t1 = keep1 ? tanhf(g_score[base + n1]) : 0.f;
    float* xr0 = x + (base + n0) * F;
    float* xr1 = x + (base + n1) * F;
    for (int i = 0; i < F; ++i) xr0[i] *= t0;
    for (int i = 0; i < F; ++i) xr1[i] *= t1;
}

// ---------------- final mean + log_softmax ----------------
__global__ void k_final(const float* __restrict__ x, float* __restrict__ out) {
    __shared__ float red[NCLS][9];
    int g = blockIdx.x;
    int base = g * NPERG;
    float acc[NCLS];
    for (int c = 0; c < NCLS; ++c) acc[c] = 0.f;
    for (int n = threadIdx.x; n < NPERG; n += blockDim.x) {
        const float* xr = x + (base + n) * NCLS;
        for (int c = 0; c < NCLS; ++c) acc[c] += xr[c];
    }
    for (int off = 16; off; off >>= 1)
        for (int c = 0; c < NCLS; ++c)
            acc[c] += __shfl_down_sync(0xffffffffu, acc[c], off);
    int lane = threadIdx.x & 31, wid = threadIdx.x >> 5;
    if (lane == 0)
        for (int c = 0; c < NCLS; ++c) red[c][wid] = acc[c];
    __syncthreads();
    if (threadIdx.x == 0) {
        int nw = blockDim.x / 32;
        float z[NCLS];
        for (int c = 0; c < NCLS; ++c) {
            float s = 0.f;
            for (int w = 0; w < nw; ++w) s += red[c][w];
            z[c] = s * (1.f / (NPERG / 4));
        }
        float mx = z[0];
        for (int c = 1; c < NCLS; ++c) mx = fmaxf(mx, z[c]);
        float se = 0.f;
        for (int c = 0; c < NCLS; ++c) se += expf(z[c] - mx);
        float lse = logf(se) + mx;
        for (int c = 0; c < NCLS; ++c) out[g * NCLS + c] = z[c] - lse;
    }
}

// ---------------- host orchestration ----------------
extern "C" void kernel_launch(void* const* d_in, const int* in_sizes, int n_in,
                              void* d_out, int out_size) {
    const float* x     = (const float*)d_in[0];
    const int*   ei    = (const int*)  d_in[1];
    const float* gamma = (const float*)d_in[3];
    const float* beta  = (const float*)d_in[4];
    const float* W1  = (const float*)d_in[5];
    const float* as1 = (const float*)d_in[6];
    const float* ad1 = (const float*)d_in[7];
    const float* b1  = (const float*)d_in[8];
    const float* W2  = (const float*)d_in[9];
    const float* as2 = (const float*)d_in[10];
    const float* ad2 = (const float*)d_in[11];
    const float* b2  = (const float*)d_in[12];
    const float* W3  = (const float*)d_in[13];
    const float* as3 = (const float*)d_in[14];
    const float* ad3 = (const float*)d_in[15];
    const float* b3  = (const float*)d_in[16];
    const float* W4  = (const float*)d_in[17];
    const float* as4 = (const float*)d_in[18];
    const float* ad4 = (const float*)d_in[19];
    const float* b4  = (const float*)d_in[20];
    const float* p1  = (const float*)d_in[21];
    const float* p2  = (const float*)d_in[22];

    int E = in_sizes[1] / 2;
    const int* src = ei;
    const int* dst = ei + E;
    int Etot = E + NTN;
    int eb = (Etot + 255) / 256;

    float *x0, *h, *oa, *ob;
    cudaGetSymbolAddress((void**)&x0, g_x0);
    cudaGetSymbolAddress((void**)&h,  g_h);
    cudaGetSymbolAddress((void**)&oa, g_oa);
    cudaGetSymbolAddress((void**)&ob, g_ob);

    int lingrid = NTN / 32;         // warp per row, RW=4, 8 warps/block
    int gatgrid = NTN * 32 / 256;   // warp per dst node

    k_stats<<<128, 128>>>(x);
    k_deg_count<<<eb, 256>>>(dst, E, Etot);
    k_bn<<<128, 256>>>(x, gamma, beta);
    k_scan_block<<<256, 256>>>();
    k_scan_top<<<1, 256>>>();
    k_scan_add<<<256, 256>>>(Etot);
    k_scatter<<<eb, 256>>>(src, dst, E, Etot);

    k_lin<NFEAT, 3, 16><<<lingrid, 256>>>(x0, W1, as1, ad1, h);
    k_gat<3, 16><<<gatgrid, 256>>>(h, b1, oa);
    k_lin<48, 3, 16><<<lingrid, 256>>>(oa, W2, as2, ad2, h);
    k_gat<3, 16><<<gatgrid, 256>>>(h, b2, ob);
    k_topk<<<NBATCH, 1024>>>(ob, p1, 48, NPERG / 2);
    k_lin<48, 2, 16><<<lingrid, 256>>>(ob, W3, as3, ad3, h);
    k_gat<2, 16><<<gatgrid, 256>>>(h, b3, oa);
    k_lin<32, 1, 10><<<lingrid, 256>>>(oa, W4, as4, ad4, h);
    k_gat<1, 10><<<gatgrid, 256>>>(h, b4, ob);
    k_topk<<<NBATCH, 1024>>>(ob, p2, 10, NPERG / 4);
    k_final<<<NBATCH, 256>>>(ob, (float*)d_out);
}

// round 6
// speedup vs baseline: 1.8838x; 1.1040x over previous
#include <cuda_runtime.h>
#include <math.h>

#define NTN   65536
#define NBATCH 32
#define NPERG 2048
#define NFEAT 128
#define NCLS  10
#define NEGV  (-1e9f)
#define MASKV (-1e30f)
#define ETOTMAX (NTN * 16 + NTN)   // 1,114,112 edges incl self loops

// ---------------- scratch (device globals; no allocation allowed) ----------
__device__ float  g_x0[NTN * NFEAT];   // normalized input
__device__ float  g_h [NTN * 48];      // per-conv linear output (max HC=48)
__device__ float  g_oa[NTN * 48];      // ping buffer
__device__ float  g_ob[NTN * 48];      // pong buffer
__device__ float4 g_alsv[NTN];         // src logits, heads in .x/.y/.z (MASKV = masked)
__device__ float  g_ald[NTN * 3];      // dst logits
__device__ float  g_e  [ETOTMAX * 3];  // per-(edge,head) logit -> alpha cache
__device__ float  g_score[NTN];        // topk raw scores
__device__ int    g_nmask[NTN];        // node mask
__device__ float  g_psum [128 * NFEAT];  // BN partial sums
__device__ float  g_psq  [128 * NFEAT];
// CSR (built once per launch)
__device__ int g_deg [NTN];
__device__ int g_off [NTN + 1];
__device__ int g_cur [NTN];
__device__ int g_bsum[256];
__device__ int g_bsex[256];
__device__ int g_csrc[ETOTMAX];

__device__ __forceinline__ float lrelu(float v) { return v > 0.f ? v : 0.2f * v; }

// ---------------- BN partial stats + zero degrees ----------------
__global__ void k_stats(const float* __restrict__ x) {
    int f = threadIdx.x;                       // 128 threads
    int b = blockIdx.x;                        // 128 blocks
    int r0 = b * (NTN / 128);
    float s = 0.f, s2 = 0.f;
    for (int r = r0; r < r0 + NTN / 128; ++r) {
        float v = x[r * NFEAT + f];
        s += v; s2 += v * v;
    }
    g_psum[b * NFEAT + f] = s;
    g_psq [b * NFEAT + f] = s2;
    int gid = b * 128 + f;
    for (int i = gid; i < NTN; i += 128 * 128) g_deg[i] = 0;
}

// ---------------- degree count ----------------
__global__ void k_deg_count(const int* __restrict__ dst, int E, int Etot) {
    int e = blockIdx.x * blockDim.x + threadIdx.x;
    if (e >= Etot) return;
    int d = (e < E) ? dst[e] : (e - E);
    atomicAdd(&g_deg[d], 1);
}

// ---------------- BN normalize + mask init ----------------
__global__ void k_bn(const float* __restrict__ x, const float* __restrict__ gamma,
                     const float* __restrict__ beta) {
    __shared__ float sg[NFEAT], sb[NFEAT];
    int tid = threadIdx.x;
    if (tid < NFEAT) {
        float s = 0.f, s2 = 0.f;
        for (int b = 0; b < 128; ++b) {
            s  += g_psum[b * NFEAT + tid];
            s2 += g_psq [b * NFEAT + tid];
        }
        float mu  = s  * (1.f / NTN);
        float var = s2 * (1.f / NTN) - mu * mu;
        float rstd = rsqrtf(var + 1e-5f);
        float ga = gamma[tid];
        sg[tid] = ga * rstd;
        sb[tid] = beta[tid] - mu * ga * rstd;
    }
    __syncthreads();
    const float4* x4 = (const float4*)x;
    float4* o4 = (float4*)g_x0;
    int nv = NTN * NFEAT / 4;
    for (int vi = blockIdx.x * blockDim.x + tid; vi < nv; vi += gridDim.x * blockDim.x) {
        float4 v = x4[vi];
        int f0 = (vi * 4) & (NFEAT - 1);
        v.x = v.x * sg[f0]     + sb[f0];
        v.y = v.y * sg[f0 + 1] + sb[f0 + 1];
        v.z = v.z * sg[f0 + 2] + sb[f0 + 2];
        v.w = v.w * sg[f0 + 3] + sb[f0 + 3];
        o4[vi] = v;
    }
    for (int i = blockIdx.x * blockDim.x + tid; i < NTN; i += gridDim.x * blockDim.x)
        g_nmask[i] = 1;
}

// ---------------- hierarchical scan of degrees ----------------
__global__ void k_scan_block() {            // 256 blocks x 256 threads
    __shared__ int sh[256];
    int n = blockIdx.x * 256 + threadIdx.x;
    int v = g_deg[n];
    sh[threadIdx.x] = v;
    __syncthreads();
    for (int o = 1; o < 256; o <<= 1) {
        int t = (threadIdx.x >= o) ? sh[threadIdx.x - o] : 0;
        __syncthreads();
        sh[threadIdx.x] += t;
        __syncthreads();
    }
    g_off[n] = sh[threadIdx.x] - v;
    if (threadIdx.x == 255) g_bsum[blockIdx.x] = sh[255];
}

__global__ void k_scan_top() {              // 1 block x 256 threads
    __shared__ int sh[256];
    int v = g_bsum[threadIdx.x];
    sh[threadIdx.x] = v;
    __syncthreads();
    for (int o = 1; o < 256; o <<= 1) {
        int t = (threadIdx.x >= o) ? sh[threadIdx.x - o] : 0;
        __syncthreads();
        sh[threadIdx.x] += t;
        __syncthreads();
    }
    g_bsex[threadIdx.x] = sh[threadIdx.x] - v;
}

__global__ void k_scan_add(int Etot) {      // 256 blocks x 256 threads
    int n = blockIdx.x * 256 + threadIdx.x;
    int o = g_off[n] + g_bsex[blockIdx.x];
    g_off[n] = o;
    g_cur[n] = o;
    if (n == 0) g_off[NTN] = Etot;
}

// ---------------- scatter edges into CSR ----------------
__global__ void k_scatter(const int* __restrict__ src, const int* __restrict__ dst,
                          int E, int Etot) {
    int e = blockIdx.x * blockDim.x + threadIdx.x;
    if (e >= Etot) return;
    int s, d;
    if (e < E) { s = src[e]; d = dst[e]; } else { s = e - E; d = s; }
    int pos = atomicAdd(&g_cur[d], 1);
    g_csrc[pos] = s;
}

// ---------------- fused linear + attention logits ----------------
// warp per 4 rows (register-blocked); lane owns channel pair (2l, 2l+1);
// W staged in smem and each float2 loaded ONCE per 4 rows.
template <int Fin, int H, int C>
__global__ __launch_bounds__(256) void k_lin(const float* __restrict__ xin,
                                             const float* __restrict__ W,
                                             const float* __restrict__ a_s,
                                             const float* __restrict__ a_d,
                                             float* __restrict__ h) {
    constexpr int HC = H * C;
    constexpr int RW = 4;
    __shared__ float Ws[Fin * HC];
    __shared__ float xs[8][RW * Fin];
    __shared__ float asv[HC], adv[HC];
    int tid = threadIdx.x, lane = tid & 31, wid = tid >> 5;
    for (int i = tid; i < Fin * HC; i += 256) Ws[i] = W[i];
    if (tid < HC) { asv[tid] = a_s[tid]; adv[tid] = a_d[tid]; }
    __syncthreads();

    int rbase = (blockIdx.x * 8 + wid) * RW;
    int c0 = 2 * lane;
    bool act = (c0 < HC);

    // cooperative load of 4 contiguous rows
    const float4* xin4 = (const float4*)(xin + (size_t)rbase * Fin);
    float4* xs4 = (float4*)xs[wid];
    #pragma unroll
    for (int t = lane; t < RW * Fin / 4; t += 32) xs4[t] = xin4[t];
    __syncwarp();

    float ax[RW], ay[RW];
    #pragma unroll
    for (int r = 0; r < RW; ++r) { ax[r] = 0.f; ay[r] = 0.f; }

    if (act) {
        #pragma unroll 4
        for (int i0 = 0; i0 < Fin; i0 += 4) {
            float2 w0 = *(const float2*)&Ws[(i0 + 0) * HC + c0];
            float2 w1 = *(const float2*)&Ws[(i0 + 1) * HC + c0];
            float2 w2 = *(const float2*)&Ws[(i0 + 2) * HC + c0];
            float2 w3 = *(const float2*)&Ws[(i0 + 3) * HC + c0];
            #pragma unroll
            for (int r = 0; r < RW; ++r) {
                float4 xv = *(const float4*)&xs[wid][r * Fin + i0];
                ax[r] += xv.x * w0.x; ay[r] += xv.x * w0.y;
                ax[r] += xv.y * w1.x; ay[r] += xv.y * w1.y;
                ax[r] += xv.z * w2.x; ay[r] += xv.z * w2.y;
                ax[r] += xv.w * w3.x; ay[r] += xv.w * w3.y;
            }
        }
        #pragma unroll
        for (int r = 0; r < RW; ++r)
            *(float2*)(h + (size_t)(rbase + r) * HC + c0) = make_float2(ax[r], ay[r]);
    }

    // attention logits per row
    #pragma unroll
    for (int r = 0; r < RW; ++r) {
        float ps = 0.f, pd = 0.f;
        if (act) {
            ps = ax[r] * asv[c0] + ay[r] * asv[c0 + 1];
            pd = ax[r] * adv[c0] + ay[r] * adv[c0 + 1];
        }
        if (C == 16) {   // 8-lane head groups
            #pragma unroll
            for (int o = 4; o; o >>= 1) {
                ps += __shfl_xor_sync(0xffffffffu, ps, o);
                pd += __shfl_xor_sync(0xffffffffu, pd, o);
            }
        } else {         // H == 1: full warp
            #pragma unroll
            for (int o = 16; o; o >>= 1) {
                ps += __shfl_xor_sync(0xffffffffu, ps, o);
                pd += __shfl_xor_sync(0xffffffffu, pd, o);
            }
        }
        float p1 = __shfl_sync(0xffffffffu, ps, 8);
        float p2 = __shfl_sync(0xffffffffu, ps, 16);
        float d1 = __shfl_sync(0xffffffffu, pd, 8);
        float d2 = __shfl_sync(0xffffffffu, pd, 16);
        if (lane == 0) {
            int rr = rbase + r;
            int msk = g_nmask[rr];
            if (H == 3) {
                g_alsv[rr] = msk ? make_float4(ps, p1, p2, 0.f)
                                 : make_float4(MASKV, MASKV, MASKV, 0.f);
                g_ald[rr * 3]     = pd;
                g_ald[rr * 3 + 1] = d1;
                g_ald[rr * 3 + 2] = d2;
            } else if (H == 2) {
                g_alsv[rr] = msk ? make_float4(ps, p1, 0.f, 0.f)
                                 : make_float4(MASKV, MASKV, 0.f, 0.f);
                g_ald[rr * 3]     = pd;
                g_ald[rr * 3 + 1] = d1;
            } else {
                g_alsv[rr] = msk ? make_float4(ps, 0.f, 0.f, 0.f)
                                 : make_float4(MASKV, 0.f, 0.f, 0.f);
                g_ald[rr * 3] = pd;
            }
        }
    }
}

// ---------------- fused attention softmax + aggregation ----------------
// warp per dst node; phase A: one float4 gather per edge, online softmax,
// alpha cached to g_e; phase B: pure alpha*h[src] accumulation.
template <int H, int C>
__global__ __launch_bounds__(256) void k_gat(const float* __restrict__ h,
                                             const float* __restrict__ b,
                                             float* __restrict__ out) {
    constexpr int HC = H * C;
    int d = (blockIdx.x * blockDim.x + threadIdx.x) >> 5;
    if (d >= NTN) return;
    int lane = threadIdx.x & 31;
    int c0 = 2 * lane;
    bool act = (c0 < HC);

    if (!g_nmask[d]) {
        if (act) *(float2*)(out + (size_t)d * HC + c0) = make_float2(b[c0], b[c0 + 1]);
        return;
    }

    int beg = g_off[d], end = g_off[d + 1];
    float ald_d[H], m[H], den[H];
    #pragma unroll
    for (int hh = 0; hh < H; ++hh) {
        ald_d[hh] = g_ald[d * 3 + hh];
        m[hh] = NEGV; den[hh] = 0.f;
    }

    // phase A: logit compute + cache + online softmax (lanes stride edges)
    for (int i = beg + lane; i < end; i += 32) {
        int s = g_csrc[i];
        float4 av = g_alsv[s];          // single 128-bit gather, all heads
        float avh[3] = {av.x, av.y, av.z};
        #pragma unroll
        for (int hh = 0; hh < H; ++hh) {
            float v = lrelu(avh[hh] + ald_d[hh]);
            g_e[i * H + hh] = v;
            if (v <= m[hh]) {
                den[hh] += __expf(v - m[hh]);
            } else {
                den[hh] = den[hh] * __expf(m[hh] - v) + 1.f;
                m[hh] = v;
            }
        }
    }
    #pragma unroll
    for (int o = 16; o; o >>= 1) {
        #pragma unroll
        for (int hh = 0; hh < H; ++hh) {
            float mo = __shfl_xor_sync(0xffffffffu, m[hh], o);
            float eo = __shfl_xor_sync(0xffffffffu, den[hh], o);
            float nm = fmaxf(m[hh], mo);
            den[hh] = den[hh] * __expf(m[hh] - nm) + eo * __expf(mo - nm);
            m[hh] = nm;
        }
    }
    float inv[H];
    #pragma unroll
    for (int hh = 0; hh < H; ++hh) inv[hh] = 1.f / fmaxf(den[hh], 1e-16f);

    // convert cached logits to alpha in place (masked edges -> 0)
    for (int i = beg + lane; i < end; i += 32) {
        #pragma unroll
        for (int hh = 0; hh < H; ++hh) {
            float v = g_e[i * H + hh];
            g_e[i * H + hh] = (v < -1e20f) ? 0.f : __expf(v - m[hh]) * inv[hh];
        }
    }
    __syncwarp();

    int hh0 = c0 / C;

    // phase B: serial edges, lanes own channel pairs; predicated gather
    float accx = 0.f, accy = 0.f;
    #pragma unroll 4
    for (int i = beg; i < end; ++i) {
        float a = act ? g_e[i * H + hh0] : 0.f;
        int s = g_csrc[i];
        if (a > 0.f) {
            float2 hv = *(const float2*)(h + (size_t)s * HC + c0);
            accx += a * hv.x;
            accy += a * hv.y;
        }
    }
    if (act) *(float2*)(out + (size_t)d * HC + c0) = make_float2(accx + b[c0], accy + b[c0 + 1]);
}

// ---------------- TopK pooling ----------------
__global__ void k_topk(float* __restrict__ x, const float* __restrict__ p,
                       int F, int kkeep) {
    __shared__ float ss[NPERG];
    __shared__ int   wsum[32];
    __shared__ int   wsex[32];
    __shared__ float s_thr;
    __shared__ int   s_need;
    int g = blockIdx.x;
    int base = g * NPERG;
    int tid = threadIdx.x;
    int lane = tid & 31, wid = tid >> 5;

    float nrm = 0.f;
    for (int i = 0; i < F; ++i) { float pv = p[i]; nrm += pv * pv; }
    nrm = rsqrtf(nrm);

    for (int n = tid; n < NPERG; n += blockDim.x) {
        int node = base + n;
        const float* xr = x + node * F;
        float sc = 0.f;
        for (int i = 0; i < F; ++i) sc += xr[i] * p[i];
        sc *= nrm;
        g_score[node] = sc;
        ss[n] = g_nmask[node] ? sc : NEGV;
    }
    __syncthreads();

    for (int kk = 2; kk <= NPERG; kk <<= 1) {
        for (int j = kk >> 1; j > 0; j >>= 1) {
            for (int i = tid; i < NPERG; i += blockDim.x) {
                int ixj = i ^ j;
                if (ixj > i) {
                    float a = ss[i], bb = ss[ixj];
                    bool up = ((i & kk) == 0);
                    if ((a > bb) == up) { ss[i] = bb; ss[ixj] = a; }
                }
            }
            __syncthreads();
        }
    }

    if (tid == 0) {
        float thr = ss[NPERG - kkeep];
        int lo = NPERG - kkeep, hi = NPERG;
        while (lo < hi) {
            int mid = (lo + hi) >> 1;
            if (ss[mid] > thr) hi = mid; else lo = mid + 1;
        }
        s_thr = thr;
        s_need = kkeep - (NPERG - lo);
    }
    __syncthreads();
    float thr = s_thr;
    int need_eq = s_need;

    int n0 = tid * 2, n1 = n0 + 1;
    float sc0 = g_nmask[base + n0] ? g_score[base + n0] : NEGV;
    float sc1 = g_nmask[base + n1] ? g_score[base + n1] : NEGV;
    int f0 = (sc0 == thr) ? 1 : 0;
    int f1 = (sc1 == thr) ? 1 : 0;
    int lsum = f0 + f1;
    int incl = lsum;
    #pragma unroll
    for (int o = 1; o < 32; o <<= 1) {
        int t = __shfl_up_sync(0xffffffffu, incl, o);
        if (lane >= o) incl += t;
    }
    if (lane == 31) wsum[wid] = incl;
    __syncthreads();
    if (wid == 0) {
        int v = wsum[lane];
        int inc2 = v;
        #pragma unroll
        for (int o = 1; o < 32; o <<= 1) {
            int t = __shfl_up_sync(0xffffffffu, inc2, o);
            if (lane >= o) inc2 += t;
        }
        wsex[lane] = inc2 - v;
    }
    __syncthreads();
    int rank0 = wsex[wid] + (incl - lsum);
    int rank1 = rank0 + f0;

    int keep0 = (sc0 > thr) || (f0 && rank0 < need_eq);
    int keep1 = (sc1 > thr) || (f1 && rank1 < need_eq);

    g_nmask[base + n0] = keep0;
    g_nmask[base + n1] = keep1;
    float t0 = keep0 ? tanhf(g_score[base + n0]) : 0.f;
    float t1 = keep1 ? tanhf(g_score[base + n1]) : 0.f;
    float* xr0 = x + (base + n0) * F;
    float* xr1 = x + (base + n1) * F;
    for (int i = 0; i < F; ++i) xr0[i] *= t0;
    for (int i = 0; i < F; ++i) xr1[i] *= t1;
}

// ---------------- final mean + log_softmax ----------------
__global__ void k_final(const float* __restrict__ x, float* __restrict__ out) {
    __shared__ float red[NCLS][9];
    int g = blockIdx.x;
    int base = g * NPERG;
    float acc[NCLS];
    for (int c = 0; c < NCLS; ++c) acc[c] = 0.f;
    for (int n = threadIdx.x; n < NPERG; n += blockDim.x) {
        const float* xr = x + (base + n) * NCLS;
        for (int c = 0; c < NCLS; ++c) acc[c] += xr[c];
    }
    for (int off = 16; off; off >>= 1)
        for (int c = 0; c < NCLS; ++c)
            acc[c] += __shfl_down_sync(0xffffffffu, acc[c], off);
    int lane = threadIdx.x & 31, wid = threadIdx.x >> 5;
    if (lane == 0)
        for (int c = 0; c < NCLS; ++c) red[c][wid] = acc[c];
    __syncthreads();
    if (threadIdx.x == 0) {
        int nw = blockDim.x / 32;
        float z[NCLS];
        for (int c = 0; c < NCLS; ++c) {
            float s = 0.f;
            for (int w = 0; w < nw; ++w) s += red[c][w];
            z[c] = s * (1.f / (NPERG / 4));
        }
        float mx = z[0];
        for (int c = 1; c < NCLS; ++c) mx = fmaxf(mx, z[c]);
        float se = 0.f;
        for (int c = 0; c < NCLS; ++c) se += expf(z[c] - mx);
        float lse = logf(se) + mx;
        for (int c = 0; c < NCLS; ++c) out[g * NCLS + c] = z[c] - lse;
    }
}

// ---------------- host orchestration ----------------
extern "C" void kernel_launch(void* const* d_in, const int* in_sizes, int n_in,
                              void* d_out, int out_size) {
    const float* x     = (const float*)d_in[0];
    const int*   ei    = (const int*)  d_in[1];
    const float* gamma = (const float*)d_in[3];
    const float* beta  = (const float*)d_in[4];
    const float* W1  = (const float*)d_in[5];
    const float* as1 = (const float*)d_in[6];
    const float* ad1 = (const float*)d_in[7];
    const float* b1  = (const float*)d_in[8];
    const float* W2  = (const float*)d_in[9];
    const float* as2 = (const float*)d_in[10];
    const float* ad2 = (const float*)d_in[11];
    const float* b2  = (const float*)d_in[12];
    const float* W3  = (const float*)d_in[13];
    const float* as3 = (const float*)d_in[14];
    const float* ad3 = (const float*)d_in[15];
    const float* b3  = (const float*)d_in[16];
    const float* W4  = (const float*)d_in[17];
    const float* as4 = (const float*)d_in[18];
    const float* ad4 = (const float*)d_in[19];
    const float* b4  = (const float*)d_in[20];
    const float* p1  = (const float*)d_in[21];
    const float* p2  = (const float*)d_in[22];

    int E = in_sizes[1] / 2;
    const int* src = ei;
    const int* dst = ei + E;
    int Etot = E + NTN;
    int eb = (Etot + 255) / 256;

    float *x0, *h, *oa, *ob;
    cudaGetSymbolAddress((void**)&x0, g_x0);
    cudaGetSymbolAddress((void**)&h,  g_h);
    cudaGetSymbolAddress((void**)&oa, g_oa);
    cudaGetSymbolAddress((void**)&ob, g_ob);

    int lingrid = NTN / 32;         // 8 warps/block x 4 rows/warp
    int gatgrid = NTN * 32 / 256;   // warp per dst node

    k_stats<<<128, 128>>>(x);                            // 0
    k_deg_count<<<eb, 256>>>(dst, E, Etot);              // 1
    k_bn<<<128, 256>>>(x, gamma, beta);                  // 2
    k_scan_block<<<256, 256>>>();                        // 3
    k_scan_top<<<1, 256>>>();                            // 4
    k_lin<NFEAT, 3, 16><<<lingrid, 256>>>(x0, W1, as1, ad1, h);   // 5 <- ncu -s 5 sample
    k_scan_add<<<256, 256>>>(Etot);                      // 6
    k_scatter<<<eb, 256>>>(src, dst, E, Etot);           // 7
    k_gat<3, 16><<<gatgrid, 256>>>(h, b1, oa);           // 8

    k_lin<48, 3, 16><<<lingrid, 256>>>(oa, W2, as2, ad2, h);
    k_gat<3, 16><<<gatgrid, 256>>>(h, b2, ob);
    k_topk<<<NBATCH, 1024>>>(ob, p1, 48, NPERG / 2);
    k_lin<48, 2, 16><<<lingrid, 256>>>(ob, W3, as3, ad3, h);
    k_gat<2, 16><<<gatgrid, 256>>>(h, b3, oa);
    k_lin<32, 1, 10><<<lingrid, 256>>>(oa, W4, as4, ad4, h);
    k_gat<1, 10><<<gatgrid, 256>>>(h, b4, ob);
    k_topk<<<NBATCH, 1024>>>(ob, p2, 10, NPERG / 4);
    k_final<<<NBATCH, 256>>>(ob, (float*)d_out);
}

// round 7
// speedup vs baseline: 1.8839x; 1.0000x over previous
#include <cuda_runtime.h>
#include <math.h>

#define NTN   65536
#define NBATCH 32
#define NPERG 2048
#define NFEAT 128
#define NCLS  10
#define NEGV  (-1e9f)
#define MASKV (-1e30f)
#define ETOTMAX (NTN * 16 + NTN)   // 1,114,112 edges incl self loops

// ---------------- scratch (device globals; no allocation allowed) ----------
__device__ float  g_x0[NTN * NFEAT];   // normalized input
__device__ float  g_h [NTN * 48];      // per-conv linear output (max HC=48)
__device__ float  g_oa[NTN * 48];      // ping buffer
__device__ float  g_ob[NTN * 48];      // pong buffer
__device__ float4 g_alsv[NTN];         // src logits, heads in .x/.y/.z (MASKV = masked)
__device__ float  g_ald[NTN * 3];      // dst logits
__device__ float  g_e  [ETOTMAX * 3];  // per-(edge,head) logit -> alpha cache
__device__ float  g_score[NTN];        // topk raw scores
__device__ int    g_nmask[NTN];        // node mask
__device__ float  g_psum [128 * NFEAT];  // BN partial sums
__device__ float  g_psq  [128 * NFEAT];
// CSR (built once per launch)
__device__ int g_deg [NTN];
__device__ int g_off [NTN + 1];
__device__ int g_cur [NTN];
__device__ int g_bsum[256];
__device__ int g_bsex[256];
__device__ int g_csrc[ETOTMAX];

__device__ __forceinline__ float lrelu(float v) { return v > 0.f ? v : 0.2f * v; }

// ---------------- BN partial stats + zero degrees ----------------
__global__ void k_stats(const float* __restrict__ x) {
    int f = threadIdx.x;                       // 128 threads
    int b = blockIdx.x;                        // 128 blocks
    int r0 = b * (NTN / 128);
    float s = 0.f, s2 = 0.f;
    for (int r = r0; r < r0 + NTN / 128; ++r) {
        float v = x[r * NFEAT + f];
        s += v; s2 += v * v;
    }
    g_psum[b * NFEAT + f] = s;
    g_psq [b * NFEAT + f] = s2;
    int gid = b * 128 + f;
    for (int i = gid; i < NTN; i += 128 * 128) g_deg[i] = 0;
}

// ---------------- degree count ----------------
__global__ void k_deg_count(const int* __restrict__ dst, int E, int Etot) {
    int e = blockIdx.x * blockDim.x + threadIdx.x;
    if (e >= Etot) return;
    int d = (e < E) ? dst[e] : (e - E);
    atomicAdd(&g_deg[d], 1);
}

// ---------------- BN normalize + mask init ----------------
__global__ void k_bn(const float* __restrict__ x, const float* __restrict__ gamma,
                     const float* __restrict__ beta) {
    __shared__ float sg[NFEAT], sb[NFEAT];
    int tid = threadIdx.x;
    if (tid < NFEAT) {
        float s = 0.f, s2 = 0.f;
        for (int b = 0; b < 128; ++b) {
            s  += g_psum[b * NFEAT + tid];
            s2 += g_psq [b * NFEAT + tid];
        }
        float mu  = s  * (1.f / NTN);
        float var = s2 * (1.f / NTN) - mu * mu;
        float rstd = rsqrtf(var + 1e-5f);
        float ga = gamma[tid];
        sg[tid] = ga * rstd;
        sb[tid] = beta[tid] - mu * ga * rstd;
    }
    __syncthreads();
    const float4* x4 = (const float4*)x;
    float4* o4 = (float4*)g_x0;
    int nv = NTN * NFEAT / 4;
    for (int vi = blockIdx.x * blockDim.x + tid; vi < nv; vi += gridDim.x * blockDim.x) {
        float4 v = x4[vi];
        int f0 = (vi * 4) & (NFEAT - 1);
        v.x = v.x * sg[f0]     + sb[f0];
        v.y = v.y * sg[f0 + 1] + sb[f0 + 1];
        v.z = v.z * sg[f0 + 2] + sb[f0 + 2];
        v.w = v.w * sg[f0 + 3] + sb[f0 + 3];
        o4[vi] = v;
    }
    for (int i = blockIdx.x * blockDim.x + tid; i < NTN; i += gridDim.x * blockDim.x)
        g_nmask[i] = 1;
}

// ---------------- hierarchical scan of degrees ----------------
__global__ void k_scan_block() {            // 256 blocks x 256 threads
    __shared__ int sh[256];
    int n = blockIdx.x * 256 + threadIdx.x;
    int v = g_deg[n];
    sh[threadIdx.x] = v;
    __syncthreads();
    for (int o = 1; o < 256; o <<= 1) {
        int t = (threadIdx.x >= o) ? sh[threadIdx.x - o] : 0;
        __syncthreads();
        sh[threadIdx.x] += t;
        __syncthreads();
    }
    g_off[n] = sh[threadIdx.x] - v;
    if (threadIdx.x == 255) g_bsum[blockIdx.x] = sh[255];
}

__global__ void k_scan_top() {              // 1 block x 256 threads
    __shared__ int sh[256];
    int v = g_bsum[threadIdx.x];
    sh[threadIdx.x] = v;
    __syncthreads();
    for (int o = 1; o < 256; o <<= 1) {
        int t = (threadIdx.x >= o) ? sh[threadIdx.x - o] : 0;
        __syncthreads();
        sh[threadIdx.x] += t;
        __syncthreads();
    }
    g_bsex[threadIdx.x] = sh[threadIdx.x] - v;
}

__global__ void k_scan_add(int Etot) {      // 256 blocks x 256 threads
    int n = blockIdx.x * 256 + threadIdx.x;
    int o = g_off[n] + g_bsex[blockIdx.x];
    g_off[n] = o;
    g_cur[n] = o;
    if (n == 0) g_off[NTN] = Etot;
}

// ---------------- scatter edges into CSR ----------------
__global__ void k_scatter(const int* __restrict__ src, const int* __restrict__ dst,
                          int E, int Etot) {
    int e = blockIdx.x * blockDim.x + threadIdx.x;
    if (e >= Etot) return;
    int s, d;
    if (e < E) { s = src[e]; d = dst[e]; } else { s = e - E; d = s; }
    int pos = atomicAdd(&g_cur[d], 1);
    g_csrc[pos] = s;
}

// ---------------- fused linear + attention logits ----------------
// warp per 4 rows (register-blocked); lane owns channel pair (2l, 2l+1);
// W staged in smem and each float2 loaded ONCE per 4 rows.
template <int Fin, int H, int C>
__global__ __launch_bounds__(256) void k_lin(const float* __restrict__ xin,
                                             const float* __restrict__ W,
                                             const float* __restrict__ a_s,
                                             const float* __restrict__ a_d,
                                             float* __restrict__ h) {
    constexpr int HC = H * C;
    constexpr int RW = 4;
    __shared__ float Ws[Fin * HC];
    __shared__ float xs[8][RW * Fin];
    __shared__ float asv[HC], adv[HC];
    int tid = threadIdx.x, lane = tid & 31, wid = tid >> 5;
    for (int i = tid; i < Fin * HC; i += 256) Ws[i] = W[i];
    if (tid < HC) { asv[tid] = a_s[tid]; adv[tid] = a_d[tid]; }
    __syncthreads();

    int rbase = (blockIdx.x * 8 + wid) * RW;
    int c0 = 2 * lane;
    bool act = (c0 < HC);

    // cooperative load of 4 contiguous rows
    const float4* xin4 = (const float4*)(xin + (size_t)rbase * Fin);
    float4* xs4 = (float4*)xs[wid];
    #pragma unroll
    for (int t = lane; t < RW * Fin / 4; t += 32) xs4[t] = xin4[t];
    __syncwarp();

    float ax[RW], ay[RW];
    #pragma unroll
    for (int r = 0; r < RW; ++r) { ax[r] = 0.f; ay[r] = 0.f; }

    if (act) {
        #pragma unroll 4
        for (int i0 = 0; i0 < Fin; i0 += 4) {
            float2 w0 = *(const float2*)&Ws[(i0 + 0) * HC + c0];
            float2 w1 = *(const float2*)&Ws[(i0 + 1) * HC + c0];
            float2 w2 = *(const float2*)&Ws[(i0 + 2) * HC + c0];
            float2 w3 = *(const float2*)&Ws[(i0 + 3) * HC + c0];
            #pragma unroll
            for (int r = 0; r < RW; ++r) {
                float4 xv = *(const float4*)&xs[wid][r * Fin + i0];
                ax[r] += xv.x * w0.x; ay[r] += xv.x * w0.y;
                ax[r] += xv.y * w1.x; ay[r] += xv.y * w1.y;
                ax[r] += xv.z * w2.x; ay[r] += xv.z * w2.y;
                ax[r] += xv.w * w3.x; ay[r] += xv.w * w3.y;
            }
        }
        #pragma unroll
        for (int r = 0; r < RW; ++r)
            *(float2*)(h + (size_t)(rbase + r) * HC + c0) = make_float2(ax[r], ay[r]);
    }

    // attention logits per row
    #pragma unroll
    for (int r = 0; r < RW; ++r) {
        float ps = 0.f, pd = 0.f;
        if (act) {
            ps = ax[r] * asv[c0] + ay[r] * asv[c0 + 1];
            pd = ax[r] * adv[c0] + ay[r] * adv[c0 + 1];
        }
        if (C == 16) {   // 8-lane head groups
            #pragma unroll
            for (int o = 4; o; o >>= 1) {
                ps += __shfl_xor_sync(0xffffffffu, ps, o);
                pd += __shfl_xor_sync(0xffffffffu, pd, o);
            }
        } else {         // H == 1: full warp
            #pragma unroll
            for (int o = 16; o; o >>= 1) {
                ps += __shfl_xor_sync(0xffffffffu, ps, o);
                pd += __shfl_xor_sync(0xffffffffu, pd, o);
            }
        }
        float p1 = __shfl_sync(0xffffffffu, ps, 8);
        float p2 = __shfl_sync(0xffffffffu, ps, 16);
        float d1 = __shfl_sync(0xffffffffu, pd, 8);
        float d2 = __shfl_sync(0xffffffffu, pd, 16);
        if (lane == 0) {
            int rr = rbase + r;
            int msk = g_nmask[rr];
            if (H == 3) {
                g_alsv[rr] = msk ? make_float4(ps, p1, p2, 0.f)
                                 : make_float4(MASKV, MASKV, MASKV, 0.f);
                g_ald[rr * 3]     = pd;
                g_ald[rr * 3 + 1] = d1;
                g_ald[rr * 3 + 2] = d2;
            } else if (H == 2) {
                g_alsv[rr] = msk ? make_float4(ps, p1, 0.f, 0.f)
                                 : make_float4(MASKV, MASKV, 0.f, 0.f);
                g_ald[rr * 3]     = pd;
                g_ald[rr * 3 + 1] = d1;
            } else {
                g_alsv[rr] = msk ? make_float4(ps, 0.f, 0.f, 0.f)
                                 : make_float4(MASKV, 0.f, 0.f, 0.f);
                g_ald[rr * 3] = pd;
            }
        }
    }
}

// ---------------- fused attention softmax + aggregation ----------------
// warp per dst node; phase A: one float4 gather per edge, online softmax,
// alpha cached to g_e; phase B: pure alpha*h[src] accumulation.
template <int H, int C>
__global__ __launch_bounds__(256) void k_gat(const float* __restrict__ h,
                                             const float* __restrict__ b,
                                             float* __restrict__ out) {
    constexpr int HC = H * C;
    int d = (blockIdx.x * blockDim.x + threadIdx.x) >> 5;
    if (d >= NTN) return;
    int lane = threadIdx.x & 31;
    int c0 = 2 * lane;
    bool act = (c0 < HC);

    if (!g_nmask[d]) {
        if (act) *(float2*)(out + (size_t)d * HC + c0) = make_float2(b[c0], b[c0 + 1]);
        return;
    }

    int beg = g_off[d], end = g_off[d + 1];
    float ald_d[H], m[H], den[H];
    #pragma unroll
    for (int hh = 0; hh < H; ++hh) {
        ald_d[hh] = g_ald[d * 3 + hh];
        m[hh] = NEGV; den[hh] = 0.f;
    }

    // phase A: logit compute + cache + online softmax (lanes stride edges)
    for (int i = beg + lane; i < end; i += 32) {
        int s = g_csrc[i];
        float4 av = g_alsv[s];          // single 128-bit gather, all heads
        float avh[3] = {av.x, av.y, av.z};
        #pragma unroll
        for (int hh = 0; hh < H; ++hh) {
            float v = lrelu(avh[hh] + ald_d[hh]);
            g_e[i * H + hh] = v;
            if (v <= m[hh]) {
                den[hh] += __expf(v - m[hh]);
            } else {
                den[hh] = den[hh] * __expf(m[hh] - v) + 1.f;
                m[hh] = v;
            }
        }
    }
    #pragma unroll
    for (int o = 16; o; o >>= 1) {
        #pragma unroll
        for (int hh = 0; hh < H; ++hh) {
            float mo = __shfl_xor_sync(0xffffffffu, m[hh], o);
            float eo = __shfl_xor_sync(0xffffffffu, den[hh], o);
            float nm = fmaxf(m[hh], mo);
            den[hh] = den[hh] * __expf(m[hh] - nm) + eo * __expf(mo - nm);
            m[hh] = nm;
        }
    }
    float inv[H];
    #pragma unroll
    for (int hh = 0; hh < H; ++hh) inv[hh] = 1.f / fmaxf(den[hh], 1e-16f);

    // convert cached logits to alpha in place (masked edges -> 0)
    for (int i = beg + lane; i < end; i += 32) {
        #pragma unroll
        for (int hh = 0; hh < H; ++hh) {
            float v = g_e[i * H + hh];
            g_e[i * H + hh] = (v < -1e20f) ? 0.f : __expf(v - m[hh]) * inv[hh];
        }
    }
    __syncwarp();

    int hh0 = c0 / C;

    // phase B: serial edges, lanes own channel pairs; predicated gather
    float accx = 0.f, accy = 0.f;
    #pragma unroll 4
    for (int i = beg; i < end; ++i) {
        float a = act ? g_e[i * H + hh0] : 0.f;
        int s = g_csrc[i];
        if (a > 0.f) {
            float2 hv = *(const float2*)(h + (size_t)s * HC + c0);
            accx += a * hv.x;
            accy += a * hv.y;
        }
    }
    if (act) *(float2*)(out + (size_t)d * HC + c0) = make_float2(accx + b[c0], accy + b[c0 + 1]);
}

// ---------------- TopK pooling ----------------
__global__ void k_topk(float* __restrict__ x, const float* __restrict__ p,
                       int F, int kkeep) {
    __shared__ float ss[NPERG];
    __shared__ int   wsum[32];
    __shared__ int   wsex[32];
    __shared__ float s_thr;
    __shared__ int   s_need;
    int g = blockIdx.x;
    int base = g * NPERG;
    int tid = threadIdx.x;
    int lane = tid & 31, wid = tid >> 5;

    float nrm = 0.f;
    for (int i = 0; i < F; ++i) { float pv = p[i]; nrm += pv * pv; }
    nrm = rsqrtf(nrm);

    for (int n = tid; n < NPERG; n += blockDim.x) {
        int node = base + n;
        const float* xr = x + node * F;
        float sc = 0.f;
        for (int i = 0; i < F; ++i) sc += xr[i] * p[i];
        sc *= nrm;
        g_score[node] = sc;
        ss[n] = g_nmask[node] ? sc : NEGV;
    }
    __syncthreads();

    for (int kk = 2; kk <= NPERG; kk <<= 1) {
        for (int j = kk >> 1; j > 0; j >>= 1) {
            for (int i = tid; i < NPERG; i += blockDim.x) {
                int ixj = i ^ j;
                if (ixj > i) {
                    float a = ss[i], bb = ss[ixj];
                    bool up = ((i & kk) == 0);
                    if ((a > bb) == up) { ss[i] = bb; ss[ixj] = a; }
                }
            }
            __syncthreads();
        }
    }

    if (tid == 0) {
        float thr = ss[NPERG - kkeep];
        int lo = NPERG - kkeep, hi = NPERG;
        while (lo < hi) {
            int mid = (lo + hi) >> 1;
            if (ss[mid] > thr) hi = mid; else lo = mid + 1;
        }
        s_thr = thr;
        s_need = kkeep - (NPERG - lo);
    }
    __syncthreads();
    float thr = s_thr;
    int need_eq = s_need;

    int n0 = tid * 2, n1 = n0 + 1;
    float sc0 = g_nmask[base + n0] ? g_score[base + n0] : NEGV;
    float sc1 = g_nmask[base + n1] ? g_score[base + n1] : NEGV;
    int f0 = (sc0 == thr) ? 1 : 0;
    int f1 = (sc1 == thr) ? 1 : 0;
    int lsum = f0 + f1;
    int incl = lsum;
    #pragma unroll
    for (int o = 1; o < 32; o <<= 1) {
        int t = __shfl_up_sync(0xffffffffu, incl, o);
        if (lane >= o) incl += t;
    }
    if (lane == 31) wsum[wid] = incl;
    __syncthreads();
    if (wid == 0) {
        int v = wsum[lane];
        int inc2 = v;
        #pragma unroll
        for (int o = 1; o < 32; o <<= 1) {
            int t = __shfl_up_sync(0xffffffffu, inc2, o);
            if (lane >= o) inc2 += t;
        }
        wsex[lane] = inc2 - v;
    }
    __syncthreads();
    int rank0 = wsex[wid] + (incl - lsum);
    int rank1 = rank0 + f0;

    int keep0 = (sc0 > thr) || (f0 && rank0 < need_eq);
    int keep1 = (sc1 > thr) || (f1 && rank1 < need_eq);

    g_nmask[base + n0] = keep0;
    g_nmask[base + n1] = keep1;
    float t0 = keep0 ? tanhf(g_score[base + n0]) : 0.f;
    float t1 = keep1 ? tanhf(g_score[base + n1]) : 0.f;
    float* xr0 = x + (base + n0) * F;
    float* xr1 = x + (base + n1) * F;
    for (int i = 0; i < F; ++i) xr0[i] *= t0;
    for (int i = 0; i < F; ++i) xr1[i] *= t1;
}

// ---------------- final mean + log_softmax ----------------
__global__ void k_final(const float* __restrict__ x, float* __restrict__ out) {
    __shared__ float red[NCLS][9];
    int g = blockIdx.x;
    int base = g * NPERG;
    float acc[NCLS];
    for (int c = 0; c < NCLS; ++c) acc[c] = 0.f;
    for (int n = threadIdx.x; n < NPERG; n += blockDim.x) {
        const float* xr = x + (base + n) * NCLS;
        for (int c = 0; c < NCLS; ++c) acc[c] += xr[c];
    }
    for (int off = 16; off; off >>= 1)
        for (int c = 0; c < NCLS; ++c)
            acc[c] += __shfl_down_sync(0xffffffffu, acc[c], off);
    int lane = threadIdx.x & 31, wid = threadIdx.x >> 5;
    if (lane == 0)
        for (int c = 0; c < NCLS; ++c) red[c][wid] = acc[c];
    __syncthreads();
    if (threadIdx.x == 0) {
        int nw = blockDim.x / 32;
        float z[NCLS];
        for (int c = 0; c < NCLS; ++c) {
            float s = 0.f;
            for (int w = 0; w < nw; ++w) s += red[c][w];
            z[c] = s * (1.f / (NPERG / 4));
        }
        float mx = z[0];
        for (int c = 1; c < NCLS; ++c) mx = fmaxf(mx, z[c]);
        float se = 0.f;
        for (int c = 0; c < NCLS; ++c) se += expf(z[c] - mx);
        float lse = logf(se) + mx;
        for (int c = 0; c < NCLS; ++c) out[g * NCLS + c] = z[c] - lse;
    }
}

// ---------------- host orchestration ----------------
extern "C" void kernel_launch(void* const* d_in, const int* in_sizes, int n_in,
                              void* d_out, int out_size) {
    const float* x     = (const float*)d_in[0];
    const int*   ei    = (const int*)  d_in[1];
    const float* gamma = (const float*)d_in[3];
    const float* beta  = (const float*)d_in[4];
    const float* W1  = (const float*)d_in[5];
    const float* as1 = (const float*)d_in[6];
    const float* ad1 = (const float*)d_in[7];
    const float* b1  = (const float*)d_in[8];
    const float* W2  = (const float*)d_in[9];
    const float* as2 = (const float*)d_in[10];
    const float* ad2 = (const float*)d_in[11];
    const float* b2  = (const float*)d_in[12];
    const float* W3  = (const float*)d_in[13];
    const float* as3 = (const float*)d_in[14];
    const float* ad3 = (const float*)d_in[15];
    const float* b3  = (const float*)d_in[16];
    const float* W4  = (const float*)d_in[17];
    const float* as4 = (const float*)d_in[18];
    const float* ad4 = (const float*)d_in[19];
    const float* b4  = (const float*)d_in[20];
    const float* p1  = (const float*)d_in[21];
    const float* p2  = (const float*)d_in[22];

    int E = in_sizes[1] / 2;
    const int* src = ei;
    const int* dst = ei + E;
    int Etot = E + NTN;
    int eb = (Etot + 255) / 256;

    float *x0, *h, *oa, *ob;
    cudaGetSymbolAddress((void**)&x0, g_x0);
    cudaGetSymbolAddress((void**)&h,  g_h);
    cudaGetSymbolAddress((void**)&oa, g_oa);
    cudaGetSymbolAddress((void**)&ob, g_ob);

    int lingrid = NTN / 32;         // 8 warps/block x 4 rows/warp
    int gatgrid = NTN * 32 / 256;   // warp per dst node

    k_stats<<<128, 128>>>(x);                            // 0
    k_deg_count<<<eb, 256>>>(dst, E, Etot);              // 1
    k_bn<<<128, 256>>>(x, gamma, beta);                  // 2
    k_scan_block<<<256, 256>>>();                        // 3
    k_scan_top<<<1, 256>>>();                            // 4
    k_lin<NFEAT, 3, 16><<<lingrid, 256>>>(x0, W1, as1, ad1, h);   // 5 <- ncu -s 5 sample
    k_scan_add<<<256, 256>>>(Etot);                      // 6
    k_scatter<<<eb, 256>>>(src, dst, E, Etot);           // 7
    k_gat<3, 16><<<gatgrid, 256>>>(h, b1, oa);           // 8

    k_lin<48, 3, 16><<<lingrid, 256>>>(oa, W2, as2, ad2, h);
    k_gat<3, 16><<<gatgrid, 256>>>(h, b2, ob);
    k_topk<<<NBATCH, 1024>>>(ob, p1, 48, NPERG / 2);
    k_lin<48, 2, 16><<<lingrid, 256>>>(ob, W3, as3, ad3, h);
    k_gat<2, 16><<<gatgrid, 256>>>(h, b3, oa);
    k_lin<32, 1, 10><<<lingrid, 256>>>(oa, W4, as4, ad4, h);
    k_gat<1, 10><<<gatgrid, 256>>>(h, b4, ob);
    k_topk<<<NBATCH, 1024>>>(ob, p2, 10, NPERG / 4);
    k_final<<<NBATCH, 256>>>(ob, (float*)d_out);
}

// round 9
// speedup vs baseline: 2.0881x; 1.1084x over previous
#include <cuda_runtime.h>
#include <math.h>

#define NTN   65536
#define NBATCH 32
#define NPERG 2048
#define NFEAT 128
#define NCLS  10
#define NEGV  (-1e9f)
#define MASKV (-1e30f)
#define ETOTMAX (NTN * 16 + NTN)   // 1,114,112 edges incl self loops

// ---------------- scratch (device globals; no allocation allowed) ----------
__device__ float  g_x0[NTN * NFEAT];   // normalized input
__device__ float  g_h [NTN * 48];      // per-conv linear output (max HC=48)
__device__ float  g_oa[NTN * 48];      // ping buffer
__device__ float  g_ob[NTN * 48];      // pong buffer
__device__ float4 g_alsv[NTN];         // src logits, heads in .x/.y/.z (MASKV = masked)
__device__ float  g_ald[NTN * 3];      // dst logits
__device__ float  g_score[NTN];        // topk raw scores
__device__ int    g_nmask[NTN];        // node mask
__device__ float  g_psum [128 * NFEAT];  // BN partial sums
__device__ float  g_psq  [128 * NFEAT];
// CSR (built once per launch)
__device__ int g_deg [NTN];
__device__ int g_off [NTN + 1];
__device__ int g_cur [NTN];
__device__ int g_bsum[256];
__device__ int g_bsex[256];
__device__ int g_csrc[ETOTMAX];

__device__ __forceinline__ float lrelu(float v) { return v > 0.f ? v : 0.2f * v; }

// ---------------- BN partial stats + zero degrees ----------------
__global__ void k_stats(const float* __restrict__ x) {
    int f = threadIdx.x;                       // 128 threads
    int b = blockIdx.x;                        // 128 blocks
    int r0 = b * (NTN / 128);
    float s = 0.f, s2 = 0.f;
    for (int r = r0; r < r0 + NTN / 128; ++r) {
        float v = x[r * NFEAT + f];
        s += v; s2 += v * v;
    }
    g_psum[b * NFEAT + f] = s;
    g_psq [b * NFEAT + f] = s2;
    int gid = b * 128 + f;
    for (int i = gid; i < NTN; i += 128 * 128) g_deg[i] = 0;
}

// ---------------- degree count ----------------
__global__ void k_deg_count(const int* __restrict__ dst, int E, int Etot) {
    int e = blockIdx.x * blockDim.x + threadIdx.x;
    if (e >= Etot) return;
    int d = (e < E) ? dst[e] : (e - E);
    atomicAdd(&g_deg[d], 1);
}

// ---------------- BN normalize + mask init ----------------
__global__ void k_bn(const float* __restrict__ x, const float* __restrict__ gamma,
                     const float* __restrict__ beta) {
    __shared__ float sg[NFEAT], sb[NFEAT];
    int tid = threadIdx.x;
    if (tid < NFEAT) {
        float s = 0.f, s2 = 0.f;
        for (int b = 0; b < 128; ++b) {
            s  += g_psum[b * NFEAT + tid];
            s2 += g_psq [b * NFEAT + tid];
        }
        float mu  = s  * (1.f / NTN);
        float var = s2 * (1.f / NTN) - mu * mu;
        float rstd = rsqrtf(var + 1e-5f);
        float ga = gamma[tid];
        sg[tid] = ga * rstd;
        sb[tid] = beta[tid] - mu * ga * rstd;
    }
    __syncthreads();
    const float4* x4 = (const float4*)x;
    float4* o4 = (float4*)g_x0;
    int nv = NTN * NFEAT / 4;
    for (int vi = blockIdx.x * blockDim.x + tid; vi < nv; vi += gridDim.x * blockDim.x) {
        float4 v = x4[vi];
        int f0 = (vi * 4) & (NFEAT - 1);
        v.x = v.x * sg[f0]     + sb[f0];
        v.y = v.y * sg[f0 + 1] + sb[f0 + 1];
        v.z = v.z * sg[f0 + 2] + sb[f0 + 2];
        v.w = v.w * sg[f0 + 3] + sb[f0 + 3];
        o4[vi] = v;
    }
    for (int i = blockIdx.x * blockDim.x + tid; i < NTN; i += gridDim.x * blockDim.x)
        g_nmask[i] = 1;
}

// ---------------- hierarchical scan of degrees ----------------
__global__ void k_scan_block() {            // 256 blocks x 256 threads
    __shared__ int sh[256];
    int n = blockIdx.x * 256 + threadIdx.x;
    int v = g_deg[n];
    sh[threadIdx.x] = v;
    __syncthreads();
    for (int o = 1; o < 256; o <<= 1) {
        int t = (threadIdx.x >= o) ? sh[threadIdx.x - o] : 0;
        __syncthreads();
        sh[threadIdx.x] += t;
        __syncthreads();
    }
    g_off[n] = sh[threadIdx.x] - v;
    if (threadIdx.x == 255) g_bsum[blockIdx.x] = sh[255];
}

__global__ void k_scan_top() {              // 1 block x 256 threads
    __shared__ int sh[256];
    int v = g_bsum[threadIdx.x];
    sh[threadIdx.x] = v;
    __syncthreads();
    for (int o = 1; o < 256; o <<= 1) {
        int t = (threadIdx.x >= o) ? sh[threadIdx.x - o] : 0;
        __syncthreads();
        sh[threadIdx.x] += t;
        __syncthreads();
    }
    g_bsex[threadIdx.x] = sh[threadIdx.x] - v;
}

__global__ void k_scan_add(int Etot) {      // 256 blocks x 256 threads
    int n = blockIdx.x * 256 + threadIdx.x;
    int o = g_off[n] + g_bsex[blockIdx.x];
    g_off[n] = o;
    g_cur[n] = o;
    if (n == 0) g_off[NTN] = Etot;
}

// ---------------- scatter edges into CSR ----------------
__global__ void k_scatter(const int* __restrict__ src, const int* __restrict__ dst,
                          int E, int Etot) {
    int e = blockIdx.x * blockDim.x + threadIdx.x;
    if (e >= Etot) return;
    int s, d;
    if (e < E) { s = src[e]; d = dst[e]; } else { s = e - E; d = s; }
    int pos = atomicAdd(&g_cur[d], 1);
    g_csrc[pos] = s;
}

// ---------------- fused linear + attention logits ----------------
// warp per 4 rows (register-blocked); lane owns channel pair (2l, 2l+1);
// W staged in smem and each float2 loaded ONCE per 4 rows.
template <int Fin, int H, int C>
__global__ __launch_bounds__(256) void k_lin(const float* __restrict__ xin,
                                             const float* __restrict__ W,
                                             const float* __restrict__ a_s,
                                             const float* __restrict__ a_d,
                                             float* __restrict__ h) {
    constexpr int HC = H * C;
    constexpr int RW = 4;
    __shared__ float Ws[Fin * HC];
    __shared__ float xs[8][RW * Fin];
    __shared__ float asv[HC], adv[HC];
    int tid = threadIdx.x, lane = tid & 31, wid = tid >> 5;
    for (int i = tid; i < Fin * HC; i += 256) Ws[i] = W[i];
    if (tid < HC) { asv[tid] = a_s[tid]; adv[tid] = a_d[tid]; }
    __syncthreads();

    int rbase = (blockIdx.x * 8 + wid) * RW;
    int c0 = 2 * lane;
    bool act = (c0 < HC);

    // cooperative load of 4 contiguous rows
    const float4* xin4 = (const float4*)(xin + (size_t)rbase * Fin);
    float4* xs4 = (float4*)xs[wid];
    #pragma unroll
    for (int t = lane; t < RW * Fin / 4; t += 32) xs4[t] = xin4[t];
    __syncwarp();

    float ax[RW], ay[RW];
    #pragma unroll
    for (int r = 0; r < RW; ++r) { ax[r] = 0.f; ay[r] = 0.f; }

    if (act) {
        #pragma unroll 4
        for (int i0 = 0; i0 < Fin; i0 += 4) {
            float2 w0 = *(const float2*)&Ws[(i0 + 0) * HC + c0];
            float2 w1 = *(const float2*)&Ws[(i0 + 1) * HC + c0];
            float2 w2 = *(const float2*)&Ws[(i0 + 2) * HC + c0];
            float2 w3 = *(const float2*)&Ws[(i0 + 3) * HC + c0];
            #pragma unroll
            for (int r = 0; r < RW; ++r) {
                float4 xv = *(const float4*)&xs[wid][r * Fin + i0];
                ax[r] += xv.x * w0.x; ay[r] += xv.x * w0.y;
                ax[r] += xv.y * w1.x; ay[r] += xv.y * w1.y;
                ax[r] += xv.z * w2.x; ay[r] += xv.z * w2.y;
                ax[r] += xv.w * w3.x; ay[r] += xv.w * w3.y;
            }
        }
        #pragma unroll
        for (int r = 0; r < RW; ++r)
            *(float2*)(h + (size_t)(rbase + r) * HC + c0) = make_float2(ax[r], ay[r]);
    }

    // attention logits per row
    #pragma unroll
    for (int r = 0; r < RW; ++r) {
        float ps = 0.f, pd = 0.f;
        if (act) {
            ps = ax[r] * asv[c0] + ay[r] * asv[c0 + 1];
            pd = ax[r] * adv[c0] + ay[r] * adv[c0 + 1];
        }
        if (C == 16) {   // 8-lane head groups
            #pragma unroll
            for (int o = 4; o; o >>= 1) {
                ps += __shfl_xor_sync(0xffffffffu, ps, o);
                pd += __shfl_xor_sync(0xffffffffu, pd, o);
            }
        } else {         // H == 1: full warp
            #pragma unroll
            for (int o = 16; o; o >>= 1) {
                ps += __shfl_xor_sync(0xffffffffu, ps, o);
                pd += __shfl_xor_sync(0xffffffffu, pd, o);
            }
        }
        float p1 = __shfl_sync(0xffffffffu, ps, 8);
        float p2 = __shfl_sync(0xffffffffu, ps, 16);
        float d1 = __shfl_sync(0xffffffffu, pd, 8);
        float d2 = __shfl_sync(0xffffffffu, pd, 16);
        if (lane == 0) {
            int rr = rbase + r;
            int msk = g_nmask[rr];
            if (H == 3) {
                g_alsv[rr] = msk ? make_float4(ps, p1, p2, 0.f)
                                 : make_float4(MASKV, MASKV, MASKV, 0.f);
                g_ald[rr * 3]     = pd;
                g_ald[rr * 3 + 1] = d1;
                g_ald[rr * 3 + 2] = d2;
            } else if (H == 2) {
                g_alsv[rr] = msk ? make_float4(ps, p1, 0.f, 0.f)
                                 : make_float4(MASKV, MASKV, 0.f, 0.f);
                g_ald[rr * 3]     = pd;
                g_ald[rr * 3 + 1] = d1;
            } else {
                g_alsv[rr] = msk ? make_float4(ps, 0.f, 0.f, 0.f)
                                 : make_float4(MASKV, 0.f, 0.f, 0.f);
                g_ald[rr * 3] = pd;
            }
        }
    }
}

// ---------------- fused attention softmax + aggregation ----------------
// warp per dst node; per-edge state lives in SHARED memory (no global cache).
// phase A: one float4 gather/edge + online softmax, logits -> smem;
// convert smem logits to alpha; phase B: broadcast LDS + alpha*h[src].
template <int H, int C>
__global__ __launch_bounds__(256) void k_gat(const float* __restrict__ h,
                                             const float* __restrict__ b,
                                             float* __restrict__ out) {
    constexpr int HC = H * C;
    constexpr int CAP = 64;                  // per-warp edge cache capacity
    __shared__ float sAl[8][CAP * H + 1];    // +1 pad: avoid 32-bank alignment
    __shared__ int   sSr[8][CAP + 1];
    int d = (blockIdx.x * blockDim.x + threadIdx.x) >> 5;
    if (d >= NTN) return;
    int lane = threadIdx.x & 31;
    int wid = (threadIdx.x >> 5) & 7;
    int c0 = 2 * lane;
    bool act = (c0 < HC);

    if (!g_nmask[d]) {
        if (act) *(float2*)(out + (size_t)d * HC + c0) = make_float2(b[c0], b[c0 + 1]);
        return;
    }

    int beg = g_off[d], end = g_off[d + 1];
    float ald_d[H], m[H], den[H];
    #pragma unroll
    for (int hh = 0; hh < H; ++hh) {
        ald_d[hh] = g_ald[d * 3 + hh];
        m[hh] = NEGV; den[hh] = 0.f;
    }

    // phase A: gather logits, cache to smem, online softmax (lanes stride edges)
    for (int i = beg + lane; i < end; i += 32) {
        int j = i - beg;
        int s = g_csrc[i];
        float4 av = g_alsv[s];               // single 128-bit gather, all heads
        float avh[3] = {av.x, av.y, av.z};
        if (j < CAP) sSr[wid][j] = s;
        #pragma unroll
        for (int hh = 0; hh < H; ++hh) {
            float v = lrelu(avh[hh] + ald_d[hh]);   // masked: ~-2e29 -> exp 0
            if (j < CAP) sAl[wid][j * H + hh] = v;
            if (v <= m[hh]) {
                den[hh] += __expf(v - m[hh]);
            } else {
                den[hh] = den[hh] * __expf(m[hh] - v) + 1.f;
                m[hh] = v;
            }
        }
    }
    #pragma unroll
    for (int o = 16; o; o >>= 1) {
        #pragma unroll
        for (int hh = 0; hh < H; ++hh) {
            float mo = __shfl_xor_sync(0xffffffffu, m[hh], o);
            float eo = __shfl_xor_sync(0xffffffffu, den[hh], o);
            float nm = fmaxf(m[hh], mo);
            den[hh] = den[hh] * __expf(m[hh] - nm) + eo * __expf(mo - nm);
            m[hh] = nm;
        }
    }
    float inv[H];
    #pragma unroll
    for (int hh = 0; hh < H; ++hh) inv[hh] = 1.f / fmaxf(den[hh], 1e-16f);

    int deg = end - beg;
    int cap = deg < CAP ? deg : CAP;

    // convert smem logits to alpha (masked edges naturally -> 0)
    for (int j = lane; j < cap; j += 32) {
        #pragma unroll
        for (int hh = 0; hh < H; ++hh) {
            float v = sAl[wid][j * H + hh];
            sAl[wid][j * H + hh] = __expf(v - m[hh]) * inv[hh];
        }
    }
    __syncwarp();

    int hh0 = c0 / C;
    float m_my = m[0], inv_my = inv[0];
    #pragma unroll
    for (int hh = 1; hh < H; ++hh)
        if (hh == hh0) { m_my = m[hh]; inv_my = inv[hh]; }
    float ald_my = ald_d[0];
    #pragma unroll
    for (int hh = 1; hh < H; ++hh)
        if (hh == hh0) ald_my = ald_d[hh];

    // phase B: serial edges, lanes own channel pairs; broadcast smem reads
    float accx = 0.f, accy = 0.f;
    #pragma unroll 4
    for (int j = 0; j < cap; ++j) {
        float a = act ? sAl[wid][j * H + hh0] : 0.f;
        int s = sSr[wid][j];
        if (a > 0.f) {
            float2 hv = *(const float2*)(h + (size_t)s * HC + c0);
            accx += a * hv.x;
            accy += a * hv.y;
        }
    }
    // tail for deg > CAP (vanishingly rare): recompute alpha from alsv
    for (int i = beg + CAP; i < end; ++i) {
        int s = g_csrc[i];
        float4 av = g_alsv[s];
        float avh[3] = {av.x, av.y, av.z};
        float v = lrelu(avh[hh0] + ald_my);
        float a = __expf(v - m_my) * inv_my;
        if (a > 0.f && act) {
            float2 hv = *(const float2*)(h + (size_t)s * HC + c0);
            accx += a * hv.x;
            accy += a * hv.y;
        }
    }
    if (act) *(float2*)(out + (size_t)d * HC + c0) = make_float2(accx + b[c0], accy + b[c0 + 1]);
}

// ---------------- TopK pooling ----------------
__global__ void k_topk(float* __restrict__ x, const float* __restrict__ p,
                       int F, int kkeep) {
    __shared__ float ss[NPERG];
    __shared__ int   wsum[32];
    __shared__ int   wsex[32];
    __shared__ float s_thr;
    __shared__ int   s_need;
    int g = blockIdx.x;
    int base = g * NPERG;
    int tid = threadIdx.x;
    int lane = tid & 31, wid = tid >> 5;

    float nrm = 0.f;
    for (int i = 0; i < F; ++i) { float pv = p[i]; nrm += pv * pv; }
    nrm = rsqrtf(nrm);

    for (int n = tid; n < NPERG; n += blockDim.x) {
        int node = base + n;
        const float* xr = x + node * F;
        float sc = 0.f;
        for (int i = 0; i < F; ++i) sc += xr[i] * p[i];
        sc *= nrm;
        g_score[node] = sc;
        ss[n] = g_nmask[node] ? sc : NEGV;
    }
    __syncthreads();

    for (int kk = 2; kk <= NPERG; kk <<= 1) {
        for (int j = kk >> 1; j > 0; j >>= 1) {
            for (int i = tid; i < NPERG; i += blockDim.x) {
                int ixj = i ^ j;
                if (ixj > i) {
                    float a = ss[i], bb = ss[ixj];
                    bool up = ((i & kk) == 0);
                    if ((a > bb) == up) { ss[i] = bb; ss[ixj] = a; }
                }
            }
            __syncthreads();
        }
    }

    if (tid == 0) {
        float thr = ss[NPERG - kkeep];
        int lo = NPERG - kkeep, hi = NPERG;
        while (lo < hi) {
            int mid = (lo + hi) >> 1;
            if (ss[mid] > thr) hi = mid; else lo = mid + 1;
        }
        s_thr = thr;
        s_need = kkeep - (NPERG - lo);
    }
    __syncthreads();
    float thr = s_thr;
    int need_eq = s_need;

    int n0 = tid * 2, n1 = n0 + 1;
    float sc0 = g_nmask[base + n0] ? g_score[base + n0] : NEGV;
    float sc1 = g_nmask[base + n1] ? g_score[base + n1] : NEGV;
    int f0 = (sc0 == thr) ? 1 : 0;
    int f1 = (sc1 == thr) ? 1 : 0;
    int lsum = f0 + f1;
    int incl = lsum;
    #pragma unroll
    for (int o = 1; o < 32; o <<= 1) {
        int t = __shfl_up_sync(0xffffffffu, incl, o);
        if (lane >= o) incl += t;
    }
    if (lane == 31) wsum[wid] = incl;
    __syncthreads();
    if (wid == 0) {
        int v = wsum[lane];
        int inc2 = v;
        #pragma unroll
        for (int o = 1; o < 32; o <<= 1) {
            int t = __shfl_up_sync(0xffffffffu, inc2, o);
            if (lane >= o) inc2 += t;
        }
        wsex[lane] = inc2 - v;
    }
    __syncthreads();
    int rank0 = wsex[wid] + (incl - lsum);
    int rank1 = rank0 + f0;

    int keep0 = (sc0 > thr) || (f0 && rank0 < need_eq);
    int keep1 = (sc1 > thr) || (f1 && rank1 < need_eq);

    g_nmask[base + n0] = keep0;
    g_nmask[base + n1] = keep1;
    float t0 = keep0 ? tanhf(g_score[base + n0]) : 0.f;
    float t1 = keep1 ? tanhf(g_score[base + n1]) : 0.f;
    float* xr0 = x + (base + n0) * F;
    float* xr1 = x + (base + n1) * F;
    for (int i = 0; i < F; ++i) xr0[i] *= t0;
    for (int i = 0; i < F; ++i) xr1[i] *= t1;
}

// ---------------- final mean + log_softmax ----------------
__global__ void k_final(const float* __restrict__ x, float* __restrict__ out) {
    __shared__ float red[NCLS][9];
    int g = blockIdx.x;
    int base = g * NPERG;
    float acc[NCLS];
    for (int c = 0; c < NCLS; ++c) acc[c] = 0.f;
    for (int n = threadIdx.x; n < NPERG; n += blockDim.x) {
        const float* xr = x + (base + n) * NCLS;
        for (int c = 0; c < NCLS; ++c) acc[c] += xr[c];
    }
    for (int off = 16; off; off >>= 1)
        for (int c = 0; c < NCLS; ++c)
            acc[c] += __shfl_down_sync(0xffffffffu, acc[c], off);
    int lane = threadIdx.x & 31, wid = threadIdx.x >> 5;
    if (lane == 0)
        for (int c = 0; c < NCLS; ++c) red[c][wid] = acc[c];
    __syncthreads();
    if (threadIdx.x == 0) {
        int nw = blockDim.x / 32;
        float z[NCLS];
        for (int c = 0; c < NCLS; ++c) {
            float s = 0.f;
            for (int w = 0; w < nw; ++w) s += red[c][w];
            z[c] = s * (1.f / (NPERG / 4));
        }
        float mx = z[0];
        for (int c = 1; c < NCLS; ++c) mx = fmaxf(mx, z[c]);
        float se = 0.f;
        for (int c = 0; c < NCLS; ++c) se += expf(z[c] - mx);
        float lse = logf(se) + mx;
        for (int c = 0; c < NCLS; ++c) out[g * NCLS + c] = z[c] - lse;
    }
}

// ---------------- host orchestration ----------------
extern "C" void kernel_launch(void* const* d_in, const int* in_sizes, int n_in,
                              void* d_out, int out_size) {
    const float* x     = (const float*)d_in[0];
    const int*   ei    = (const int*)  d_in[1];
    const float* gamma = (const float*)d_in[3];
    const float* beta  = (const float*)d_in[4];
    const float* W1  = (const float*)d_in[5];
    const float* as1 = (const float*)d_in[6];
    const float* ad1 = (const float*)d_in[7];
    const float* b1  = (const float*)d_in[8];
    const float* W2  = (const float*)d_in[9];
    const float* as2 = (const float*)d_in[10];
    const float* ad2 = (const float*)d_in[11];
    const float* b2  = (const float*)d_in[12];
    const float* W3  = (const float*)d_in[13];
    const float* as3 = (const float*)d_in[14];
    const float* ad3 = (const float*)d_in[15];
    const float* b3  = (const float*)d_in[16];
    const float* W4  = (const float*)d_in[17];
    const float* as4 = (const float*)d_in[18];
    const float* ad4 = (const float*)d_in[19];
    const float* b4  = (const float*)d_in[20];
    const float* p1  = (const float*)d_in[21];
    const float* p2  = (const float*)d_in[22];

    int E = in_sizes[1] / 2;
    const int* src = ei;
    const int* dst = ei + E;
    int Etot = E + NTN;
    int eb = (Etot + 255) / 256;

    float *x0, *h, *oa, *ob;
    cudaGetSymbolAddress((void**)&x0, g_x0);
    cudaGetSymbolAddress((void**)&h,  g_h);
    cudaGetSymbolAddress((void**)&oa, g_oa);
    cudaGetSymbolAddress((void**)&ob, g_ob);

    int lingrid = NTN / 32;         // 8 warps/block x 4 rows/warp
    int gatgrid = NTN * 32 / 256;   // warp per dst node

    k_stats<<<128, 128>>>(x);                                      // 0
    k_bn<<<128, 256>>>(x, gamma, beta);                            // 1
    k_deg_count<<<eb, 256>>>(dst, E, Etot);                        // 2
    k_lin<NFEAT, 3, 16><<<lingrid, 256>>>(x0, W1, as1, ad1, h);    // 3 <- ncu sample
    k_scan_block<<<256, 256>>>();                                  // 4
    k_scan_top<<<1, 256>>>();                                      // 5
    k_scan_add<<<256, 256>>>(Etot);                                // 6
    k_scatter<<<eb, 256>>>(src, dst, E, Etot);                     // 7
    k_gat<3, 16><<<gatgrid, 256>>>(h, b1, oa);                     // 8

    k_lin<48, 3, 16><<<lingrid, 256>>>(oa, W2, as2, ad2, h);
    k_gat<3, 16><<<gatgrid, 256>>>(h, b2, ob);
    k_topk<<<NBATCH, 1024>>>(ob, p1, 48, NPERG / 2);
    k_lin<48, 2, 16><<<lingrid, 256>>>(ob, W3, as3, ad3, h);
    k_gat<2, 16><<<gatgrid, 256>>>(h, b3, oa);
    k_lin<32, 1, 10><<<lingrid, 256>>>(oa, W4, as4, ad4, h);
    k_gat<1, 10><<<gatgrid, 256>>>(h, b4, ob);
    k_topk<<<NBATCH, 1024>>>(ob, p2, 10, NPERG / 4);
    k_final<<<NBATCH, 256>>>(ob, (float*)d_out);
}

// round 10
// speedup vs baseline: 2.1548x; 1.0319x over previous
#include <cuda_runtime.h>
#include <math.h>

#define NTN   65536
#define NBATCH 32
#define NPERG 2048
#define NFEAT 128
#define NCLS  10
#define NEGV  (-1e9f)
#define MASKV (-1e30f)
#define ETOTMAX (NTN * 16 + NTN)   // 1,114,112 edges incl self loops

// ---------------- scratch (device globals; no allocation allowed) ----------
__device__ float  g_h [NTN * 48];      // per-conv linear output (max HC=48)
__device__ float  g_oa[NTN * 48];      // ping buffer
__device__ float  g_ob[NTN * 48];      // pong buffer
__device__ float4 g_alsv[NTN];         // src logits, heads in .x/.y/.z (MASKV = masked)
__device__ float  g_ald[NTN * 3];      // dst logits
__device__ float  g_score[NTN];        // topk raw scores
__device__ int    g_nmask[NTN];        // node mask
__device__ float  g_psum [128 * NFEAT];  // BN partial sums
__device__ float  g_psq  [128 * NFEAT];
// CSR (built once per launch)
__device__ int g_deg [NTN];
__device__ int g_off [NTN + 1];
__device__ int g_cur [NTN];
__device__ int g_bsum[256];
__device__ int g_bsex[256];
__device__ int g_csrc[ETOTMAX];

__device__ __forceinline__ float lrelu(float v) { return v > 0.f ? v : 0.2f * v; }

// ---------------- BN partial stats + zero degrees + mask init ----------------
__global__ void k_stats(const float* __restrict__ x) {
    int f = threadIdx.x;                       // 128 threads
    int b = blockIdx.x;                        // 128 blocks
    int r0 = b * (NTN / 128);
    float s = 0.f, s2 = 0.f;
    for (int r = r0; r < r0 + NTN / 128; ++r) {
        float v = x[r * NFEAT + f];
        s += v; s2 += v * v;
    }
    g_psum[b * NFEAT + f] = s;
    g_psq [b * NFEAT + f] = s2;
    int gid = b * 128 + f;
    for (int i = gid; i < NTN; i += 128 * 128) { g_deg[i] = 0; g_nmask[i] = 1; }
}

// ---------------- degree count ----------------
__global__ void k_deg_count(const int* __restrict__ dst, int E, int Etot) {
    int e = blockIdx.x * blockDim.x + threadIdx.x;
    if (e >= Etot) return;
    int d = (e < E) ? dst[e] : (e - E);
    atomicAdd(&g_deg[d], 1);
}

// ---------------- hierarchical scan of degrees ----------------
__global__ void k_scan_block() {            // 256 blocks x 256 threads
    __shared__ int sh[256];
    int n = blockIdx.x * 256 + threadIdx.x;
    int v = g_deg[n];
    sh[threadIdx.x] = v;
    __syncthreads();
    for (int o = 1; o < 256; o <<= 1) {
        int t = (threadIdx.x >= o) ? sh[threadIdx.x - o] : 0;
        __syncthreads();
        sh[threadIdx.x] += t;
        __syncthreads();
    }
    g_off[n] = sh[threadIdx.x] - v;
    if (threadIdx.x == 255) g_bsum[blockIdx.x] = sh[255];
}

__global__ void k_scan_top() {              // 1 block x 256 threads
    __shared__ int sh[256];
    int v = g_bsum[threadIdx.x];
    sh[threadIdx.x] = v;
    __syncthreads();
    for (int o = 1; o < 256; o <<= 1) {
        int t = (threadIdx.x >= o) ? sh[threadIdx.x - o] : 0;
        __syncthreads();
        sh[threadIdx.x] += t;
        __syncthreads();
    }
    g_bsex[threadIdx.x] = sh[threadIdx.x] - v;
}

__global__ void k_scan_add(int Etot) {      // 256 blocks x 256 threads
    int n = blockIdx.x * 256 + threadIdx.x;
    int o = g_off[n] + g_bsex[blockIdx.x];
    g_off[n] = o;
    g_cur[n] = o;
    if (n == 0) g_off[NTN] = Etot;
}

// ---------------- scatter edges into CSR ----------------
__global__ void k_scatter(const int* __restrict__ src, const int* __restrict__ dst,
                          int E, int Etot) {
    int e = blockIdx.x * blockDim.x + threadIdx.x;
    if (e >= Etot) return;
    int s, d;
    if (e < E) { s = src[e]; d = dst[e]; } else { s = e - E; d = s; }
    int pos = atomicAdd(&g_cur[d], 1);
    g_csrc[pos] = s;
}

// ---------------- fused (BN +) linear + attention logits ----------------
// warp per 8 rows (register-blocked); lane owns channel pair (2l, 2l+1);
// W staged in smem in K-chunks; each W float2 loaded ONCE per 8 rows.
// BNF: apply full batch-norm affine (gamma*rstd, beta-mu*gamma*rstd)
// while staging x into smem (conv1 only) — exact same math as separate k_bn.
template <int Fin, int H, int C, bool BNF>
__global__ __launch_bounds__(256) void k_lin(const float* __restrict__ xin,
                                             const float* __restrict__ W,
                                             const float* __restrict__ a_s,
                                             const float* __restrict__ a_d,
                                             const float* __restrict__ gamma,
                                             const float* __restrict__ beta,
                                             float* __restrict__ h) {
    constexpr int HC = H * C;
    constexpr int RW = 8;
    constexpr int KCH = (Fin * HC * 4 > 12 * 1024) ? Fin / 2 : Fin;  // W chunk
    __shared__ float Ws[KCH * HC];
    __shared__ float xs[8][RW * Fin];
    __shared__ float asv[HC], adv[HC];
    __shared__ float sg[BNF ? NFEAT : 1], sb[BNF ? NFEAT : 1];
    int tid = threadIdx.x, lane = tid & 31, wid = tid >> 5;
    if (tid < HC) { asv[tid] = a_s[tid]; adv[tid] = a_d[tid]; }
    if (BNF && tid < NFEAT) {
        float s = 0.f, s2 = 0.f;
        for (int b = 0; b < 128; ++b) {
            s  += g_psum[b * NFEAT + tid];
            s2 += g_psq [b * NFEAT + tid];
        }
        float mu  = s  * (1.f / NTN);
        float var = s2 * (1.f / NTN) - mu * mu;
        float rstd = rsqrtf(var + 1e-5f);
        float ga = gamma[tid];
        sg[tid] = ga * rstd;
        sb[tid] = beta[tid] - mu * ga * rstd;
    }
    __syncthreads();

    int rbase = (blockIdx.x * 8 + wid) * RW;
    int c0 = 2 * lane;
    bool act = (c0 < HC);

    // cooperative load of 8 contiguous rows (+ BN affine for conv1)
    const float4* xin4 = (const float4*)(xin + (size_t)rbase * Fin);
    float4* xs4 = (float4*)xs[wid];
    for (int t = lane; t < RW * Fin / 4; t += 32) {
        float4 v = xin4[t];
        if (BNF) {
            int f0 = (t * 4) & (Fin - 1);
            v.x = v.x * sg[f0]     + sb[f0];
            v.y = v.y * sg[f0 + 1] + sb[f0 + 1];
            v.z = v.z * sg[f0 + 2] + sb[f0 + 2];
            v.w = v.w * sg[f0 + 3] + sb[f0 + 3];
        }
        xs4[t] = v;
    }

    float ax[RW], ay[RW];
    #pragma unroll
    for (int r = 0; r < RW; ++r) { ax[r] = 0.f; ay[r] = 0.f; }

    for (int kb = 0; kb < Fin; kb += KCH) {
        __syncthreads();
        for (int i = tid; i < KCH * HC; i += 256) Ws[i] = W[kb * HC + i];
        __syncthreads();
        if (act) {
            #pragma unroll 4
            for (int i0 = 0; i0 < KCH; i0 += 4) {
                float2 w0 = *(const float2*)&Ws[(i0 + 0) * HC + c0];
                float2 w1 = *(const float2*)&Ws[(i0 + 1) * HC + c0];
                float2 w2 = *(const float2*)&Ws[(i0 + 2) * HC + c0];
                float2 w3 = *(const float2*)&Ws[(i0 + 3) * HC + c0];
                #pragma unroll
                for (int r = 0; r < RW; ++r) {
                    float4 xv = *(const float4*)&xs[wid][r * Fin + kb + i0];
                    ax[r] += xv.x * w0.x; ay[r] += xv.x * w0.y;
                    ax[r] += xv.y * w1.x; ay[r] += xv.y * w1.y;
                    ax[r] += xv.z * w2.x; ay[r] += xv.z * w2.y;
                    ax[r] += xv.w * w3.x; ay[r] += xv.w * w3.y;
                }
            }
        }
    }
    if (act) {
        #pragma unroll
        for (int r = 0; r < RW; ++r)
            *(float2*)(h + (size_t)(rbase + r) * HC + c0) = make_float2(ax[r], ay[r]);
    }

    // attention logits per row
    #pragma unroll
    for (int r = 0; r < RW; ++r) {
        float ps = 0.f, pd = 0.f;
        if (act) {
            ps = ax[r] * asv[c0] + ay[r] * asv[c0 + 1];
            pd = ax[r] * adv[c0] + ay[r] * adv[c0 + 1];
        }
        if (C == 16) {   // 8-lane head groups
            #pragma unroll
            for (int o = 4; o; o >>= 1) {
                ps += __shfl_xor_sync(0xffffffffu, ps, o);
                pd += __shfl_xor_sync(0xffffffffu, pd, o);
            }
        } else {         // H == 1: full warp
            #pragma unroll
            for (int o = 16; o; o >>= 1) {
                ps += __shfl_xor_sync(0xffffffffu, ps, o);
                pd += __shfl_xor_sync(0xffffffffu, pd, o);
            }
        }
        float p1 = __shfl_sync(0xffffffffu, ps, 8);
        float p2 = __shfl_sync(0xffffffffu, ps, 16);
        float d1 = __shfl_sync(0xffffffffu, pd, 8);
        float d2 = __shfl_sync(0xffffffffu, pd, 16);
        if (lane == 0) {
            int rr = rbase + r;
            int msk = g_nmask[rr];
            if (H == 3) {
                g_alsv[rr] = msk ? make_float4(ps, p1, p2, 0.f)
                                 : make_float4(MASKV, MASKV, MASKV, 0.f);
                g_ald[rr * 3]     = pd;
                g_ald[rr * 3 + 1] = d1;
                g_ald[rr * 3 + 2] = d2;
            } else if (H == 2) {
                g_alsv[rr] = msk ? make_float4(ps, p1, 0.f, 0.f)
                                 : make_float4(MASKV, MASKV, 0.f, 0.f);
                g_ald[rr * 3]     = pd;
                g_ald[rr * 3 + 1] = d1;
            } else {
                g_alsv[rr] = msk ? make_float4(ps, 0.f, 0.f, 0.f)
                                 : make_float4(MASKV, 0.f, 0.f, 0.f);
                g_ald[rr * 3] = pd;
            }
        }
    }
}

// ---------------- fused attention softmax + aggregation ----------------
// warp per dst node; per-edge state lives in SHARED memory (no global cache).
template <int H, int C>
__global__ __launch_bounds__(256) void k_gat(const float* __restrict__ h,
                                             const float* __restrict__ b,
                                             float* __restrict__ out) {
    constexpr int HC = H * C;
    constexpr int CAP = 64;                  // per-warp edge cache capacity
    __shared__ float sAl[8][CAP * H + 1];
    __shared__ int   sSr[8][CAP + 1];
    int d = (blockIdx.x * blockDim.x + threadIdx.x) >> 5;
    if (d >= NTN) return;
    int lane = threadIdx.x & 31;
    int wid = (threadIdx.x >> 5) & 7;
    int c0 = 2 * lane;
    bool act = (c0 < HC);

    if (!g_nmask[d]) {
        if (act) *(float2*)(out + (size_t)d * HC + c0) = make_float2(b[c0], b[c0 + 1]);
        return;
    }

    int beg = g_off[d], end = g_off[d + 1];
    float ald_d[H], m[H], den[H];
    #pragma unroll
    for (int hh = 0; hh < H; ++hh) {
        ald_d[hh] = g_ald[d * 3 + hh];
        m[hh] = NEGV; den[hh] = 0.f;
    }

    for (int i = beg + lane; i < end; i += 32) {
        int j = i - beg;
        int s = g_csrc[i];
        float4 av = g_alsv[s];               // single 128-bit gather, all heads
        float avh[3] = {av.x, av.y, av.z};
        if (j < CAP) sSr[wid][j] = s;
        #pragma unroll
        for (int hh = 0; hh < H; ++hh) {
            float v = lrelu(avh[hh] + ald_d[hh]);   // masked: ~-2e29 -> exp 0
            if (j < CAP) sAl[wid][j * H + hh] = v;
            if (v <= m[hh]) {
                den[hh] += __expf(v - m[hh]);
            } else {
                den[hh] = den[hh] * __expf(m[hh] - v) + 1.f;
                m[hh] = v;
            }
        }
    }
    #pragma unroll
    for (int o = 16; o; o >>= 1) {
        #pragma unroll
        for (int hh = 0; hh < H; ++hh) {
            float mo = __shfl_xor_sync(0xffffffffu, m[hh], o);
            float eo = __shfl_xor_sync(0xffffffffu, den[hh], o);
            float nm = fmaxf(m[hh], mo);
            den[hh] = den[hh] * __expf(m[hh] - nm) + eo * __expf(mo - nm);
            m[hh] = nm;
        }
    }
    float inv[H];
    #pragma unroll
    for (int hh = 0; hh < H; ++hh) inv[hh] = 1.f / fmaxf(den[hh], 1e-16f);

    int deg = end - beg;
    int cap = deg < CAP ? deg : CAP;

    for (int j = lane; j < cap; j += 32) {
        #pragma unroll
        for (int hh = 0; hh < H; ++hh) {
            float v = sAl[wid][j * H + hh];
            sAl[wid][j * H + hh] = __expf(v - m[hh]) * inv[hh];
        }
    }
    __syncwarp();

    int hh0 = c0 / C;
    float m_my = m[0], inv_my = inv[0];
    #pragma unroll
    for (int hh = 1; hh < H; ++hh)
        if (hh == hh0) { m_my = m[hh]; inv_my = inv[hh]; }
    float ald_my = ald_d[0];
    #pragma unroll
    for (int hh = 1; hh < H; ++hh)
        if (hh == hh0) ald_my = ald_d[hh];

    float accx = 0.f, accy = 0.f;
    #pragma unroll 4
    for (int j = 0; j < cap; ++j) {
        float a = act ? sAl[wid][j * H + hh0] : 0.f;
        int s = sSr[wid][j];
        if (a > 0.f) {
            float2 hv = *(const float2*)(h + (size_t)s * HC + c0);
            accx += a * hv.x;
            accy += a * hv.y;
        }
    }
    for (int i = beg + CAP; i < end; ++i) {   // overflow tail (rare)
        int s = g_csrc[i];
        float4 av = g_alsv[s];
        float avh[3] = {av.x, av.y, av.z};
        float v = lrelu(avh[hh0] + ald_my);
        float a = __expf(v - m_my) * inv_my;
        if (a > 0.f && act) {
            float2 hv = *(const float2*)(h + (size_t)s * HC + c0);
            accx += a * hv.x;
            accy += a * hv.y;
        }
    }
    if (act) *(float2*)(out + (size_t)d * HC + c0) = make_float2(accx + b[c0], accy + b[c0 + 1]);
}

// ---------------- TopK pooling ----------------
__global__ void k_topk(float* __restrict__ x, const float* __restrict__ p,
                       int F, int kkeep) {
    __shared__ float ss[NPERG];
    __shared__ int   wsum[32];
    __shared__ int   wsex[32];
    __shared__ float s_thr;
    __shared__ int   s_need;
    int g = blockIdx.x;
    int base = g * NPERG;
    int tid = threadIdx.x;
    int lane = tid & 31, wid = tid >> 5;

    float nrm = 0.f;
    for (int i = 0; i < F; ++i) { float pv = p[i]; nrm += pv * pv; }
    nrm = rsqrtf(nrm);

    for (int n = tid; n < NPERG; n += blockDim.x) {
        int node = base + n;
        const float* xr = x + node * F;
        float sc = 0.f;
        for (int i = 0; i < F; ++i) sc += xr[i] * p[i];
        sc *= nrm;
        g_score[node] = sc;
        ss[n] = g_nmask[node] ? sc : NEGV;
    }
    __syncthreads();

    for (int kk = 2; kk <= NPERG; kk <<= 1) {
        for (int j = kk >> 1; j > 0; j >>= 1) {
            for (int i = tid; i < NPERG; i += blockDim.x) {
                int ixj = i ^ j;
                if (ixj > i) {
                    float a = ss[i], bb = ss[ixj];
                    bool up = ((i & kk) == 0);
                    if ((a > bb) == up) { ss[i] = bb; ss[ixj] = a; }
                }
            }
            __syncthreads();
        }
    }

    if (tid == 0) {
        float thr = ss[NPERG - kkeep];
        int lo = NPERG - kkeep, hi = NPERG;
        while (lo < hi) {
            int mid = (lo + hi) >> 1;
            if (ss[mid] > thr) hi = mid; else lo = mid + 1;
        }
        s_thr = thr;
        s_need = kkeep - (NPERG - lo);
    }
    __syncthreads();
    float thr = s_thr;
    int need_eq = s_need;

    int n0 = tid * 2, n1 = n0 + 1;
    float sc0 = g_nmask[base + n0] ? g_score[base + n0] : NEGV;
    float sc1 = g_nmask[base + n1] ? g_score[base + n1] : NEGV;
    int f0 = (sc0 == thr) ? 1 : 0;
    int f1 = (sc1 == thr) ? 1 : 0;
    int lsum = f0 + f1;
    int incl = lsum;
    #pragma unroll
    for (int o = 1; o < 32; o <<= 1) {
        int t = __shfl_up_sync(0xffffffffu, incl, o);
        if (lane >= o) incl += t;
    }
    if (lane == 31) wsum[wid] = incl;
    __syncthreads();
    if (wid == 0) {
        int v = wsum[lane];
        int inc2 = v;
        #pragma unroll
        for (int o = 1; o < 32; o <<= 1) {
            int t = __shfl_up_sync(0xffffffffu, inc2, o);
            if (lane >= o) inc2 += t;
        }
        wsex[lane] = inc2 - v;
    }
    __syncthreads();
    int rank0 = wsex[wid] + (incl - lsum);
    int rank1 = rank0 + f0;

    int keep0 = (sc0 > thr) || (f0 && rank0 < need_eq);
    int keep1 = (sc1 > thr) || (f1 && rank1 < need_eq);

    g_nmask[base + n0] = keep0;
    g_nmask[base + n1] = keep1;
    float t0 = keep0 ? tanhf(g_score[base + n0]) : 0.f;
    float t1 = keep1 ? tanhf(g_score[base + n1]) : 0.f;
    float* xr0 = x + (base + n0) * F;
    float* xr1 = x + (base + n1) * F;
    for (int i = 0; i < F; ++i) xr0[i] *= t0;
    for (int i = 0; i < F; ++i) xr1[i] *= t1;
}

// ---------------- final mean + log_softmax ----------------
__global__ void k_final(const float* __restrict__ x, float* __restrict__ out) {
    __shared__ float red[NCLS][9];
    int g = blockIdx.x;
    int base = g * NPERG;
    float acc[NCLS];
    for (int c = 0; c < NCLS; ++c) acc[c] = 0.f;
    for (int n = threadIdx.x; n < NPERG; n += blockDim.x) {
        const float* xr = x + (base + n) * NCLS;
        for (int c = 0; c < NCLS; ++c) acc[c] += xr[c];
    }
    for (int off = 16; off; off >>= 1)
        for (int c = 0; c < NCLS; ++c)
            acc[c] += __shfl_down_sync(0xffffffffu, acc[c], off);
    int lane = threadIdx.x & 31, wid = threadIdx.x >> 5;
    if (lane == 0)
        for (int c = 0; c < NCLS; ++c) red[c][wid] = acc[c];
    __syncthreads();
    if (threadIdx.x == 0) {
        int nw = blockDim.x / 32;
        float z[NCLS];
        for (int c = 0; c < NCLS; ++c) {
            float s = 0.f;
            for (int w = 0; w < nw; ++w) s += red[c][w];
            z[c] = s * (1.f / (NPERG / 4));
        }
        float mx = z[0];
        for (int c = 1; c < NCLS; ++c) mx = fmaxf(mx, z[c]);
        float se = 0.f;
        for (int c = 0; c < NCLS; ++c) se += expf(z[c] - mx);
        float lse = logf(se) + mx;
        for (int c = 0; c < NCLS; ++c) out[g * NCLS + c] = z[c] - lse;
    }
}

// ---------------- host orchestration ----------------
extern "C" void kernel_launch(void* const* d_in, const int* in_sizes, int n_in,
                              void* d_out, int out_size) {
    const float* x     = (const float*)d_in[0];
    const int*   ei    = (const int*)  d_in[1];
    const float* gamma = (const float*)d_in[3];
    const float* beta  = (const float*)d_in[4];
    const float* W1  = (const float*)d_in[5];
    const float* as1 = (const float*)d_in[6];
    const float* ad1 = (const float*)d_in[7];
    const float* b1  = (const float*)d_in[8];
    const float* W2  = (const float*)d_in[9];
    const float* as2 = (const float*)d_in[10];
    const float* ad2 = (const float*)d_in[11];
    const float* b2  = (const float*)d_in[12];
    const float* W3  = (const float*)d_in[13];
    const float* as3 = (const float*)d_in[14];
    const float* ad3 = (const float*)d_in[15];
    const float* b3  = (const float*)d_in[16];
    const float* W4  = (const float*)d_in[17];
    const float* as4 = (const float*)d_in[18];
    const float* ad4 = (const float*)d_in[19];
    const float* b4  = (const float*)d_in[20];
    const float* p1  = (const float*)d_in[21];
    const float* p2  = (const float*)d_in[22];

    int E = in_sizes[1] / 2;
    const int* src = ei;
    const int* dst = ei + E;
    int Etot = E + NTN;
    int eb = (Etot + 255) / 256;

    float *h, *oa, *ob;
    cudaGetSymbolAddress((void**)&h,  g_h);
    cudaGetSymbolAddress((void**)&oa, g_oa);
    cudaGetSymbolAddress((void**)&ob, g_ob);

    int lingrid = NTN / 64;         // 8 warps/block x 8 rows/warp
    int gatgrid = NTN * 32 / 256;   // warp per dst node

    k_stats<<<128, 128>>>(x);                                      // 0
    k_deg_count<<<eb, 256>>>(dst, E, Etot);                        // 1
    k_scan_block<<<256, 256>>>();                                  // 2
    k_lin<NFEAT, 3, 16, true><<<lingrid, 256>>>(x, W1, as1, ad1, gamma, beta, h); // 3 <- ncu
    k_scan_top<<<1, 256>>>();                                      // 4
    k_scan_add<<<256, 256>>>(Etot);                                // 5
    k_scatter<<<eb, 256>>>(src, dst, E, Etot);                     // 6
    k_gat<3, 16><<<gatgrid, 256>>>(h, b1, oa);                     // 7

    k_lin<48, 3, 16, false><<<lingrid, 256>>>(oa, W2, as2, ad2, gamma, beta, h);
    k_gat<3, 16><<<gatgrid, 256>>>(h, b2, ob);
    k_topk<<<NBATCH, 1024>>>(ob, p1, 48, NPERG / 2);
    k_lin<48, 2, 16, false><<<lingrid, 256>>>(ob, W3, as3, ad3, gamma, beta, h);
    k_gat<2, 16><<<gatgrid, 256>>>(h, b3, oa);
    k_lin<32, 1, 10, false><<<lingrid, 256>>>(oa, W4, as4, ad4, gamma, beta, h);
    k_gat<1, 10><<<gatgrid, 256>>>(h, b4, ob);
    k_topk<<<NBATCH, 1024>>>(ob, p2, 10, NPERG / 4);
    k_final<<<NBATCH, 256>>>(ob, (float*)d_out);
}

// round 11
// speedup vs baseline: 2.1662x; 1.0053x over previous
#include <cuda_runtime.h>
#include <math.h>

#define NTN   65536
#define NBATCH 32
#define NPERG 2048
#define NFEAT 128
#define NCLS  10
#define NEGV  (-1e9f)
#define MASKV (-1e30f)
#define ETOTMAX (NTN * 16 + NTN)   // 1,114,112 edges incl self loops

// ---------------- scratch (device globals; no allocation allowed) ----------
__device__ float  g_h [NTN * 48];      // per-conv linear output (max HC=48)
__device__ float  g_oa[NTN * 48];      // ping buffer
__device__ float  g_ob[NTN * 48];      // pong buffer
__device__ float4 g_alsv[NTN];         // src logits, heads in .x/.y/.z (MASKV = masked)
__device__ float  g_ald[NTN * 3];      // dst logits
__device__ float  g_score[NTN];        // topk raw scores
__device__ int    g_nmask[NTN];        // node mask
__device__ float  g_psum [128 * NFEAT];  // BN partial sums
__device__ float  g_psq  [128 * NFEAT];
// CSR (built once per launch)
__device__ int g_deg [NTN];
__device__ int g_off [NTN + 1];
__device__ int g_cur [NTN];
__device__ int g_bsum[256];
__device__ int g_bsex[256];
__device__ int g_csrc[ETOTMAX];

__device__ __forceinline__ float lrelu(float v) { return v > 0.f ? v : 0.2f * v; }

// ---------------- BN partial stats + zero degrees + mask init ----------------
__global__ void k_stats(const float* __restrict__ x) {
    int f = threadIdx.x;                       // 128 threads
    int b = blockIdx.x;                        // 128 blocks
    int r0 = b * (NTN / 128);
    float s = 0.f, s2 = 0.f;
    for (int r = r0; r < r0 + NTN / 128; ++r) {
        float v = x[r * NFEAT + f];
        s += v; s2 += v * v;
    }
    g_psum[b * NFEAT + f] = s;
    g_psq [b * NFEAT + f] = s2;
    int gid = b * 128 + f;
    for (int i = gid; i < NTN; i += 128 * 128) { g_deg[i] = 0; g_nmask[i] = 1; }
}

// ---------------- degree count ----------------
__global__ void k_deg_count(const int* __restrict__ dst, int E, int Etot) {
    int e = blockIdx.x * blockDim.x + threadIdx.x;
    if (e >= Etot) return;
    int d = (e < E) ? dst[e] : (e - E);
    atomicAdd(&g_deg[d], 1);
}

// ---------------- hierarchical scan of degrees ----------------
__global__ void k_scan_block() {            // 256 blocks x 256 threads
    __shared__ int sh[256];
    int n = blockIdx.x * 256 + threadIdx.x;
    int v = g_deg[n];
    sh[threadIdx.x] = v;
    __syncthreads();
    for (int o = 1; o < 256; o <<= 1) {
        int t = (threadIdx.x >= o) ? sh[threadIdx.x - o] : 0;
        __syncthreads();
        sh[threadIdx.x] += t;
        __syncthreads();
    }
    g_off[n] = sh[threadIdx.x] - v;
    if (threadIdx.x == 255) g_bsum[blockIdx.x] = sh[255];
}

__global__ void k_scan_top() {              // 1 block x 256 threads
    __shared__ int sh[256];
    int v = g_bsum[threadIdx.x];
    sh[threadIdx.x] = v;
    __syncthreads();
    for (int o = 1; o < 256; o <<= 1) {
        int t = (threadIdx.x >= o) ? sh[threadIdx.x - o] : 0;
        __syncthreads();
        sh[threadIdx.x] += t;
        __syncthreads();
    }
    g_bsex[threadIdx.x] = sh[threadIdx.x] - v;
}

__global__ void k_scan_add(int Etot) {      // 256 blocks x 256 threads
    int n = blockIdx.x * 256 + threadIdx.x;
    int o = g_off[n] + g_bsex[blockIdx.x];
    g_off[n] = o;
    g_cur[n] = o;
    if (n == 0) g_off[NTN] = Etot;
}

// ---------------- scatter edges into CSR ----------------
__global__ void k_scatter(const int* __restrict__ src, const int* __restrict__ dst,
                          int E, int Etot) {
    int e = blockIdx.x * blockDim.x + threadIdx.x;
    if (e >= Etot) return;
    int s, d;
    if (e < E) { s = src[e]; d = dst[e]; } else { s = e - E; d = s; }
    int pos = atomicAdd(&g_cur[d], 1);
    g_csrc[pos] = s;
}

// ---------------- fused (BN +) linear + attention logits ----------------
// warp per RW rows (register-blocked); lane owns channel pair (2l, 2l+1);
// W fully staged in smem; each W float2 loaded ONCE per RW rows.
// BNF: apply batch-norm affine while staging x (conv1 only).
template <int Fin, int H, int C, int RW, bool BNF>
__global__ __launch_bounds__(256) void k_lin(const float* __restrict__ xin,
                                             const float* __restrict__ W,
                                             const float* __restrict__ a_s,
                                             const float* __restrict__ a_d,
                                             const float* __restrict__ gamma,
                                             const float* __restrict__ beta,
                                             float* __restrict__ h) {
    constexpr int HC = H * C;
    __shared__ float Ws[Fin * HC];
    __shared__ float xs[8][RW * Fin];
    __shared__ float asv[HC], adv[HC];
    __shared__ float sg[BNF ? NFEAT : 1], sb[BNF ? NFEAT : 1];
    int tid = threadIdx.x, lane = tid & 31, wid = tid >> 5;
    for (int i = tid; i < Fin * HC; i += 256) Ws[i] = W[i];
    if (tid < HC) { asv[tid] = a_s[tid]; adv[tid] = a_d[tid]; }
    if (BNF && tid < NFEAT) {
        float s = 0.f, s2 = 0.f;
        for (int b = 0; b < 128; ++b) {
            s  += g_psum[b * NFEAT + tid];
            s2 += g_psq [b * NFEAT + tid];
        }
        float mu  = s  * (1.f / NTN);
        float var = s2 * (1.f / NTN) - mu * mu;
        float rstd = rsqrtf(var + 1e-5f);
        float ga = gamma[tid];
        sg[tid] = ga * rstd;
        sb[tid] = beta[tid] - mu * ga * rstd;
    }
    __syncthreads();

    int rbase = (blockIdx.x * 8 + wid) * RW;
    int c0 = 2 * lane;
    bool act = (c0 < HC);

    // cooperative load of RW contiguous rows (+ BN affine for conv1)
    const float4* xin4 = (const float4*)(xin + (size_t)rbase * Fin);
    float4* xs4 = (float4*)xs[wid];
    for (int t = lane; t < RW * Fin / 4; t += 32) {
        float4 v = xin4[t];
        if (BNF) {
            int f0 = (t * 4) & (Fin - 1);
            v.x = v.x * sg[f0]     + sb[f0];
            v.y = v.y * sg[f0 + 1] + sb[f0 + 1];
            v.z = v.z * sg[f0 + 2] + sb[f0 + 2];
            v.w = v.w * sg[f0 + 3] + sb[f0 + 3];
        }
        xs4[t] = v;
    }
    __syncwarp();

    float ax[RW], ay[RW];
    #pragma unroll
    for (int r = 0; r < RW; ++r) { ax[r] = 0.f; ay[r] = 0.f; }

    if (act) {
        #pragma unroll 4
        for (int i0 = 0; i0 < Fin; i0 += 4) {
            float2 w0 = *(const float2*)&Ws[(i0 + 0) * HC + c0];
            float2 w1 = *(const float2*)&Ws[(i0 + 1) * HC + c0];
            float2 w2 = *(const float2*)&Ws[(i0 + 2) * HC + c0];
            float2 w3 = *(const float2*)&Ws[(i0 + 3) * HC + c0];
            #pragma unroll
            for (int r = 0; r < RW; ++r) {
                float4 xv = *(const float4*)&xs[wid][r * Fin + i0];
                ax[r] += xv.x * w0.x; ay[r] += xv.x * w0.y;
                ax[r] += xv.y * w1.x; ay[r] += xv.y * w1.y;
                ax[r] += xv.z * w2.x; ay[r] += xv.z * w2.y;
                ax[r] += xv.w * w3.x; ay[r] += xv.w * w3.y;
            }
        }
        #pragma unroll
        for (int r = 0; r < RW; ++r)
            *(float2*)(h + (size_t)(rbase + r) * HC + c0) = make_float2(ax[r], ay[r]);
    }

    // attention logits per row
    #pragma unroll
    for (int r = 0; r < RW; ++r) {
        float ps = 0.f, pd = 0.f;
        if (act) {
            ps = ax[r] * asv[c0] + ay[r] * asv[c0 + 1];
            pd = ax[r] * adv[c0] + ay[r] * adv[c0 + 1];
        }
        if (C == 16) {   // 8-lane head groups
            #pragma unroll
            for (int o = 4; o; o >>= 1) {
                ps += __shfl_xor_sync(0xffffffffu, ps, o);
                pd += __shfl_xor_sync(0xffffffffu, pd, o);
            }
        } else {         // H == 1: full warp
            #pragma unroll
            for (int o = 16; o; o >>= 1) {
                ps += __shfl_xor_sync(0xffffffffu, ps, o);
                pd += __shfl_xor_sync(0xffffffffu, pd, o);
            }
        }
        float p1 = __shfl_sync(0xffffffffu, ps, 8);
        float p2 = __shfl_sync(0xffffffffu, ps, 16);
        float d1 = __shfl_sync(0xffffffffu, pd, 8);
        float d2 = __shfl_sync(0xffffffffu, pd, 16);
        if (lane == 0) {
            int rr = rbase + r;
            int msk = g_nmask[rr];
            if (H == 3) {
                g_alsv[rr] = msk ? make_float4(ps, p1, p2, 0.f)
                                 : make_float4(MASKV, MASKV, MASKV, 0.f);
                g_ald[rr * 3]     = pd;
                g_ald[rr * 3 + 1] = d1;
                g_ald[rr * 3 + 2] = d2;
            } else if (H == 2) {
                g_alsv[rr] = msk ? make_float4(ps, p1, 0.f, 0.f)
                                 : make_float4(MASKV, MASKV, 0.f, 0.f);
                g_ald[rr * 3]     = pd;
                g_ald[rr * 3 + 1] = d1;
            } else {
                g_alsv[rr] = msk ? make_float4(ps, 0.f, 0.f, 0.f)
                                 : make_float4(MASKV, 0.f, 0.f, 0.f);
                g_ald[rr * 3] = pd;
            }
        }
    }
}

// ---------------- fused attention softmax + aggregation ----------------
// warp per dst node; per-edge state in smem; warp-compacted alpha list so
// phase B is a dense branch-free alpha*h[src] loop with batched gathers.
template <int H, int C>
__global__ __launch_bounds__(256) void k_gat(const float* __restrict__ h,
                                             const float* __restrict__ b,
                                             float* __restrict__ out) {
    constexpr int HC = H * C;
    constexpr int CAP = 64;                  // per-warp edge cache capacity
    __shared__ float sAl[8][CAP * H + 1];    // raw logits
    __shared__ int   sSr[8][CAP + 1];
    __shared__ float sAc[8][CAP * H + 1];    // compacted alphas
    __shared__ int   sSc[8][CAP + 1];
    int d = (blockIdx.x * blockDim.x + threadIdx.x) >> 5;
    if (d >= NTN) return;
    int lane = threadIdx.x & 31;
    int wid = (threadIdx.x >> 5) & 7;
    int c0 = 2 * lane;
    bool act = (c0 < HC);

    if (!g_nmask[d]) {
        if (act) *(float2*)(out + (size_t)d * HC + c0) = make_float2(b[c0], b[c0 + 1]);
        return;
    }

    int beg = g_off[d], end = g_off[d + 1];
    float ald_d[H], m[H], den[H];
    #pragma unroll
    for (int hh = 0; hh < H; ++hh) {
        ald_d[hh] = g_ald[d * 3 + hh];
        m[hh] = NEGV; den[hh] = 0.f;
    }

    // phase A: gather logits, cache to smem, online softmax (lanes stride edges)
    for (int i = beg + lane; i < end; i += 32) {
        int j = i - beg;
        int s = g_csrc[i];
        float4 av = g_alsv[s];               // single 128-bit gather, all heads
        float avh[3] = {av.x, av.y, av.z};
        if (j < CAP) sSr[wid][j] = s;
        #pragma unroll
        for (int hh = 0; hh < H; ++hh) {
            float v = lrelu(avh[hh] + ald_d[hh]);   // masked: ~-2e29 -> exp 0
            if (j < CAP) sAl[wid][j * H + hh] = v;
            if (v <= m[hh]) {
                den[hh] += __expf(v - m[hh]);
            } else {
                den[hh] = den[hh] * __expf(m[hh] - v) + 1.f;
                m[hh] = v;
            }
        }
    }
    #pragma unroll
    for (int o = 16; o; o >>= 1) {
        #pragma unroll
        for (int hh = 0; hh < H; ++hh) {
            float mo = __shfl_xor_sync(0xffffffffu, m[hh], o);
            float eo = __shfl_xor_sync(0xffffffffu, den[hh], o);
            float nm = fmaxf(m[hh], mo);
            den[hh] = den[hh] * __expf(m[hh] - nm) + eo * __expf(mo - nm);
            m[hh] = nm;
        }
    }
    float inv[H];
    #pragma unroll
    for (int hh = 0; hh < H; ++hh) inv[hh] = 1.f / fmaxf(den[hh], 1e-16f);

    int deg = end - beg;
    int cap = deg < CAP ? deg : CAP;

    // convert logits to alpha + warp-compact surviving edges (ballot+popc)
    int nk = 0;
    for (int j0 = 0; j0 < cap; j0 += 32) {
        int j = j0 + lane;
        bool have = (j < cap);
        float aH[H]; int s = 0;
        bool keep = false;
        if (have) {
            s = sSr[wid][j];
            #pragma unroll
            for (int hh = 0; hh < H; ++hh)
                aH[hh] = __expf(sAl[wid][j * H + hh] - m[hh]) * inv[hh];
            #pragma unroll
            for (int hh = 0; hh < H; ++hh) keep = keep || (aH[hh] > 0.f);
        }
        unsigned bal = __ballot_sync(0xffffffffu, keep);
        int pos = nk + __popc(bal & ((1u << lane) - 1u));
        if (keep) {
            sSc[wid][pos] = s;
            #pragma unroll
            for (int hh = 0; hh < H; ++hh) sAc[wid][pos * H + hh] = aH[hh];
        }
        nk += __popc(bal);
    }
    __syncwarp();

    int hh0 = c0 / C;
    float m_my = m[0], inv_my = inv[0];
    #pragma unroll
    for (int hh = 1; hh < H; ++hh)
        if (hh == hh0) { m_my = m[hh]; inv_my = inv[hh]; }
    float ald_my = ald_d[0];
    #pragma unroll
    for (int hh = 1; hh < H; ++hh)
        if (hh == hh0) ald_my = ald_d[hh];

    // phase B: dense branch-free accumulation over compacted edges
    float accx = 0.f, accy = 0.f;
    if (act) {
        #pragma unroll 4
        for (int j = 0; j < nk; ++j) {
            float a = sAc[wid][j * H + hh0];
            int s = sSc[wid][j];
            float2 hv = *(const float2*)(h + (size_t)s * HC + c0);
            accx += a * hv.x;
            accy += a * hv.y;
        }
    }
    // tail for deg > CAP (vanishingly rare): recompute alpha from alsv
    for (int i = beg + CAP; i < end; ++i) {
        int s = g_csrc[i];
        float4 av = g_alsv[s];
        float avh[3] = {av.x, av.y, av.z};
        float v = lrelu(avh[hh0] + ald_my);
        float a = __expf(v - m_my) * inv_my;
        if (a > 0.f && act) {
            float2 hv = *(const float2*)(h + (size_t)s * HC + c0);
            accx += a * hv.x;
            accy += a * hv.y;
        }
    }
    if (act) *(float2*)(out + (size_t)d * HC + c0) = make_float2(accx + b[c0], accy + b[c0 + 1]);
}

// ---------------- TopK pooling ----------------
__global__ void k_topk(float* __restrict__ x, const float* __restrict__ p,
                       int F, int kkeep) {
    __shared__ float ss[NPERG];
    __shared__ int   wsum[32];
    __shared__ int   wsex[32];
    __shared__ float s_thr;
    __shared__ int   s_need;
    int g = blockIdx.x;
    int base = g * NPERG;
    int tid = threadIdx.x;
    int lane = tid & 31, wid = tid >> 5;

    float nrm = 0.f;
    for (int i = 0; i < F; ++i) { float pv = p[i]; nrm += pv * pv; }
    nrm = rsqrtf(nrm);

    for (int n = tid; n < NPERG; n += blockDim.x) {
        int node = base + n;
        const float* xr = x + node * F;
        float sc = 0.f;
        for (int i = 0; i < F; ++i) sc += xr[i] * p[i];
        sc *= nrm;
        g_score[node] = sc;
        ss[n] = g_nmask[node] ? sc : NEGV;
    }
    __syncthreads();

    for (int kk = 2; kk <= NPERG; kk <<= 1) {
        for (int j = kk >> 1; j > 0; j >>= 1) {
            for (int i = tid; i < NPERG; i += blockDim.x) {
                int ixj = i ^ j;
                if (ixj > i) {
                    float a = ss[i], bb = ss[ixj];
                    bool up = ((i & kk) == 0);
                    if ((a > bb) == up) { ss[i] = bb; ss[ixj] = a; }
                }
            }
            __syncthreads();
        }
    }

    if (tid == 0) {
        float thr = ss[NPERG - kkeep];
        int lo = NPERG - kkeep, hi = NPERG;
        while (lo < hi) {
            int mid = (lo + hi) >> 1;
            if (ss[mid] > thr) hi = mid; else lo = mid + 1;
        }
        s_thr = thr;
        s_need = kkeep - (NPERG - lo);
    }
    __syncthreads();
    float thr = s_thr;
    int need_eq = s_need;

    int n0 = tid * 2, n1 = n0 + 1;
    float sc0 = g_nmask[base + n0] ? g_score[base + n0] : NEGV;
    float sc1 = g_nmask[base + n1] ? g_score[base + n1] : NEGV;
    int f0 = (sc0 == thr) ? 1 : 0;
    int f1 = (sc1 == thr) ? 1 : 0;
    int lsum = f0 + f1;
    int incl = lsum;
    #pragma unroll
    for (int o = 1; o < 32; o <<= 1) {
        int t = __shfl_up_sync(0xffffffffu, incl, o);
        if (lane >= o) incl += t;
    }
    if (lane == 31) wsum[wid] = incl;
    __syncthreads();
    if (wid == 0) {
        int v = wsum[lane];
        int inc2 = v;
        #pragma unroll
        for (int o = 1; o < 32; o <<= 1) {
            int t = __shfl_up_sync(0xffffffffu, inc2, o);
            if (lane >= o) inc2 += t;
        }
        wsex[lane] = inc2 - v;
    }
    __syncthreads();
    int rank0 = wsex[wid] + (incl - lsum);
    int rank1 = rank0 + f0;

    int keep0 = (sc0 > thr) || (f0 && rank0 < need_eq);
    int keep1 = (sc1 > thr) || (f1 && rank1 < need_eq);

    g_nmask[base + n0] = keep0;
    g_nmask[base + n1] = keep1;
    float t0 = keep0 ? tanhf(g_score[base + n0]) : 0.f;
    float t1 = keep1 ? tanhf(g_score[base + n1]) : 0.f;
    float* xr0 = x + (base + n0) * F;
    float* xr1 = x + (base + n1) * F;
    for (int i = 0; i < F; ++i) xr0[i] *= t0;
    for (int i = 0; i < F; ++i) xr1[i] *= t1;
}

// ---------------- final mean + log_softmax ----------------
__global__ void k_final(const float* __restrict__ x, float* __restrict__ out) {
    __shared__ float red[NCLS][9];
    int g = blockIdx.x;
    int base = g * NPERG;
    float acc[NCLS];
    for (int c = 0; c < NCLS; ++c) acc[c] = 0.f;
    for (int n = threadIdx.x; n < NPERG; n += blockDim.x) {
        const float* xr = x + (base + n) * NCLS;
        for (int c = 0; c < NCLS; ++c) acc[c] += xr[c];
    }
    for (int off = 16; off; off >>= 1)
        for (int c = 0; c < NCLS; ++c)
            acc[c] += __shfl_down_sync(0xffffffffu, acc[c], off);
    int lane = threadIdx.x & 31, wid = threadIdx.x >> 5;
    if (lane == 0)
        for (int c = 0; c < NCLS; ++c) red[c][wid] = acc[c];
    __syncthreads();
    if (threadIdx.x == 0) {
        int nw = blockDim.x / 32;
        float z[NCLS];
        for (int c = 0; c < NCLS; ++c) {
            float s = 0.f;
            for (int w = 0; w < nw; ++w) s += red[c][w];
            z[c] = s * (1.f / (NPERG / 4));
        }
        float mx = z[0];
        for (int c = 1; c < NCLS; ++c) mx = fmaxf(mx, z[c]);
        float se = 0.f;
        for (int c = 0; c < NCLS; ++c) se += expf(z[c] - mx);
        float lse = logf(se) + mx;
        for (int c = 0; c < NCLS; ++c) out[g * NCLS + c] = z[c] - lse;
    }
}

// ---------------- host orchestration ----------------
extern "C" void kernel_launch(void* const* d_in, const int* in_sizes, int n_in,
                              void* d_out, int out_size) {
    const float* x     = (const float*)d_in[0];
    const int*   ei    = (const int*)  d_in[1];
    const float* gamma = (const float*)d_in[3];
    const float* beta  = (const float*)d_in[4];
    const float* W1  = (const float*)d_in[5];
    const float* as1 = (const float*)d_in[6];
    const float* ad1 = (const float*)d_in[7];
    const float* b1  = (const float*)d_in[8];
    const float* W2  = (const float*)d_in[9];
    const float* as2 = (const float*)d_in[10];
    const float* ad2 = (const float*)d_in[11];
    const float* b2  = (const float*)d_in[12];
    const float* W3  = (const float*)d_in[13];
    const float* as3 = (const float*)d_in[14];
    const float* ad3 = (const float*)d_in[15];
    const float* b3  = (const float*)d_in[16];
    const float* W4  = (const float*)d_in[17];
    const float* as4 = (const float*)d_in[18];
    const float* ad4 = (const float*)d_in[19];
    const float* b4  = (const float*)d_in[20];
    const float* p1  = (const float*)d_in[21];
    const float* p2  = (const float*)d_in[22];

    int E = in_sizes[1] / 2;
    const int* src = ei;
    const int* dst = ei + E;
    int Etot = E + NTN;
    int eb = (Etot + 255) / 256;

    float *h, *oa, *ob;
    cudaGetSymbolAddress((void**)&h,  g_h);
    cudaGetSymbolAddress((void**)&oa, g_oa);
    cudaGetSymbolAddress((void**)&ob, g_ob);

    int lingrid4 = NTN / 32;        // 8 warps/block x 4 rows/warp (conv1)
    int lingrid8 = NTN / 64;        // 8 warps/block x 8 rows/warp (small convs)
    int gatgrid = NTN * 32 / 256;   // warp per dst node

    k_stats<<<128, 128>>>(x);                                      // 0
    k_deg_count<<<eb, 256>>>(dst, E, Etot);                        // 1
    k_scan_block<<<256, 256>>>();                                  // 2
    k_lin<NFEAT, 3, 16, 4, true><<<lingrid4, 256>>>(x, W1, as1, ad1, gamma, beta, h); // 3 <- ncu
    k_scan_top<<<1, 256>>>();                                      // 4
    k_scan_add<<<256, 256>>>(Etot);                                // 5
    k_scatter<<<eb, 256>>>(src, dst, E, Etot);                     // 6
    k_gat<3, 16><<<gatgrid, 256>>>(h, b1, oa);                     // 7

    k_lin<48, 3, 16, 8, false><<<lingrid8, 256>>>(oa, W2, as2, ad2, gamma, beta, h);
    k_gat<3, 16><<<gatgrid, 256>>>(h, b2, ob);
    k_topk<<<NBATCH, 1024>>>(ob, p1, 48, NPERG / 2);
    k_lin<48, 2, 16, 8, false><<<lingrid8, 256>>>(ob, W3, as3, ad3, gamma, beta, h);
    k_gat<2, 16><<<gatgrid, 256>>>(h, b3, oa);
    k_lin<32, 1, 10, 8, false><<<lingrid8, 256>>>(oa, W4, as4, ad4, gamma, beta, h);
    k_gat<1, 10><<<gatgrid, 256>>>(h, b4, ob);
    k_topk<<<NBATCH, 1024>>>(ob, p2, 10, NPERG / 4);
    k_final<<<NBATCH, 256>>>(ob, (float*)d_out);
}

// round 12
// speedup vs baseline: 2.6661x; 1.2307x over previous
#include <cuda_runtime.h>
#include <math.h>

#define NTN   65536
#define NBATCH 32
#define NPERG 2048
#define NFEAT 128
#define NCLS  10
#define NEGV  (-1e9f)
#define MASKV (-1e30f)
#define ETOTMAX (NTN * 16 + NTN)   // 1,114,112 edges incl self loops

// ---------------- scratch (device globals; no allocation allowed) ----------
__device__ float  g_h [NTN * 48];      // per-conv linear output (max HC=48)
__device__ float  g_oa[NTN * 48];      // ping buffer
__device__ float  g_ob[NTN * 48];      // pong buffer
__device__ float4 g_alsv[NTN];         // src logits, heads in .x/.y/.z (MASKV = masked)
__device__ float  g_ald[NTN * 3];      // dst logits
__device__ float  g_score[NTN];        // topk raw scores
__device__ int    g_nmask[NTN];        // node mask
__device__ float  g_psum [128 * NFEAT];  // BN partial sums
__device__ float  g_psq  [128 * NFEAT];
__device__ float  g_bnc  [2 * NFEAT];    // BN affine: scale[0:128], shift[128:256]
// CSR (built once per launch)
__device__ int g_deg [NTN];
__device__ int g_off [NTN + 1];
__device__ int g_cur [NTN];
__device__ int g_bsum[256];
__device__ int g_bsex[256];
__device__ int g_csrc[ETOTMAX];

__device__ __forceinline__ float lrelu(float v) { return v > 0.f ? v : 0.2f * v; }

// ---------------- BN partial stats + zero degrees + mask init ----------------
__global__ void k_stats(const float* __restrict__ x) {
    int f = threadIdx.x;                       // 128 threads
    int b = blockIdx.x;                        // 128 blocks
    int r0 = b * (NTN / 128);
    float s = 0.f, s2 = 0.f;
    for (int r = r0; r < r0 + NTN / 128; ++r) {
        float v = x[r * NFEAT + f];
        s += v; s2 += v * v;
    }
    g_psum[b * NFEAT + f] = s;
    g_psq [b * NFEAT + f] = s2;
    int gid = b * 128 + f;
    for (int i = gid; i < NTN; i += 128 * 128) { g_deg[i] = 0; g_nmask[i] = 1; }
}

// ---------------- BN coefficient reduce (ONE block) ----------------
__global__ void k_bncoef(const float* __restrict__ gamma, const float* __restrict__ beta) {
    int f = threadIdx.x;                       // 128 threads
    float s = 0.f, s2 = 0.f;
    for (int b = 0; b < 128; ++b) {
        s  += g_psum[b * NFEAT + f];
        s2 += g_psq [b * NFEAT + f];
    }
    float mu  = s  * (1.f / NTN);
    float var = s2 * (1.f / NTN) - mu * mu;
    float rstd = rsqrtf(var + 1e-5f);
    float ga = gamma[f];
    g_bnc[f]         = ga * rstd;
    g_bnc[NFEAT + f] = beta[f] - mu * ga * rstd;
}

// ---------------- degree count ----------------
__global__ void k_deg_count(const int* __restrict__ dst, int E, int Etot) {
    int e = blockIdx.x * blockDim.x + threadIdx.x;
    if (e >= Etot) return;
    int d = (e < E) ? dst[e] : (e - E);
    atomicAdd(&g_deg[d], 1);
}

// ---------------- hierarchical scan of degrees ----------------
__global__ void k_scan_block() {            // 256 blocks x 256 threads
    __shared__ int sh[256];
    int n = blockIdx.x * 256 + threadIdx.x;
    int v = g_deg[n];
    sh[threadIdx.x] = v;
    __syncthreads();
    for (int o = 1; o < 256; o <<= 1) {
        int t = (threadIdx.x >= o) ? sh[threadIdx.x - o] : 0;
        __syncthreads();
        sh[threadIdx.x] += t;
        __syncthreads();
    }
    g_off[n] = sh[threadIdx.x] - v;
    if (threadIdx.x == 255) g_bsum[blockIdx.x] = sh[255];
}

__global__ void k_scan_top() {              // 1 block x 256 threads
    __shared__ int sh[256];
    int v = g_bsum[threadIdx.x];
    sh[threadIdx.x] = v;
    __syncthreads();
    for (int o = 1; o < 256; o <<= 1) {
        int t = (threadIdx.x >= o) ? sh[threadIdx.x - o] : 0;
        __syncthreads();
        sh[threadIdx.x] += t;
        __syncthreads();
    }
    g_bsex[threadIdx.x] = sh[threadIdx.x] - v;
}

__global__ void k_scan_add(int Etot) {      // 256 blocks x 256 threads
    int n = blockIdx.x * 256 + threadIdx.x;
    int o = g_off[n] + g_bsex[blockIdx.x];
    g_off[n] = o;
    g_cur[n] = o;
    if (n == 0) g_off[NTN] = Etot;
}

// ---------------- scatter edges into CSR ----------------
__global__ void k_scatter(const int* __restrict__ src, const int* __restrict__ dst,
                          int E, int Etot) {
    int e = blockIdx.x * blockDim.x + threadIdx.x;
    if (e >= Etot) return;
    int s, d;
    if (e < E) { s = src[e]; d = dst[e]; } else { s = e - E; d = s; }
    int pos = atomicAdd(&g_cur[d], 1);
    g_csrc[pos] = s;
}

// ---------------- fused (BN +) linear + attention logits ----------------
// warp per RW rows (register-blocked); lane owns channel pair (2l, 2l+1);
// W fully staged in smem; each W float2 loaded ONCE per RW rows.
// BNF: apply precomputed batch-norm affine while staging x (conv1 only).
template <int Fin, int H, int C, int RW, bool BNF>
__global__ __launch_bounds__(256) void k_lin(const float* __restrict__ xin,
                                             const float* __restrict__ W,
                                             const float* __restrict__ a_s,
                                             const float* __restrict__ a_d,
                                             float* __restrict__ h) {
    constexpr int HC = H * C;
    __shared__ float Ws[Fin * HC];
    __shared__ float xs[8][RW * Fin];
    __shared__ float asv[HC], adv[HC];
    __shared__ float sg[BNF ? NFEAT : 1], sb[BNF ? NFEAT : 1];
    int tid = threadIdx.x, lane = tid & 31, wid = tid >> 5;
    for (int i = tid; i < Fin * HC; i += 256) Ws[i] = W[i];
    if (tid < HC) { asv[tid] = a_s[tid]; adv[tid] = a_d[tid]; }
    if (BNF && tid < NFEAT) {
        sg[tid] = g_bnc[tid];
        sb[tid] = g_bnc[NFEAT + tid];
    }
    __syncthreads();

    int rbase = (blockIdx.x * 8 + wid) * RW;
    int c0 = 2 * lane;
    bool act = (c0 < HC);

    // cooperative load of RW contiguous rows (+ BN affine for conv1)
    const float4* xin4 = (const float4*)(xin + (size_t)rbase * Fin);
    float4* xs4 = (float4*)xs[wid];
    for (int t = lane; t < RW * Fin / 4; t += 32) {
        float4 v = xin4[t];
        if (BNF) {
            int f0 = (t * 4) & (Fin - 1);
            v.x = v.x * sg[f0]     + sb[f0];
            v.y = v.y * sg[f0 + 1] + sb[f0 + 1];
            v.z = v.z * sg[f0 + 2] + sb[f0 + 2];
            v.w = v.w * sg[f0 + 3] + sb[f0 + 3];
        }
        xs4[t] = v;
    }
    __syncwarp();

    float ax[RW], ay[RW];
    #pragma unroll
    for (int r = 0; r < RW; ++r) { ax[r] = 0.f; ay[r] = 0.f; }

    if (act) {
        #pragma unroll 4
        for (int i0 = 0; i0 < Fin; i0 += 4) {
            float2 w0 = *(const float2*)&Ws[(i0 + 0) * HC + c0];
            float2 w1 = *(const float2*)&Ws[(i0 + 1) * HC + c0];
            float2 w2 = *(const float2*)&Ws[(i0 + 2) * HC + c0];
            float2 w3 = *(const float2*)&Ws[(i0 + 3) * HC + c0];
            #pragma unroll
            for (int r = 0; r < RW; ++r) {
                float4 xv = *(const float4*)&xs[wid][r * Fin + i0];
                ax[r] += xv.x * w0.x; ay[r] += xv.x * w0.y;
                ax[r] += xv.y * w1.x; ay[r] += xv.y * w1.y;
                ax[r] += xv.z * w2.x; ay[r] += xv.z * w2.y;
                ax[r] += xv.w * w3.x; ay[r] += xv.w * w3.y;
            }
        }
        #pragma unroll
        for (int r = 0; r < RW; ++r)
            *(float2*)(h + (size_t)(rbase + r) * HC + c0) = make_float2(ax[r], ay[r]);
    }

    // attention logits per row
    #pragma unroll
    for (int r = 0; r < RW; ++r) {
        float ps = 0.f, pd = 0.f;
        if (act) {
            ps = ax[r] * asv[c0] + ay[r] * asv[c0 + 1];
            pd = ax[r] * adv[c0] + ay[r] * adv[c0 + 1];
        }
        if (C == 16) {   // 8-lane head groups
            #pragma unroll
            for (int o = 4; o; o >>= 1) {
                ps += __shfl_xor_sync(0xffffffffu, ps, o);
                pd += __shfl_xor_sync(0xffffffffu, pd, o);
            }
        } else {         // H == 1: full warp
            #pragma unroll
            for (int o = 16; o; o >>= 1) {
                ps += __shfl_xor_sync(0xffffffffu, ps, o);
                pd += __shfl_xor_sync(0xffffffffu, pd, o);
            }
        }
        float p1 = __shfl_sync(0xffffffffu, ps, 8);
        float p2 = __shfl_sync(0xffffffffu, ps, 16);
        float d1 = __shfl_sync(0xffffffffu, pd, 8);
        float d2 = __shfl_sync(0xffffffffu, pd, 16);
        if (lane == 0) {
            int rr = rbase + r;
            int msk = g_nmask[rr];
            if (H == 3) {
                g_alsv[rr] = msk ? make_float4(ps, p1, p2, 0.f)
                                 : make_float4(MASKV, MASKV, MASKV, 0.f);
                g_ald[rr * 3]     = pd;
                g_ald[rr * 3 + 1] = d1;
                g_ald[rr * 3 + 2] = d2;
            } else if (H == 2) {
                g_alsv[rr] = msk ? make_float4(ps, p1, 0.f, 0.f)
                                 : make_float4(MASKV, MASKV, 0.f, 0.f);
                g_ald[rr * 3]     = pd;
                g_ald[rr * 3 + 1] = d1;
            } else {
                g_alsv[rr] = msk ? make_float4(ps, 0.f, 0.f, 0.f)
                                 : make_float4(MASKV, 0.f, 0.f, 0.f);
                g_ald[rr * 3] = pd;
            }
        }
    }
}

// ---------------- fused attention softmax + aggregation ----------------
// warp per dst node; per-edge state in smem.
// MASKED=false (pre-pool convs): all nodes live, alpha converted in place.
// MASKED=true (post-pool convs): ballot-compacted alpha list halves phase B.
template <int H, int C, bool MASKED>
__global__ __launch_bounds__(256) void k_gat(const float* __restrict__ h,
                                             const float* __restrict__ b,
                                             float* __restrict__ out) {
    constexpr int HC = H * C;
    constexpr int CAP = 64;                  // per-warp edge cache capacity
    __shared__ float sAl[8][CAP * H + 1];    // logits -> alphas
    __shared__ int   sSr[8][CAP + 1];
    __shared__ float sAc[MASKED ? 8 : 1][MASKED ? (CAP * H + 1) : 1];
    __shared__ int   sSc[MASKED ? 8 : 1][MASKED ? (CAP + 1) : 1];
    int d = (blockIdx.x * blockDim.x + threadIdx.x) >> 5;
    if (d >= NTN) return;
    int lane = threadIdx.x & 31;
    int wid = (threadIdx.x >> 5) & 7;
    int c0 = 2 * lane;
    bool act = (c0 < HC);

    if (MASKED && !g_nmask[d]) {
        if (act) *(float2*)(out + (size_t)d * HC + c0) = make_float2(b[c0], b[c0 + 1]);
        return;
    }

    int beg = g_off[d], end = g_off[d + 1];
    float ald_d[H], m[H], den[H];
    #pragma unroll
    for (int hh = 0; hh < H; ++hh) {
        ald_d[hh] = g_ald[d * 3 + hh];
        m[hh] = NEGV; den[hh] = 0.f;
    }

    // phase A: gather logits, cache to smem, online softmax (lanes stride edges)
    for (int i = beg + lane; i < end; i += 32) {
        int j = i - beg;
        int s = g_csrc[i];
        float4 av = g_alsv[s];               // single 128-bit gather, all heads
        float avh[3] = {av.x, av.y, av.z};
        if (j < CAP) sSr[wid][j] = s;
        #pragma unroll
        for (int hh = 0; hh < H; ++hh) {
            float v = lrelu(avh[hh] + ald_d[hh]);   // masked: ~-2e29 -> exp 0
            if (j < CAP) sAl[wid][j * H + hh] = v;
            if (v <= m[hh]) {
                den[hh] += __expf(v - m[hh]);
            } else {
                den[hh] = den[hh] * __expf(m[hh] - v) + 1.f;
                m[hh] = v;
            }
        }
    }
    #pragma unroll
    for (int o = 16; o; o >>= 1) {
        #pragma unroll
        for (int hh = 0; hh < H; ++hh) {
            float mo = __shfl_xor_sync(0xffffffffu, m[hh], o);
            float eo = __shfl_xor_sync(0xffffffffu, den[hh], o);
            float nm = fmaxf(m[hh], mo);
            den[hh] = den[hh] * __expf(m[hh] - nm) + eo * __expf(mo - nm);
            m[hh] = nm;
        }
    }
    float inv[H];
    #pragma unroll
    for (int hh = 0; hh < H; ++hh) inv[hh] = 1.f / fmaxf(den[hh], 1e-16f);

    int deg = end - beg;
    int cap = deg < CAP ? deg : CAP;
    int nk;

    if (MASKED) {
        // convert + warp-compact surviving edges (ballot+popc)
        nk = 0;
        for (int j0 = 0; j0 < cap; j0 += 32) {
            int j = j0 + lane;
            bool have = (j < cap);
            float aH[H]; int s = 0;
            bool keep = false;
            if (have) {
                s = sSr[wid][j];
                #pragma unroll
                for (int hh = 0; hh < H; ++hh)
                    aH[hh] = __expf(sAl[wid][j * H + hh] - m[hh]) * inv[hh];
                #pragma unroll
                for (int hh = 0; hh < H; ++hh) keep = keep || (aH[hh] > 0.f);
            }
            unsigned bal = __ballot_sync(0xffffffffu, keep);
            int pos = nk + __popc(bal & ((1u << lane) - 1u));
            if (keep) {
                sSc[wid][pos] = s;
                #pragma unroll
                for (int hh = 0; hh < H; ++hh) sAc[wid][pos * H + hh] = aH[hh];
            }
            nk += __popc(bal);
        }
    } else {
        // all edges live: convert alpha in place
        for (int j = lane; j < cap; j += 32) {
            #pragma unroll
            for (int hh = 0; hh < H; ++hh) {
                float v = sAl[wid][j * H + hh];
                sAl[wid][j * H + hh] = __expf(v - m[hh]) * inv[hh];
            }
        }
        nk = cap;
    }
    __syncwarp();

    int hh0 = c0 / C;
    float m_my = m[0], inv_my = inv[0];
    #pragma unroll
    for (int hh = 1; hh < H; ++hh)
        if (hh == hh0) { m_my = m[hh]; inv_my = inv[hh]; }
    float ald_my = ald_d[0];
    #pragma unroll
    for (int hh = 1; hh < H; ++hh)
        if (hh == hh0) ald_my = ald_d[hh];

    // phase B: dense branch-free accumulation
    float accx = 0.f, accy = 0.f;
    if (act) {
        #pragma unroll 4
        for (int j = 0; j < nk; ++j) {
            float a = MASKED ? sAc[wid][j * H + hh0] : sAl[wid][j * H + hh0];
            int s = MASKED ? sSc[wid][j] : sSr[wid][j];
            float2 hv = *(const float2*)(h + (size_t)s * HC + c0);
            accx += a * hv.x;
            accy += a * hv.y;
        }
    }
    // tail for deg > CAP (vanishingly rare): recompute alpha from alsv
    for (int i = beg + CAP; i < end; ++i) {
        int s = g_csrc[i];
        float4 av = g_alsv[s];
        float avh[3] = {av.x, av.y, av.z};
        float v = lrelu(avh[hh0] + ald_my);
        float a = __expf(v - m_my) * inv_my;
        if (a > 0.f && act) {
            float2 hv = *(const float2*)(h + (size_t)s * HC + c0);
            accx += a * hv.x;
            accy += a * hv.y;
        }
    }
    if (act) *(float2*)(out + (size_t)d * HC + c0) = make_float2(accx + b[c0], accy + b[c0 + 1]);
}

// ---------------- TopK pooling (float2-vectorized; F must be even) --------
__global__ void k_topk(float* __restrict__ x, const float* __restrict__ p,
                       int F, int kkeep) {
    __shared__ float ss[NPERG];
    __shared__ int   wsum[32];
    __shared__ int   wsex[32];
    __shared__ float s_thr;
    __shared__ int   s_need;
    int g = blockIdx.x;
    int base = g * NPERG;
    int tid = threadIdx.x;
    int lane = tid & 31, wid = tid >> 5;
    int F2 = F >> 1;
    const float2* p2 = (const float2*)p;

    float nrm = 0.f;
    for (int i = 0; i < F2; ++i) { float2 pv = p2[i]; nrm += pv.x * pv.x + pv.y * pv.y; }
    nrm = rsqrtf(nrm);

    for (int n = tid; n < NPERG; n += blockDim.x) {
        int node = base + n;
        const float2* xr = (const float2*)(x + (size_t)node * F);
        float sc = 0.f;
        for (int i = 0; i < F2; ++i) {
            float2 xv = xr[i], pv = p2[i];
            sc += xv.x * pv.x + xv.y * pv.y;
        }
        sc *= nrm;
        g_score[node] = sc;
        ss[n] = g_nmask[node] ? sc : NEGV;
    }
    __syncthreads();

    for (int kk = 2; kk <= NPERG; kk <<= 1) {
        for (int j = kk >> 1; j > 0; j >>= 1) {
            for (int i = tid; i < NPERG; i += blockDim.x) {
                int ixj = i ^ j;
                if (ixj > i) {
                    float a = ss[i], bb = ss[ixj];
                    bool up = ((i & kk) == 0);
                    if ((a > bb) == up) { ss[i] = bb; ss[ixj] = a; }
                }
            }
            __syncthreads();
        }
    }

    if (tid == 0) {
        float thr = ss[NPERG - kkeep];
        int lo = NPERG - kkeep, hi = NPERG;
        while (lo < hi) {
            int mid = (lo + hi) >> 1;
            if (ss[mid] > thr) hi = mid; else lo = mid + 1;
        }
        s_thr = thr;
        s_need = kkeep - (NPERG - lo);
    }
    __syncthreads();
    float thr = s_thr;
    int need_eq = s_need;

    int n0 = tid * 2, n1 = n0 + 1;
    float sc0 = g_nmask[base + n0] ? g_score[base + n0] : NEGV;
    float sc1 = g_nmask[base + n1] ? g_score[base + n1] : NEGV;
    int f0 = (sc0 == thr) ? 1 : 0;
    int f1 = (sc1 == thr) ? 1 : 0;
    int lsum = f0 + f1;
    int incl = lsum;
    #pragma unroll
    for (int o = 1; o < 32; o <<= 1) {
        int t = __shfl_up_sync(0xffffffffu, incl, o);
        if (lane >= o) incl += t;
    }
    if (lane == 31) wsum[wid] = incl;
    __syncthreads();
    if (wid == 0) {
        int v = wsum[lane];
        int inc2 = v;
        #pragma unroll
        for (int o = 1; o < 32; o <<= 1) {
            int t = __shfl_up_sync(0xffffffffu, inc2, o);
            if (lane >= o) inc2 += t;
        }
        wsex[lane] = inc2 - v;
    }
    __syncthreads();
    int rank0 = wsex[wid] + (incl - lsum);
    int rank1 = rank0 + f0;

    int keep0 = (sc0 > thr) || (f0 && rank0 < need_eq);
    int keep1 = (sc1 > thr) || (f1 && rank1 < need_eq);

    g_nmask[base + n0] = keep0;
    g_nmask[base + n1] = keep1;
    float t0 = keep0 ? tanhf(g_score[base + n0]) : 0.f;
    float t1 = keep1 ? tanhf(g_score[base + n1]) : 0.f;
    float2* xr0 = (float2*)(x + (size_t)(base + n0) * F);
    float2* xr1 = (float2*)(x + (size_t)(base + n1) * F);
    for (int i = 0; i < F2; ++i) { float2 v = xr0[i]; v.x *= t0; v.y *= t0; xr0[i] = v; }
    for (int i = 0; i < F2; ++i) { float2 v = xr1[i]; v.x *= t1; v.y *= t1; xr1[i] = v; }
}

// ---------------- final mean + log_softmax ----------------
__global__ void k_final(const float* __restrict__ x, float* __restrict__ out) {
    __shared__ float red[NCLS][9];
    int g = blockIdx.x;
    int base = g * NPERG;
    float acc[NCLS];
    for (int c = 0; c < NCLS; ++c) acc[c] = 0.f;
    for (int n = threadIdx.x; n < NPERG; n += blockDim.x) {
        const float2* xr = (const float2*)(x + (size_t)(base + n) * NCLS);
        #pragma unroll
        for (int c = 0; c < NCLS / 2; ++c) {
            float2 v = xr[c];
            acc[2 * c] += v.x;
            acc[2 * c + 1] += v.y;
        }
    }
    for (int off = 16; off; off >>= 1)
        for (int c = 0; c < NCLS; ++c)
            acc[c] += __shfl_down_sync(0xffffffffu, acc[c], off);
    int lane = threadIdx.x & 31, wid = threadIdx.x >> 5;
    if (lane == 0)
        for (int c = 0; c < NCLS; ++c) red[c][wid] = acc[c];
    __syncthreads();
    if (threadIdx.x == 0) {
        int nw = blockDim.x / 32;
        float z[NCLS];
        for (int c = 0; c < NCLS; ++c) {
            float s = 0.f;
            for (int w = 0; w < nw; ++w) s += red[c][w];
            z[c] = s * (1.f / (NPERG / 4));
        }
        float mx = z[0];
        for (int c = 1; c < NCLS; ++c) mx = fmaxf(mx, z[c]);
        float se = 0.f;
        for (int c = 0; c < NCLS; ++c) se += expf(z[c] - mx);
        float lse = logf(se) + mx;
        for (int c = 0; c < NCLS; ++c) out[g * NCLS + c] = z[c] - lse;
    }
}

// ---------------- host orchestration ----------------
extern "C" void kernel_launch(void* const* d_in, const int* in_sizes, int n_in,
                              void* d_out, int out_size) {
    const float* x     = (const float*)d_in[0];
    const int*   ei    = (const int*)  d_in[1];
    const float* gamma = (const float*)d_in[3];
    const float* beta  = (const float*)d_in[4];
    const float* W1  = (const float*)d_in[5];
    const float* as1 = (const float*)d_in[6];
    const float* ad1 = (const float*)d_in[7];
    const float* b1  = (const float*)d_in[8];
    const float* W2  = (const float*)d_in[9];
    const float* as2 = (const float*)d_in[10];
    const float* ad2 = (const float*)d_in[11];
    const float* b2  = (const float*)d_in[12];
    const float* W3  = (const float*)d_in[13];
    const float* as3 = (const float*)d_in[14];
    const float* ad3 = (const float*)d_in[15];
    const float* b3  = (const float*)d_in[16];
    const float* W4  = (const float*)d_in[17];
    const float* as4 = (const float*)d_in[18];
    const float* ad4 = (const float*)d_in[19];
    const float* b4  = (const float*)d_in[20];
    const float* p1  = (const float*)d_in[21];
    const float* p2  = (const float*)d_in[22];

    int E = in_sizes[1] / 2;
    const int* src = ei;
    const int* dst = ei + E;
    int Etot = E + NTN;
    int eb = (Etot + 255) / 256;

    float *h, *oa, *ob;
    cudaGetSymbolAddress((void**)&h,  g_h);
    cudaGetSymbolAddress((void**)&oa, g_oa);
    cudaGetSymbolAddress((void**)&ob, g_ob);

    int lingrid4 = NTN / 32;        // 8 warps/block x 4 rows/warp (conv1)
    int lingrid8 = NTN / 64;        // 8 warps/block x 8 rows/warp (small convs)
    int gatgrid = NTN * 32 / 256;   // warp per dst node

    k_stats<<<128, 128>>>(x);                                      // 0
    k_deg_count<<<eb, 256>>>(dst, E, Etot);                        // 1
    k_bncoef<<<1, 128>>>(gamma, beta);                             // 2
    k_lin<NFEAT, 3, 16, 4, true><<<lingrid4, 256>>>(x, W1, as1, ad1, h); // 3 <- ncu
    k_scan_block<<<256, 256>>>();                                  // 4
    k_scan_top<<<1, 256>>>();                                      // 5
    k_scan_add<<<256, 256>>>(Etot);                                // 6
    k_scatter<<<eb, 256>>>(src, dst, E, Etot);                     // 7
    k_gat<3, 16, false><<<gatgrid, 256>>>(h, b1, oa);              // 8

    k_lin<48, 3, 16, 8, false><<<lingrid8, 256>>>(oa, W2, as2, ad2, h);
    k_gat<3, 16, false><<<gatgrid, 256>>>(h, b2, ob);
    k_topk<<<NBATCH, 1024>>>(ob, p1, 48, NPERG / 2);
    k_lin<48, 2, 16, 8, false><<<lingrid8, 256>>>(ob, W3, as3, ad3, h);
    k_gat<2, 16, true><<<gatgrid, 256>>>(h, b3, oa);
    k_lin<32, 1, 10, 8, false><<<lingrid8, 256>>>(oa, W4, as4, ad4, h);
    k_gat<1, 10, true><<<gatgrid, 256>>>(h, b4, ob);
    k_topk<<<NBATCH, 1024>>>(ob, p2, 10, NPERG / 4);
    k_final<<<NBATCH, 256>>>(ob, (float*)d_out);
}

// round 13
// speedup vs baseline: 2.7023x; 1.0136x over previous
#include <cuda_runtime.h>
#include <math.h>

#define NTN   65536
#define NBATCH 32
#define NPERG 2048
#define NFEAT 128
#define NCLS  10
#define NEGV  (-1e9f)
#define MASKV (-1e30f)
#define ETOTMAX (NTN * 16 + NTN)   // 1,114,112 edges incl self loops

// ---------------- scratch (device globals; no allocation allowed) ----------
__device__ float  g_h [NTN * 48];      // per-conv linear output (max HC=48)
__device__ float  g_oa[NTN * 48];      // ping buffer
__device__ float  g_ob[NTN * 48];      // pong buffer
__device__ float4 g_alsv[NTN];         // src logits, heads in .x/.y/.z (MASKV = masked)
__device__ float  g_ald[NTN * 3];      // dst logits
__device__ float  g_score[NTN];        // topk raw scores
__device__ int    g_nmask[NTN];        // node mask
__device__ float  g_psum [128 * NFEAT];  // BN partial sums
__device__ float  g_psq  [128 * NFEAT];
__device__ float  g_bnc  [2 * NFEAT];    // BN affine: scale[0:128], shift[128:256]
// CSR (built once per launch)
__device__ int g_deg [NTN];
__device__ int g_off [NTN + 1];
__device__ int g_cur [NTN];
__device__ int g_bsum[256];
__device__ int g_csrc[ETOTMAX];

__device__ __forceinline__ float lrelu(float v) { return v > 0.f ? v : 0.2f * v; }

// ---------------- BN partial stats + zero degrees + mask init ----------------
__global__ void k_stats(const float* __restrict__ x) {
    int f = threadIdx.x;                       // 128 threads
    int b = blockIdx.x;                        // 128 blocks
    int r0 = b * (NTN / 128);
    float s = 0.f, s2 = 0.f;
    for (int r = r0; r < r0 + NTN / 128; ++r) {
        float v = x[r * NFEAT + f];
        s += v; s2 += v * v;
    }
    g_psum[b * NFEAT + f] = s;
    g_psq [b * NFEAT + f] = s2;
    int gid = b * 128 + f;
    for (int i = gid; i < NTN; i += 128 * 128) { g_deg[i] = 0; g_nmask[i] = 1; }
}

// ---------------- degree count + BN coefficient reduce (fused) -------------
// blocks [0, eb) count degrees; the LAST block reduces BN coefficients.
__global__ void k_deg_bnc(const int* __restrict__ dst, int E, int Etot,
                          const float* __restrict__ gamma, const float* __restrict__ beta) {
    if (blockIdx.x == gridDim.x - 1) {
        int f = threadIdx.x;
        if (f < NFEAT) {
            float s = 0.f, s2 = 0.f;
            for (int b = 0; b < 128; ++b) {
                s  += g_psum[b * NFEAT + f];
                s2 += g_psq [b * NFEAT + f];
            }
            float mu  = s  * (1.f / NTN);
            float var = s2 * (1.f / NTN) - mu * mu;
            float rstd = rsqrtf(var + 1e-5f);
            float ga = gamma[f];
            g_bnc[f]         = ga * rstd;
            g_bnc[NFEAT + f] = beta[f] - mu * ga * rstd;
        }
        return;
    }
    int e = blockIdx.x * blockDim.x + threadIdx.x;
    if (e >= Etot) return;
    int d = (e < E) ? dst[e] : (e - E);
    atomicAdd(&g_deg[d], 1);
}

// ---------------- hierarchical scan of degrees ----------------
__global__ void k_scan_block() {            // 256 blocks x 256 threads
    __shared__ int sh[256];
    int n = blockIdx.x * 256 + threadIdx.x;
    int v = g_deg[n];
    sh[threadIdx.x] = v;
    __syncthreads();
    for (int o = 1; o < 256; o <<= 1) {
        int t = (threadIdx.x >= o) ? sh[threadIdx.x - o] : 0;
        __syncthreads();
        sh[threadIdx.x] += t;
        __syncthreads();
    }
    g_off[n] = sh[threadIdx.x] - v;
    if (threadIdx.x == 255) g_bsum[blockIdx.x] = sh[255];
}

// fused top-scan + add-back: every block redundantly scans the 256 block
// sums in smem (cheap), then applies its own exclusive offset.
__global__ void k_scan_add2(int Etot) {     // 256 blocks x 256 threads
    __shared__ int sh[256];
    int t = threadIdx.x;
    sh[t] = g_bsum[t];
    __syncthreads();
    for (int o = 1; o < 256; o <<= 1) {
        int v = (t >= o) ? sh[t - o] : 0;
        __syncthreads();
        sh[t] += v;
        __syncthreads();
    }
    int bsex = (blockIdx.x > 0) ? sh[blockIdx.x - 1] : 0;   // broadcast read
    int n = blockIdx.x * 256 + t;
    int o2 = g_off[n] + bsex;
    g_off[n] = o2;
    g_cur[n] = o2;
    if (n == 0) g_off[NTN] = Etot;
}

// ---------------- scatter edges into CSR ----------------
__global__ void k_scatter(const int* __restrict__ src, const int* __restrict__ dst,
                          int E, int Etot) {
    int e = blockIdx.x * blockDim.x + threadIdx.x;
    if (e >= Etot) return;
    int s, d;
    if (e < E) { s = src[e]; d = dst[e]; } else { s = e - E; d = s; }
    int pos = atomicAdd(&g_cur[d], 1);
    g_csrc[pos] = s;
}

// ---------------- fused (BN +) linear + attention logits ----------------
template <int Fin, int H, int C, int RW, bool BNF>
__global__ __launch_bounds__(256) void k_lin(const float* __restrict__ xin,
                                             const float* __restrict__ W,
                                             const float* __restrict__ a_s,
                                             const float* __restrict__ a_d,
                                             float* __restrict__ h) {
    constexpr int HC = H * C;
    __shared__ float Ws[Fin * HC];
    __shared__ float xs[8][RW * Fin];
    __shared__ float asv[HC], adv[HC];
    __shared__ float sg[BNF ? NFEAT : 1], sb[BNF ? NFEAT : 1];
    int tid = threadIdx.x, lane = tid & 31, wid = tid >> 5;
    for (int i = tid; i < Fin * HC; i += 256) Ws[i] = W[i];
    if (tid < HC) { asv[tid] = a_s[tid]; adv[tid] = a_d[tid]; }
    if (BNF && tid < NFEAT) {
        sg[tid] = g_bnc[tid];
        sb[tid] = g_bnc[NFEAT + tid];
    }
    __syncthreads();

    int rbase = (blockIdx.x * 8 + wid) * RW;
    int c0 = 2 * lane;
    bool act = (c0 < HC);

    const float4* xin4 = (const float4*)(xin + (size_t)rbase * Fin);
    float4* xs4 = (float4*)xs[wid];
    for (int t = lane; t < RW * Fin / 4; t += 32) {
        float4 v = xin4[t];
        if (BNF) {
            int f0 = (t * 4) & (Fin - 1);
            v.x = v.x * sg[f0]     + sb[f0];
            v.y = v.y * sg[f0 + 1] + sb[f0 + 1];
            v.z = v.z * sg[f0 + 2] + sb[f0 + 2];
            v.w = v.w * sg[f0 + 3] + sb[f0 + 3];
        }
        xs4[t] = v;
    }
    __syncwarp();

    float ax[RW], ay[RW];
    #pragma unroll
    for (int r = 0; r < RW; ++r) { ax[r] = 0.f; ay[r] = 0.f; }

    if (act) {
        #pragma unroll 4
        for (int i0 = 0; i0 < Fin; i0 += 4) {
            float2 w0 = *(const float2*)&Ws[(i0 + 0) * HC + c0];
            float2 w1 = *(const float2*)&Ws[(i0 + 1) * HC + c0];
            float2 w2 = *(const float2*)&Ws[(i0 + 2) * HC + c0];
            float2 w3 = *(const float2*)&Ws[(i0 + 3) * HC + c0];
            #pragma unroll
            for (int r = 0; r < RW; ++r) {
                float4 xv = *(const float4*)&xs[wid][r * Fin + i0];
                ax[r] += xv.x * w0.x; ay[r] += xv.x * w0.y;
                ax[r] += xv.y * w1.x; ay[r] += xv.y * w1.y;
                ax[r] += xv.z * w2.x; ay[r] += xv.z * w2.y;
                ax[r] += xv.w * w3.x; ay[r] += xv.w * w3.y;
            }
        }
        #pragma unroll
        for (int r = 0; r < RW; ++r)
            *(float2*)(h + (size_t)(rbase + r) * HC + c0) = make_float2(ax[r], ay[r]);
    }

    #pragma unroll
    for (int r = 0; r < RW; ++r) {
        float ps = 0.f, pd = 0.f;
        if (act) {
            ps = ax[r] * asv[c0] + ay[r] * asv[c0 + 1];
            pd = ax[r] * adv[c0] + ay[r] * adv[c0 + 1];
        }
        if (C == 16) {
            #pragma unroll
            for (int o = 4; o; o >>= 1) {
                ps += __shfl_xor_sync(0xffffffffu, ps, o);
                pd += __shfl_xor_sync(0xffffffffu, pd, o);
            }
        } else {
            #pragma unroll
            for (int o = 16; o; o >>= 1) {
                ps += __shfl_xor_sync(0xffffffffu, ps, o);
                pd += __shfl_xor_sync(0xffffffffu, pd, o);
            }
        }
        float p1 = __shfl_sync(0xffffffffu, ps, 8);
        float p2 = __shfl_sync(0xffffffffu, ps, 16);
        float d1 = __shfl_sync(0xffffffffu, pd, 8);
        float d2 = __shfl_sync(0xffffffffu, pd, 16);
        if (lane == 0) {
            int rr = rbase + r;
            int msk = g_nmask[rr];
            if (H == 3) {
                g_alsv[rr] = msk ? make_float4(ps, p1, p2, 0.f)
                                 : make_float4(MASKV, MASKV, MASKV, 0.f);
                g_ald[rr * 3]     = pd;
                g_ald[rr * 3 + 1] = d1;
                g_ald[rr * 3 + 2] = d2;
            } else if (H == 2) {
                g_alsv[rr] = msk ? make_float4(ps, p1, 0.f, 0.f)
                                 : make_float4(MASKV, MASKV, 0.f, 0.f);
                g_ald[rr * 3]     = pd;
                g_ald[rr * 3 + 1] = d1;
            } else {
                g_alsv[rr] = msk ? make_float4(ps, 0.f, 0.f, 0.f)
                                 : make_float4(MASKV, 0.f, 0.f, 0.f);
                g_ald[rr * 3] = pd;
            }
        }
    }
}

// ---------------- fused attention softmax + aggregation ----------------
// warp per dst node; per-edge state in smem.
// NG = groups per warp for phase B: each group of 32/NG lanes owns the
// channel pairs and walks a different edge (stride NG); groups are merged
// by a shfl_xor reduction over strides >= group size.
template <int H, int C, bool MASKED, int NG>
__global__ __launch_bounds__(256) void k_gat(const float* __restrict__ h,
                                             const float* __restrict__ b,
                                             float* __restrict__ out) {
    constexpr int HC = H * C;
    constexpr int CAP = 64;                  // per-warp edge cache capacity
    constexpr int GSZ = 32 / NG;             // lanes per group
    __shared__ float sAl[8][CAP * H + 1];    // logits -> alphas
    __shared__ int   sSr[8][CAP + 1];
    __shared__ float sAc[MASKED ? 8 : 1][MASKED ? (CAP * H + 1) : 1];
    __shared__ int   sSc[MASKED ? 8 : 1][MASKED ? (CAP + 1) : 1];
    int d = (blockIdx.x * blockDim.x + threadIdx.x) >> 5;
    if (d >= NTN) return;
    int lane = threadIdx.x & 31;
    int wid = (threadIdx.x >> 5) & 7;
    int grp = lane / GSZ;
    int lc  = lane & (GSZ - 1);
    int c0 = 2 * lc;
    bool act = (c0 < HC);          // active channel pair within group
    bool wlane = (grp == 0) && act; // lanes that write output

    if (MASKED && !g_nmask[d]) {
        if (wlane) *(float2*)(out + (size_t)d * HC + c0) = make_float2(b[c0], b[c0 + 1]);
        return;
    }

    int beg = g_off[d], end = g_off[d + 1];
    float ald_d[H], m[H], den[H];
    #pragma unroll
    for (int hh = 0; hh < H; ++hh) {
        ald_d[hh] = g_ald[d * 3 + hh];
        m[hh] = NEGV; den[hh] = 0.f;
    }

    // phase A: gather logits, cache to smem, online softmax (lanes stride edges)
    for (int i = beg + lane; i < end; i += 32) {
        int j = i - beg;
        int s = g_csrc[i];
        float4 av = g_alsv[s];               // single 128-bit gather, all heads
        float avh[3] = {av.x, av.y, av.z};
        if (j < CAP) sSr[wid][j] = s;
        #pragma unroll
        for (int hh = 0; hh < H; ++hh) {
            float v = lrelu(avh[hh] + ald_d[hh]);   // masked: ~-2e29 -> exp 0
            if (j < CAP) sAl[wid][j * H + hh] = v;
            if (v <= m[hh]) {
                den[hh] += __expf(v - m[hh]);
            } else {
                den[hh] = den[hh] * __expf(m[hh] - v) + 1.f;
                m[hh] = v;
            }
        }
    }
    #pragma unroll
    for (int o = 16; o; o >>= 1) {
        #pragma unroll
        for (int hh = 0; hh < H; ++hh) {
            float mo = __shfl_xor_sync(0xffffffffu, m[hh], o);
            float eo = __shfl_xor_sync(0xffffffffu, den[hh], o);
            float nm = fmaxf(m[hh], mo);
            den[hh] = den[hh] * __expf(m[hh] - nm) + eo * __expf(mo - nm);
            m[hh] = nm;
        }
    }
    float inv[H];
    #pragma unroll
    for (int hh = 0; hh < H; ++hh) inv[hh] = 1.f / fmaxf(den[hh], 1e-16f);

    int deg = end - beg;
    int cap = deg < CAP ? deg : CAP;
    int nk;

    if (MASKED) {
        // convert + warp-compact surviving edges (ballot+popc)
        nk = 0;
        for (int j0 = 0; j0 < cap; j0 += 32) {
            int j = j0 + lane;
            bool have = (j < cap);
            float aH[H]; int s = 0;
            bool keep = false;
            if (have) {
                s = sSr[wid][j];
                #pragma unroll
                for (int hh = 0; hh < H; ++hh)
                    aH[hh] = __expf(sAl[wid][j * H + hh] - m[hh]) * inv[hh];
                #pragma unroll
                for (int hh = 0; hh < H; ++hh) keep = keep || (aH[hh] > 0.f);
            }
            unsigned bal = __ballot_sync(0xffffffffu, keep);
            int pos = nk + __popc(bal & ((1u << lane) - 1u));
            if (keep) {
                sSc[wid][pos] = s;
                #pragma unroll
                for (int hh = 0; hh < H; ++hh) sAc[wid][pos * H + hh] = aH[hh];
            }
            nk += __popc(bal);
        }
    } else {
        for (int j = lane; j < cap; j += 32) {
            #pragma unroll
            for (int hh = 0; hh < H; ++hh) {
                float v = sAl[wid][j * H + hh];
                sAl[wid][j * H + hh] = __expf(v - m[hh]) * inv[hh];
            }
        }
        nk = cap;
    }
    __syncwarp();

    int hh0 = c0 / C;
    float m_my = m[0], inv_my = inv[0];
    #pragma unroll
    for (int hh = 1; hh < H; ++hh)
        if (hh == hh0) { m_my = m[hh]; inv_my = inv[hh]; }
    float ald_my = ald_d[0];
    #pragma unroll
    for (int hh = 1; hh < H; ++hh)
        if (hh == hh0) ald_my = ald_d[hh];

    // phase B: each group walks edges grp, grp+NG, ...; dense, branch-free
    float accx = 0.f, accy = 0.f;
    if (act) {
        #pragma unroll 8
        for (int j = grp; j < nk; j += NG) {
            float a = MASKED ? sAc[wid][j * H + hh0] : sAl[wid][j * H + hh0];
            int s = MASKED ? sSc[wid][j] : sSr[wid][j];
            float2 hv = *(const float2*)(h + (size_t)s * HC + c0);
            accx += a * hv.x;
            accy += a * hv.y;
        }
    }
    // tail for deg > CAP (vanishingly rare): recompute alpha from alsv
    for (int i = beg + CAP + grp; i < end; i += NG) {
        int s = g_csrc[i];
        float4 av = g_alsv[s];
        float avh[3] = {av.x, av.y, av.z};
        float v = lrelu(avh[hh0] + ald_my);
        float a = __expf(v - m_my) * inv_my;
        if (a > 0.f && act) {
            float2 hv = *(const float2*)(h + (size_t)s * HC + c0);
            accx += a * hv.x;
            accy += a * hv.y;
        }
    }
    // merge groups
    #pragma unroll
    for (int o = GSZ; o < 32; o <<= 1) {
        accx += __shfl_xor_sync(0xffffffffu, accx, o);
        accy += __shfl_xor_sync(0xffffffffu, accy, o);
    }
    if (wlane) *(float2*)(out + (size_t)d * HC + c0) = make_float2(accx + b[c0], accy + b[c0 + 1]);
}

// ---------------- TopK pooling (float2-vectorized; F must be even) --------
__global__ void k_topk(float* __restrict__ x, const float* __restrict__ p,
                       int F, int kkeep) {
    __shared__ float ss[NPERG];
    __shared__ int   wsum[32];
    __shared__ int   wsex[32];
    __shared__ float s_thr;
    __shared__ int   s_need;
    int g = blockIdx.x;
    int base = g * NPERG;
    int tid = threadIdx.x;
    int lane = tid & 31, wid = tid >> 5;
    int F2 = F >> 1;
    const float2* p2 = (const float2*)p;

    float nrm = 0.f;
    for (int i = 0; i < F2; ++i) { float2 pv = p2[i]; nrm += pv.x * pv.x + pv.y * pv.y; }
    nrm = rsqrtf(nrm);

    for (int n = tid; n < NPERG; n += blockDim.x) {
        int node = base + n;
        const float2* xr = (const float2*)(x + (size_t)node * F);
        float sc = 0.f;
        for (int i = 0; i < F2; ++i) {
            float2 xv = xr[i], pv = p2[i];
            sc += xv.x * pv.x + xv.y * pv.y;
        }
        sc *= nrm;
        g_score[node] = sc;
        ss[n] = g_nmask[node] ? sc : NEGV;
    }
    __syncthreads();

    for (int kk = 2; kk <= NPERG; kk <<= 1) {
        for (int j = kk >> 1; j > 0; j >>= 1) {
            for (int i = tid; i < NPERG; i += blockDim.x) {
                int ixj = i ^ j;
                if (ixj > i) {
                    float a = ss[i], bb = ss[ixj];
                    bool up = ((i & kk) == 0);
                    if ((a > bb) == up) { ss[i] = bb; ss[ixj] = a; }
                }
            }
            __syncthreads();
        }
    }

    if (tid == 0) {
        float thr = ss[NPERG - kkeep];
        int lo = NPERG - kkeep, hi = NPERG;
        while (lo < hi) {
            int mid = (lo + hi) >> 1;
            if (ss[mid] > thr) hi = mid; else lo = mid + 1;
        }
        s_thr = thr;
        s_need = kkeep - (NPERG - lo);
    }
    __syncthreads();
    float thr = s_thr;
    int need_eq = s_need;

    int n0 = tid * 2, n1 = n0 + 1;
    float sc0 = g_nmask[base + n0] ? g_score[base + n0] : NEGV;
    float sc1 = g_nmask[base + n1] ? g_score[base + n1] : NEGV;
    int f0 = (sc0 == thr) ? 1 : 0;
    int f1 = (sc1 == thr) ? 1 : 0;
    int lsum = f0 + f1;
    int incl = lsum;
    #pragma unroll
    for (int o = 1; o < 32; o <<= 1) {
        int t = __shfl_up_sync(0xffffffffu, incl, o);
        if (lane >= o) incl += t;
    }
    if (lane == 31) wsum[wid] = incl;
    __syncthreads();
    if (wid == 0) {
        int v = wsum[lane];
        int inc2 = v;
        #pragma unroll
        for (int o = 1; o < 32; o <<= 1) {
            int t = __shfl_up_sync(0xffffffffu, inc2, o);
            if (lane >= o) inc2 += t;
        }
        wsex[lane] = inc2 - v;
    }
    __syncthreads();
    int rank0 = wsex[wid] + (incl - lsum);
    int rank1 = rank0 + f0;

    int keep0 = (sc0 > thr) || (f0 && rank0 < need_eq);
    int keep1 = (sc1 > thr) || (f1 && rank1 < need_eq);

    g_nmask[base + n0] = keep0;
    g_nmask[base + n1] = keep1;
    float t0 = keep0 ? tanhf(g_score[base + n0]) : 0.f;
    float t1 = keep1 ? tanhf(g_score[base + n1]) : 0.f;
    float2* xr0 = (float2*)(x + (size_t)(base + n0) * F);
    float2* xr1 = (float2*)(x + (size_t)(base + n1) * F);
    for (int i = 0; i < F2; ++i) { float2 v = xr0[i]; v.x *= t0; v.y *= t0; xr0[i] = v; }
    for (int i = 0; i < F2; ++i) { float2 v = xr1[i]; v.x *= t1; v.y *= t1; xr1[i] = v; }
}

// ---------------- final mean + log_softmax ----------------
__global__ void k_final(const float* __restrict__ x, float* __restrict__ out) {
    __shared__ float red[NCLS][9];
    int g = blockIdx.x;
    int base = g * NPERG;
    float acc[NCLS];
    for (int c = 0; c < NCLS; ++c) acc[c] = 0.f;
    for (int n = threadIdx.x; n < NPERG; n += blockDim.x) {
        const float2* xr = (const float2*)(x + (size_t)(base + n) * NCLS);
        #pragma unroll
        for (int c = 0; c < NCLS / 2; ++c) {
            float2 v = xr[c];
            acc[2 * c] += v.x;
            acc[2 * c + 1] += v.y;
        }
    }
    for (int off = 16; off; off >>= 1)
        for (int c = 0; c < NCLS; ++c)
            acc[c] += __shfl_down_sync(0xffffffffu, acc[c], off);
    int lane = threadIdx.x & 31, wid = threadIdx.x >> 5;
    if (lane == 0)
        for (int c = 0; c < NCLS; ++c) red[c][wid] = acc[c];
    __syncthreads();
    if (threadIdx.x == 0) {
        int nw = blockDim.x / 32;
        float z[NCLS];
        for (int c = 0; c < NCLS; ++c) {
            float s = 0.f;
            for (int w = 0; w < nw; ++w) s += red[c][w];
            z[c] = s * (1.f / (NPERG / 4));
        }
        float mx = z[0];
        for (int c = 1; c < NCLS; ++c) mx = fmaxf(mx, z[c]);
        float se = 0.f;
        for (int c = 0; c < NCLS; ++c) se += expf(z[c] - mx);
        float lse = logf(se) + mx;
        for (int c = 0; c < NCLS; ++c) out[g * NCLS + c] = z[c] - lse;
    }
}

// ---------------- host orchestration ----------------
extern "C" void kernel_launch(void* const* d_in, const int* in_sizes, int n_in,
                              void* d_out, int out_size) {
    const float* x     = (const float*)d_in[0];
    const int*   ei    = (const int*)  d_in[1];
    const float* gamma = (const float*)d_in[3];
    const float* beta  = (const float*)d_in[4];
    const float* W1  = (const float*)d_in[5];
    const float* as1 = (const float*)d_in[6];
    const float* ad1 = (const float*)d_in[7];
    const float* b1  = (const float*)d_in[8];
    const float* W2  = (const float*)d_in[9];
    const float* as2 = (const float*)d_in[10];
    const float* ad2 = (const float*)d_in[11];
    const float* b2  = (const float*)d_in[12];
    const float* W3  = (const float*)d_in[13];
    const float* as3 = (const float*)d_in[14];
    const float* ad3 = (const float*)d_in[15];
    const float* b3  = (const float*)d_in[16];
    const float* W4  = (const float*)d_in[17];
    const float* as4 = (const float*)d_in[18];
    const float* ad4 = (const float*)d_in[19];
    const float* b4  = (const float*)d_in[20];
    const float* p1  = (const float*)d_in[21];
    const float* p2  = (const float*)d_in[22];

    int E = in_sizes[1] / 2;
    const int* src = ei;
    const int* dst = ei + E;
    int Etot = E + NTN;
    int eb = (Etot + 255) / 256;

    float *h, *oa, *ob;
    cudaGetSymbolAddress((void**)&h,  g_h);
    cudaGetSymbolAddress((void**)&oa, g_oa);
    cudaGetSymbolAddress((void**)&ob, g_ob);

    int lingrid4 = NTN / 32;        // 8 warps/block x 4 rows/warp (conv1)
    int lingrid8 = NTN / 64;        // 8 warps/block x 8 rows/warp (small convs)
    int gatgrid = NTN * 32 / 256;   // warp per dst node

    k_stats<<<128, 128>>>(x);                                      // 0
    k_deg_bnc<<<eb + 1, 256>>>(dst, E, Etot, gamma, beta);         // 1
    k_scan_block<<<256, 256>>>();                                  // 2
    k_lin<NFEAT, 3, 16, 4, true><<<lingrid4, 256>>>(x, W1, as1, ad1, h); // 3 <- ncu
    k_scan_add2<<<256, 256>>>(Etot);                               // 4
    k_scatter<<<eb, 256>>>(src, dst, E, Etot);                     // 5
    k_gat<3, 16, false, 1><<<gatgrid, 256>>>(h, b1, oa);           // 6

    k_lin<48, 3, 16, 8, false><<<lingrid8, 256>>>(oa, W2, as2, ad2, h);
    k_gat<3, 16, false, 1><<<gatgrid, 256>>>(h, b2, ob);
    k_topk<<<NBATCH, 1024>>>(ob, p1, 48, NPERG / 2);
    k_lin<48, 2, 16, 8, false><<<lingrid8, 256>>>(ob, W3, as3, ad3, h);
    k_gat<2, 16, true, 2><<<gatgrid, 256>>>(h, b3, oa);
    k_lin<32, 1, 10, 8, false><<<lingrid8, 256>>>(oa, W4, as4, ad4, h);
    k_gat<1, 10, true, 4><<<gatgrid, 256>>>(h, b4, ob);
    k_topk<<<NBATCH, 1024>>>(ob, p2, 10, NPERG / 4);
    k_final<<<NBATCH, 256>>>(ob, (float*)d_out);
}

// round 14
// speedup vs baseline: 2.8303x; 1.0474x over previous
#include <cuda_runtime.h>
#include <math.h>

#define NTN   65536
#define NBATCH 32
#define NPERG 2048
#define NFEAT 128
#define NCLS  10
#define NEGV  (-1e9f)
#define MASKV (-1e30f)
#define ETOTMAX (NTN * 16 + NTN)   // 1,114,112 edges incl self loops

// ---------------- scratch (device globals; no allocation allowed) ----------
__device__ float  g_h [NTN * 48];      // per-conv linear output (max HC=48)
__device__ float  g_oa[NTN * 48];      // ping buffer
__device__ float  g_ob[NTN * 48];      // pong buffer
__device__ float4 g_alsv[NTN];         // src logits, heads in .x/.y/.z (MASKV = masked)
__device__ float  g_ald[NTN * 3];      // dst logits
__device__ float  g_score[NTN];        // topk raw scores
__device__ int    g_nmask[NTN];        // node mask
__device__ float  g_psum [128 * NFEAT];  // BN partial sums
__device__ float  g_psq  [128 * NFEAT];
__device__ float  g_bnc  [2 * NFEAT];    // BN affine: scale[0:128], shift[128:256]
// CSR (built once per launch)
__device__ int g_deg [NTN];
__device__ int g_off [NTN + 1];
__device__ int g_cur [NTN];
__device__ int g_bsum[256];
__device__ int g_csrc[ETOTMAX];

__device__ __forceinline__ float lrelu(float v) { return v > 0.f ? v : 0.2f * v; }

// ---------------- BN partial stats + zero degrees + mask init ----------------
__global__ void k_stats(const float* __restrict__ x) {
    int f = threadIdx.x;                       // 128 threads
    int b = blockIdx.x;                        // 128 blocks
    int r0 = b * (NTN / 128);
    float s = 0.f, s2 = 0.f;
    for (int r = r0; r < r0 + NTN / 128; ++r) {
        float v = x[r * NFEAT + f];
        s += v; s2 += v * v;
    }
    g_psum[b * NFEAT + f] = s;
    g_psq [b * NFEAT + f] = s2;
    int gid = b * 128 + f;
    for (int i = gid; i < NTN; i += 128 * 128) { g_deg[i] = 0; g_nmask[i] = 1; }
}

// ---------------- degree count + BN coefficient reduce (fused) -------------
__global__ void k_deg_bnc(const int* __restrict__ dst, int E, int Etot,
                          const float* __restrict__ gamma, const float* __restrict__ beta) {
    if (blockIdx.x == gridDim.x - 1) {
        int f = threadIdx.x;
        if (f < NFEAT) {
            float s = 0.f, s2 = 0.f;
            for (int b = 0; b < 128; ++b) {
                s  += g_psum[b * NFEAT + f];
                s2 += g_psq [b * NFEAT + f];
            }
            float mu  = s  * (1.f / NTN);
            float var = s2 * (1.f / NTN) - mu * mu;
            float rstd = rsqrtf(var + 1e-5f);
            float ga = gamma[f];
            g_bnc[f]         = ga * rstd;
            g_bnc[NFEAT + f] = beta[f] - mu * ga * rstd;
        }
        return;
    }
    int e = blockIdx.x * blockDim.x + threadIdx.x;
    if (e >= Etot) return;
    int d = (e < E) ? dst[e] : (e - E);
    atomicAdd(&g_deg[d], 1);
}

// ---------------- hierarchical scan of degrees ----------------
__global__ void k_scan_block() {            // 256 blocks x 256 threads
    __shared__ int sh[256];
    int n = blockIdx.x * 256 + threadIdx.x;
    int v = g_deg[n];
    sh[threadIdx.x] = v;
    __syncthreads();
    for (int o = 1; o < 256; o <<= 1) {
        int t = (threadIdx.x >= o) ? sh[threadIdx.x - o] : 0;
        __syncthreads();
        sh[threadIdx.x] += t;
        __syncthreads();
    }
    g_off[n] = sh[threadIdx.x] - v;
    if (threadIdx.x == 255) g_bsum[blockIdx.x] = sh[255];
}

__global__ void k_scan_add2(int Etot) {     // 256 blocks x 256 threads
    __shared__ int sh[256];
    int t = threadIdx.x;
    sh[t] = g_bsum[t];
    __syncthreads();
    for (int o = 1; o < 256; o <<= 1) {
        int v = (t >= o) ? sh[t - o] : 0;
        __syncthreads();
        sh[t] += v;
        __syncthreads();
    }
    int bsex = (blockIdx.x > 0) ? sh[blockIdx.x - 1] : 0;   // broadcast read
    int n = blockIdx.x * 256 + t;
    int o2 = g_off[n] + bsex;
    g_off[n] = o2;
    g_cur[n] = o2;
    if (n == 0) g_off[NTN] = Etot;
}

// ---------------- scatter edges into CSR ----------------
__global__ void k_scatter(const int* __restrict__ src, const int* __restrict__ dst,
                          int E, int Etot) {
    int e = blockIdx.x * blockDim.x + threadIdx.x;
    if (e >= Etot) return;
    int s, d;
    if (e < E) { s = src[e]; d = dst[e]; } else { s = e - E; d = s; }
    int pos = atomicAdd(&g_cur[d], 1);
    g_csrc[pos] = s;
}

// ---------------- fused (BN +) linear + attention logits ----------------
template <int Fin, int H, int C, int RW, bool BNF>
__global__ __launch_bounds__(256) void k_lin(const float* __restrict__ xin,
                                             const float* __restrict__ W,
                                             const float* __restrict__ a_s,
                                             const float* __restrict__ a_d,
                                             float* __restrict__ h) {
    constexpr int HC = H * C;
    __shared__ float Ws[Fin * HC];
    __shared__ float xs[8][RW * Fin];
    __shared__ float asv[HC], adv[HC];
    __shared__ float sg[BNF ? NFEAT : 1], sb[BNF ? NFEAT : 1];
    int tid = threadIdx.x, lane = tid & 31, wid = tid >> 5;
    for (int i = tid; i < Fin * HC; i += 256) Ws[i] = W[i];
    if (tid < HC) { asv[tid] = a_s[tid]; adv[tid] = a_d[tid]; }
    if (BNF && tid < NFEAT) {
        sg[tid] = g_bnc[tid];
        sb[tid] = g_bnc[NFEAT + tid];
    }
    __syncthreads();

    int rbase = (blockIdx.x * 8 + wid) * RW;
    int c0 = 2 * lane;
    bool act = (c0 < HC);

    const float4* xin4 = (const float4*)(xin + (size_t)rbase * Fin);
    float4* xs4 = (float4*)xs[wid];
    for (int t = lane; t < RW * Fin / 4; t += 32) {
        float4 v = xin4[t];
        if (BNF) {
            int f0 = (t * 4) & (Fin - 1);
            v.x = v.x * sg[f0]     + sb[f0];
            v.y = v.y * sg[f0 + 1] + sb[f0 + 1];
            v.z = v.z * sg[f0 + 2] + sb[f0 + 2];
            v.w = v.w * sg[f0 + 3] + sb[f0 + 3];
        }
        xs4[t] = v;
    }
    __syncwarp();

    float ax[RW], ay[RW];
    #pragma unroll
    for (int r = 0; r < RW; ++r) { ax[r] = 0.f; ay[r] = 0.f; }

    if (act) {
        #pragma unroll 4
        for (int i0 = 0; i0 < Fin; i0 += 4) {
            float2 w0 = *(const float2*)&Ws[(i0 + 0) * HC + c0];
            float2 w1 = *(const float2*)&Ws[(i0 + 1) * HC + c0];
            float2 w2 = *(const float2*)&Ws[(i0 + 2) * HC + c0];
            float2 w3 = *(const float2*)&Ws[(i0 + 3) * HC + c0];
            #pragma unroll
            for (int r = 0; r < RW; ++r) {
                float4 xv = *(const float4*)&xs[wid][r * Fin + i0];
                ax[r] += xv.x * w0.x; ay[r] += xv.x * w0.y;
                ax[r] += xv.y * w1.x; ay[r] += xv.y * w1.y;
                ax[r] += xv.z * w2.x; ay[r] += xv.z * w2.y;
                ax[r] += xv.w * w3.x; ay[r] += xv.w * w3.y;
            }
        }
        #pragma unroll
        for (int r = 0; r < RW; ++r)
            *(float2*)(h + (size_t)(rbase + r) * HC + c0) = make_float2(ax[r], ay[r]);
    }

    #pragma unroll
    for (int r = 0; r < RW; ++r) {
        float ps = 0.f, pd = 0.f;
        if (act) {
            ps = ax[r] * asv[c0] + ay[r] * asv[c0 + 1];
            pd = ax[r] * adv[c0] + ay[r] * adv[c0 + 1];
        }
        if (C == 16) {
            #pragma unroll
            for (int o = 4; o; o >>= 1) {
                ps += __shfl_xor_sync(0xffffffffu, ps, o);
                pd += __shfl_xor_sync(0xffffffffu, pd, o);
            }
        } else {
            #pragma unroll
            for (int o = 16; o; o >>= 1) {
                ps += __shfl_xor_sync(0xffffffffu, ps, o);
                pd += __shfl_xor_sync(0xffffffffu, pd, o);
            }
        }
        float p1 = __shfl_sync(0xffffffffu, ps, 8);
        float p2 = __shfl_sync(0xffffffffu, ps, 16);
        float d1 = __shfl_sync(0xffffffffu, pd, 8);
        float d2 = __shfl_sync(0xffffffffu, pd, 16);
        if (lane == 0) {
            int rr = rbase + r;
            int msk = g_nmask[rr];
            if (H == 3) {
                g_alsv[rr] = msk ? make_float4(ps, p1, p2, 0.f)
                                 : make_float4(MASKV, MASKV, MASKV, 0.f);
                g_ald[rr * 3]     = pd;
                g_ald[rr * 3 + 1] = d1;
                g_ald[rr * 3 + 2] = d2;
            } else if (H == 2) {
                g_alsv[rr] = msk ? make_float4(ps, p1, 0.f, 0.f)
                                 : make_float4(MASKV, MASKV, 0.f, 0.f);
                g_ald[rr * 3]     = pd;
                g_ald[rr * 3 + 1] = d1;
            } else {
                g_alsv[rr] = msk ? make_float4(ps, 0.f, 0.f, 0.f)
                                 : make_float4(MASKV, 0.f, 0.f, 0.f);
                g_ald[rr * 3] = pd;
            }
        }
    }
}

// ---------------- fused attention softmax + aggregation ----------------
// warp per dst node; DEFERRED-NORMALIZATION softmax:
//   phase A: logits -> smem, track MAX only (no expf)
//   butterfly: max only (fmaxf, no MUFU)
//   convert:  ex = expf(v - m) once per (edge,head); den accumulated per lane
//   butterfly: den sum (adds only)
//   phase B:  accumulate ex*h[src]; single multiply by 1/den at the end.
// Exactly matches reference math (ex/den), fewer and non-serialized expf.
template <int H, int C, bool MASKED, int NG>
__global__ __launch_bounds__(256) void k_gat(const float* __restrict__ h,
                                             const float* __restrict__ b,
                                             float* __restrict__ out) {
    constexpr int HC = H * C;
    constexpr int CAP = 64;                  // per-warp edge cache capacity
    constexpr int GSZ = 32 / NG;             // lanes per group
    __shared__ float sAl[8][CAP * H + 1];    // logits -> unnormalized ex
    __shared__ int   sSr[8][CAP + 1];
    __shared__ float sAc[MASKED ? 8 : 1][MASKED ? (CAP * H + 1) : 1];
    __shared__ int   sSc[MASKED ? 8 : 1][MASKED ? (CAP + 1) : 1];
    int d = (blockIdx.x * blockDim.x + threadIdx.x) >> 5;
    if (d >= NTN) return;
    int lane = threadIdx.x & 31;
    int wid = (threadIdx.x >> 5) & 7;
    int grp = lane / GSZ;
    int lc  = lane & (GSZ - 1);
    int c0 = 2 * lc;
    bool act = (c0 < HC);
    bool wlane = (grp == 0) && act;

    if (MASKED && !g_nmask[d]) {
        if (wlane) *(float2*)(out + (size_t)d * HC + c0) = make_float2(b[c0], b[c0 + 1]);
        return;
    }

    int beg = g_off[d], end = g_off[d + 1];
    float ald_d[H], m[H];
    #pragma unroll
    for (int hh = 0; hh < H; ++hh) {
        ald_d[hh] = g_ald[d * 3 + hh];
        m[hh] = NEGV;
    }

    // phase A: gather logits, cache to smem, track max (lanes stride edges)
    for (int i = beg + lane; i < end; i += 32) {
        int j = i - beg;
        int s = g_csrc[i];
        float4 av = g_alsv[s];               // single 128-bit gather, all heads
        float avh[3] = {av.x, av.y, av.z};
        if (j < CAP) sSr[wid][j] = s;
        #pragma unroll
        for (int hh = 0; hh < H; ++hh) {
            float v = lrelu(avh[hh] + ald_d[hh]);   // masked: ~-2e29
            if (j < CAP) sAl[wid][j * H + hh] = v;
            m[hh] = fmaxf(m[hh], v);
        }
    }
    // butterfly max (no expf)
    #pragma unroll
    for (int o = 16; o; o >>= 1) {
        #pragma unroll
        for (int hh = 0; hh < H; ++hh)
            m[hh] = fmaxf(m[hh], __shfl_xor_sync(0xffffffffu, m[hh], o));
    }

    int deg = end - beg;
    int cap = deg < CAP ? deg : CAP;
    int nk;
    float den[H];
    #pragma unroll
    for (int hh = 0; hh < H; ++hh) den[hh] = 0.f;

    if (MASKED) {
        // convert + accumulate den + warp-compact surviving edges
        nk = 0;
        for (int j0 = 0; j0 < cap; j0 += 32) {
            int j = j0 + lane;
            bool have = (j < cap);
            float exH[H]; int s = 0;
            bool keep = false;
            if (have) {
                s = sSr[wid][j];
                #pragma unroll
                for (int hh = 0; hh < H; ++hh) {
                    float ex = __expf(sAl[wid][j * H + hh] - m[hh]);
                    exH[hh] = ex;
                    den[hh] += ex;
                    keep = keep || (ex > 0.f);
                }
            }
            unsigned bal = __ballot_sync(0xffffffffu, keep);
            int pos = nk + __popc(bal & ((1u << lane) - 1u));
            if (keep) {
                sSc[wid][pos] = s;
                #pragma unroll
                for (int hh = 0; hh < H; ++hh) sAc[wid][pos * H + hh] = exH[hh];
            }
            nk += __popc(bal);
        }
    } else {
        // convert in place + accumulate den
        for (int j = lane; j < cap; j += 32) {
            #pragma unroll
            for (int hh = 0; hh < H; ++hh) {
                float ex = __expf(sAl[wid][j * H + hh] - m[hh]);
                sAl[wid][j * H + hh] = ex;
                den[hh] += ex;
            }
        }
        nk = cap;
    }
    // tail edges beyond CAP also contribute to den (recompute path)
    for (int i = beg + CAP + lane; i < end; i += 32) {
        int s = g_csrc[i];
        float4 av = g_alsv[s];
        float avh[3] = {av.x, av.y, av.z};
        #pragma unroll
        for (int hh = 0; hh < H; ++hh)
            den[hh] += __expf(lrelu(avh[hh] + ald_d[hh]) - m[hh]);
    }
    // butterfly den sum (adds only)
    #pragma unroll
    for (int o = 16; o; o >>= 1) {
        #pragma unroll
        for (int hh = 0; hh < H; ++hh)
            den[hh] += __shfl_xor_sync(0xffffffffu, den[hh], o);
    }
    __syncwarp();

    int hh0 = c0 / C;
    float m_my = m[0], den_my = den[0];
    #pragma unroll
    for (int hh = 1; hh < H; ++hh)
        if (hh == hh0) { m_my = m[hh]; den_my = den[hh]; }
    float inv_my = 1.f / fmaxf(den_my, 1e-16f);
    float ald_my = ald_d[0];
    #pragma unroll
    for (int hh = 1; hh < H; ++hh)
        if (hh == hh0) ald_my = ald_d[hh];

    // phase B: each group walks edges grp, grp+NG, ...; unnormalized ex
    float accx = 0.f, accy = 0.f;
    if (act) {
        #pragma unroll 8
        for (int j = grp; j < nk; j += NG) {
            float a = MASKED ? sAc[wid][j * H + hh0] : sAl[wid][j * H + hh0];
            int s = MASKED ? sSc[wid][j] : sSr[wid][j];
            float2 hv = *(const float2*)(h + (size_t)s * HC + c0);
            accx += a * hv.x;
            accy += a * hv.y;
        }
    }
    // tail for deg > CAP (vanishingly rare)
    for (int i = beg + CAP + grp; i < end; i += NG) {
        int s = g_csrc[i];
        float4 av = g_alsv[s];
        float avh[3] = {av.x, av.y, av.z};
        float a = __expf(lrelu(avh[hh0] + ald_my) - m_my);
        if (a > 0.f && act) {
            float2 hv = *(const float2*)(h + (size_t)s * HC + c0);
            accx += a * hv.x;
            accy += a * hv.y;
        }
    }
    // merge groups, then normalize once
    #pragma unroll
    for (int o = GSZ; o < 32; o <<= 1) {
        accx += __shfl_xor_sync(0xffffffffu, accx, o);
        accy += __shfl_xor_sync(0xffffffffu, accy, o);
    }
    if (wlane) *(float2*)(out + (size_t)d * HC + c0) =
        make_float2(accx * inv_my + b[c0], accy * inv_my + b[c0 + 1]);
}

// ---------------- TopK pooling (float2-vectorized; F must be even) --------
__global__ void k_topk(float* __restrict__ x, const float* __restrict__ p,
                       int F, int kkeep) {
    __shared__ float ss[NPERG];
    __shared__ int   wsum[32];
    __shared__ int   wsex[32];
    __shared__ float s_thr;
    __shared__ int   s_need;
    int g = blockIdx.x;
    int base = g * NPERG;
    int tid = threadIdx.x;
    int lane = tid & 31, wid = tid >> 5;
    int F2 = F >> 1;
    const float2* p2 = (const float2*)p;

    float nrm = 0.f;
    for (int i = 0; i < F2; ++i) { float2 pv = p2[i]; nrm += pv.x * pv.x + pv.y * pv.y; }
    nrm = rsqrtf(nrm);

    for (int n = tid; n < NPERG; n += blockDim.x) {
        int node = base + n;
        const float2* xr = (const float2*)(x + (size_t)node * F);
        float sc = 0.f;
        for (int i = 0; i < F2; ++i) {
            float2 xv = xr[i], pv = p2[i];
            sc += xv.x * pv.x + xv.y * pv.y;
        }
        sc *= nrm;
        g_score[node] = sc;
        ss[n] = g_nmask[node] ? sc : NEGV;
    }
    __syncthreads();

    for (int kk = 2; kk <= NPERG; kk <<= 1) {
        for (int j = kk >> 1; j > 0; j >>= 1) {
            for (int i = tid; i < NPERG; i += blockDim.x) {
                int ixj = i ^ j;
                if (ixj > i) {
                    float a = ss[i], bb = ss[ixj];
                    bool up = ((i & kk) == 0);
                    if ((a > bb) == up) { ss[i] = bb; ss[ixj] = a; }
                }
            }
            __syncthreads();
        }
    }

    if (tid == 0) {
        float thr = ss[NPERG - kkeep];
        int lo = NPERG - kkeep, hi = NPERG;
        while (lo < hi) {
            int mid = (lo + hi) >> 1;
            if (ss[mid] > thr) hi = mid; else lo = mid + 1;
        }
        s_thr = thr;
        s_need = kkeep - (NPERG - lo);
    }
    __syncthreads();
    float thr = s_thr;
    int need_eq = s_need;

    int n0 = tid * 2, n1 = n0 + 1;
    float sc0 = g_nmask[base + n0] ? g_score[base + n0] : NEGV;
    float sc1 = g_nmask[base + n1] ? g_score[base + n1] : NEGV;
    int f0 = (sc0 == thr) ? 1 : 0;
    int f1 = (sc1 == thr) ? 1 : 0;
    int lsum = f0 + f1;
    int incl = lsum;
    #pragma unroll
    for (int o = 1; o < 32; o <<= 1) {
        int t = __shfl_up_sync(0xffffffffu, incl, o);
        if (lane >= o) incl += t;
    }
    if (lane == 31) wsum[wid] = incl;
    __syncthreads();
    if (wid == 0) {
        int v = wsum[lane];
        int inc2 = v;
        #pragma unroll
        for (int o = 1; o < 32; o <<= 1) {
            int t = __shfl_up_sync(0xffffffffu, inc2, o);
            if (lane >= o) inc2 += t;
        }
        wsex[lane] = inc2 - v;
    }
    __syncthreads();
    int rank0 = wsex[wid] + (incl - lsum);
    int rank1 = rank0 + f0;

    int keep0 = (sc0 > thr) || (f0 && rank0 < need_eq);
    int keep1 = (sc1 > thr) || (f1 && rank1 < need_eq);

    g_nmask[base + n0] = keep0;
    g_nmask[base + n1] = keep1;
    float t0 = keep0 ? tanhf(g_score[base + n0]) : 0.f;
    float t1 = keep1 ? tanhf(g_score[base + n1]) : 0.f;
    float2* xr0 = (float2*)(x + (size_t)(base + n0) * F);
    float2* xr1 = (float2*)(x + (size_t)(base + n1) * F);
    for (int i = 0; i < F2; ++i) { float2 v = xr0[i]; v.x *= t0; v.y *= t0; xr0[i] = v; }
    for (int i = 0; i < F2; ++i) { float2 v = xr1[i]; v.x *= t1; v.y *= t1; xr1[i] = v; }
}

// ---------------- final mean + log_softmax ----------------
__global__ void k_final(const float* __restrict__ x, float* __restrict__ out) {
    __shared__ float red[NCLS][9];
    int g = blockIdx.x;
    int base = g * NPERG;
    float acc[NCLS];
    for (int c = 0; c < NCLS; ++c) acc[c] = 0.f;
    for (int n = threadIdx.x; n < NPERG; n += blockDim.x) {
        const float2* xr = (const float2*)(x + (size_t)(base + n) * NCLS);
        #pragma unroll
        for (int c = 0; c < NCLS / 2; ++c) {
            float2 v = xr[c];
            acc[2 * c] += v.x;
            acc[2 * c + 1] += v.y;
        }
    }
    for (int off = 16; off; off >>= 1)
        for (int c = 0; c < NCLS; ++c)
            acc[c] += __shfl_down_sync(0xffffffffu, acc[c], off);
    int lane = threadIdx.x & 31, wid = threadIdx.x >> 5;
    if (lane == 0)
        for (int c = 0; c < NCLS; ++c) red[c][wid] = acc[c];
    __syncthreads();
    if (threadIdx.x == 0) {
        int nw = blockDim.x / 32;
        float z[NCLS];
        for (int c = 0; c < NCLS; ++c) {
            float s = 0.f;
            for (int w = 0; w < nw; ++w) s += red[c][w];
            z[c] = s * (1.f / (NPERG / 4));
        }
        float mx = z[0];
        for (int c = 1; c < NCLS; ++c) mx = fmaxf(mx, z[c]);
        float se = 0.f;
        for (int c = 0; c < NCLS; ++c) se += expf(z[c] - mx);
        float lse = logf(se) + mx;
        for (int c = 0; c < NCLS; ++c) out[g * NCLS + c] = z[c] - lse;
    }
}

// ---------------- host orchestration ----------------
extern "C" void kernel_launch(void* const* d_in, const int* in_sizes, int n_in,
                              void* d_out, int out_size) {
    const float* x     = (const float*)d_in[0];
    const int*   ei    = (const int*)  d_in[1];
    const float* gamma = (const float*)d_in[3];
    const float* beta  = (const float*)d_in[4];
    const float* W1  = (const float*)d_in[5];
    const float* as1 = (const float*)d_in[6];
    const float* ad1 = (const float*)d_in[7];
    const float* b1  = (const float*)d_in[8];
    const float* W2  = (const float*)d_in[9];
    const float* as2 = (const float*)d_in[10];
    const float* ad2 = (const float*)d_in[11];
    const float* b2  = (const float*)d_in[12];
    const float* W3  = (const float*)d_in[13];
    const float* as3 = (const float*)d_in[14];
    const float* ad3 = (const float*)d_in[15];
    const float* b3  = (const float*)d_in[16];
    const float* W4  = (const float*)d_in[17];
    const float* as4 = (const float*)d_in[18];
    const float* ad4 = (const float*)d_in[19];
    const float* b4  = (const float*)d_in[20];
    const float* p1  = (const float*)d_in[21];
    const float* p2  = (const float*)d_in[22];

    int E = in_sizes[1] / 2;
    const int* src = ei;
    const int* dst = ei + E;
    int Etot = E + NTN;
    int eb = (Etot + 255) / 256;

    float *h, *oa, *ob;
    cudaGetSymbolAddress((void**)&h,  g_h);
    cudaGetSymbolAddress((void**)&oa, g_oa);
    cudaGetSymbolAddress((void**)&ob, g_ob);

    int lingrid4 = NTN / 32;        // 8 warps/block x 4 rows/warp (conv1)
    int lingrid8 = NTN / 64;        // 8 warps/block x 8 rows/warp (small convs)
    int gatgrid = NTN * 32 / 256;   // warp per dst node

    k_stats<<<128, 128>>>(x);                                      // 0
    k_deg_bnc<<<eb + 1, 256>>>(dst, E, Etot, gamma, beta);         // 1
    k_scan_block<<<256, 256>>>();                                  // 2
    k_lin<NFEAT, 3, 16, 4, true><<<lingrid4, 256>>>(x, W1, as1, ad1, h); // 3 <- ncu
    k_scan_add2<<<256, 256>>>(Etot);                               // 4
    k_scatter<<<eb, 256>>>(src, dst, E, Etot);                     // 5
    k_gat<3, 16, false, 1><<<gatgrid, 256>>>(h, b1, oa);           // 6

    k_lin<48, 3, 16, 8, false><<<lingrid8, 256>>>(oa, W2, as2, ad2, h);
    k_gat<3, 16, false, 1><<<gatgrid, 256>>>(h, b2, ob);
    k_topk<<<NBATCH, 1024>>>(ob, p1, 48, NPERG / 2);
    k_lin<48, 2, 16, 8, false><<<lingrid8, 256>>>(ob, W3, as3, ad3, h);
    k_gat<2, 16, true, 2><<<gatgrid, 256>>>(h, b3, oa);
    k_lin<32, 1, 10, 8, false><<<lingrid8, 256>>>(oa, W4, as4, ad4, h);
    k_gat<1, 10, true, 4><<<gatgrid, 256>>>(h, b4, ob);
    k_topk<<<NBATCH, 1024>>>(ob, p2, 10, NPERG / 4);
    k_final<<<NBATCH, 256>>>(ob, (float*)d_out);
}

// round 15
// speedup vs baseline: 2.9567x; 1.0446x over previous
#include <cuda_runtime.h>
#include <math.h>

#define NTN   65536
#define NBATCH 32
#define NPERG 2048
#define NFEAT 128
#define NCLS  10
#define NEGV  (-1e9f)
#define MASKV (-1e30f)
#define ETOTMAX (NTN * 16 + NTN)   // 1,114,112 edges incl self loops
#define NLIVE1 (NTN / 2)           // live nodes after pool1 (exactly half)

// ---------------- scratch (device globals; no allocation allowed) ----------
__device__ float  g_h [NTN * 48];      // per-conv linear output (max HC=48)
__device__ float  g_oa[NTN * 48];      // ping buffer
__device__ float  g_ob[NTN * 48];      // pong buffer
__device__ float4 g_alsv[NTN];         // src logits, heads in .x/.y/.z (MASKV = masked)
__device__ float  g_ald[NTN * 3];      // dst logits
__device__ float  g_score[NTN];        // topk raw scores
__device__ int    g_nmask[NTN];        // node mask
__device__ int    g_live[NTN];         // compacted live-node list (pool1)
__device__ float  g_psum [128 * NFEAT];  // BN partial sums
__device__ float  g_psq  [128 * NFEAT];
__device__ float  g_bnc  [2 * NFEAT];    // BN affine: scale[0:128], shift[128:256]
// CSR (built once per launch)
__device__ int g_deg [NTN];
__device__ int g_off [NTN + 1];
__device__ int g_cur [NTN];
__device__ int g_bsum[256];
__device__ int g_csrc[ETOTMAX];

__device__ __forceinline__ float lrelu(float v) { return v > 0.f ? v : 0.2f * v; }

// ---------------- BN partial stats + zero degrees + mask init ----------------
__global__ void k_stats(const float* __restrict__ x) {
    int f = threadIdx.x;                       // 128 threads
    int b = blockIdx.x;                        // 128 blocks
    int r0 = b * (NTN / 128);
    float s = 0.f, s2 = 0.f;
    for (int r = r0; r < r0 + NTN / 128; ++r) {
        float v = x[r * NFEAT + f];
        s += v; s2 += v * v;
    }
    g_psum[b * NFEAT + f] = s;
    g_psq [b * NFEAT + f] = s2;
    int gid = b * 128 + f;
    for (int i = gid; i < NTN; i += 128 * 128) { g_deg[i] = 0; g_nmask[i] = 1; }
}

// ---------------- degree count + BN coefficient reduce (fused) -------------
__global__ void k_deg_bnc(const int* __restrict__ dst, int E, int Etot,
                          const float* __restrict__ gamma, const float* __restrict__ beta) {
    if (blockIdx.x == gridDim.x - 1) {
        int f = threadIdx.x;
        if (f < NFEAT) {
            float s = 0.f, s2 = 0.f;
            for (int b = 0; b < 128; ++b) {
                s  += g_psum[b * NFEAT + f];
                s2 += g_psq [b * NFEAT + f];
            }
            float mu  = s  * (1.f / NTN);
            float var = s2 * (1.f / NTN) - mu * mu;
            float rstd = rsqrtf(var + 1e-5f);
            float ga = gamma[f];
            g_bnc[f]         = ga * rstd;
            g_bnc[NFEAT + f] = beta[f] - mu * ga * rstd;
        }
        return;
    }
    int e = blockIdx.x * blockDim.x + threadIdx.x;
    if (e >= Etot) return;
    int d = (e < E) ? dst[e] : (e - E);
    atomicAdd(&g_deg[d], 1);
}

// ---------------- hierarchical scan of degrees ----------------
__global__ void k_scan_block() {            // 256 blocks x 256 threads
    __shared__ int sh[256];
    int n = blockIdx.x * 256 + threadIdx.x;
    int v = g_deg[n];
    sh[threadIdx.x] = v;
    __syncthreads();
    for (int o = 1; o < 256; o <<= 1) {
        int t = (threadIdx.x >= o) ? sh[threadIdx.x - o] : 0;
        __syncthreads();
        sh[threadIdx.x] += t;
        __syncthreads();
    }
    g_off[n] = sh[threadIdx.x] - v;
    if (threadIdx.x == 255) g_bsum[blockIdx.x] = sh[255];
}

__global__ void k_scan_add2(int Etot) {     // 256 blocks x 256 threads
    __shared__ int sh[256];
    int t = threadIdx.x;
    sh[t] = g_bsum[t];
    __syncthreads();
    for (int o = 1; o < 256; o <<= 1) {
        int v = (t >= o) ? sh[t - o] : 0;
        __syncthreads();
        sh[t] += v;
        __syncthreads();
    }
    int bsex = (blockIdx.x > 0) ? sh[blockIdx.x - 1] : 0;   // broadcast read
    int n = blockIdx.x * 256 + t;
    int o2 = g_off[n] + bsex;
    g_off[n] = o2;
    g_cur[n] = o2;
    if (n == 0) g_off[NTN] = Etot;
}

// ---------------- scatter edges into CSR ----------------
__global__ void k_scatter(const int* __restrict__ src, const int* __restrict__ dst,
                          int E, int Etot) {
    int e = blockIdx.x * blockDim.x + threadIdx.x;
    if (e >= Etot) return;
    int s, d;
    if (e < E) { s = src[e]; d = dst[e]; } else { s = e - E; d = s; }
    int pos = atomicAdd(&g_cur[d], 1);
    g_csrc[pos] = s;
}

// ---------------- fused (BN +) linear + attention logits ----------------
// IDX: rows indirected through g_live (post-pool convs run live rows only).
template <int Fin, int H, int C, int RW, bool BNF, bool IDX>
__global__ __launch_bounds__(256) void k_lin(const float* __restrict__ xin,
                                             const float* __restrict__ W,
                                             const float* __restrict__ a_s,
                                             const float* __restrict__ a_d,
                                             float* __restrict__ h) {
    constexpr int HC = H * C;
    constexpr int FV = Fin / 4;
    __shared__ float Ws[Fin * HC];
    __shared__ float xs[8][RW * Fin];
    __shared__ float asv[HC], adv[HC];
    __shared__ float sg[BNF ? NFEAT : 1], sb[BNF ? NFEAT : 1];
    int tid = threadIdx.x, lane = tid & 31, wid = tid >> 5;
    for (int i = tid; i < Fin * HC; i += 256) Ws[i] = W[i];
    if (tid < HC) { asv[tid] = a_s[tid]; adv[tid] = a_d[tid]; }
    if (BNF && tid < NFEAT) {
        sg[tid] = g_bnc[tid];
        sb[tid] = g_bnc[NFEAT + tid];
    }
    __syncthreads();

    int rbase = (blockIdx.x * 8 + wid) * RW;
    int c0 = 2 * lane;
    bool act = (c0 < HC);

    // cooperative load of RW rows (+ BN affine for conv1)
    float4* xs4 = (float4*)xs[wid];
    for (int t = lane; t < RW * FV; t += 32) {
        int r = t / FV, off = t - r * FV;
        int row = IDX ? g_live[rbase + r] : (rbase + r);
        float4 v = ((const float4*)(xin + (size_t)row * Fin))[off];
        if (BNF) {
            int f0 = (off * 4) & (Fin - 1);
            v.x = v.x * sg[f0]     + sb[f0];
            v.y = v.y * sg[f0 + 1] + sb[f0 + 1];
            v.z = v.z * sg[f0 + 2] + sb[f0 + 2];
            v.w = v.w * sg[f0 + 3] + sb[f0 + 3];
        }
        xs4[t] = v;
    }
    __syncwarp();

    float ax[RW], ay[RW];
    #pragma unroll
    for (int r = 0; r < RW; ++r) { ax[r] = 0.f; ay[r] = 0.f; }

    if (act) {
        #pragma unroll 4
        for (int i0 = 0; i0 < Fin; i0 += 4) {
            float2 w0 = *(const float2*)&Ws[(i0 + 0) * HC + c0];
            float2 w1 = *(const float2*)&Ws[(i0 + 1) * HC + c0];
            float2 w2 = *(const float2*)&Ws[(i0 + 2) * HC + c0];
            float2 w3 = *(const float2*)&Ws[(i0 + 3) * HC + c0];
            #pragma unroll
            for (int r = 0; r < RW; ++r) {
                float4 xv = *(const float4*)&xs[wid][r * Fin + i0];
                ax[r] += xv.x * w0.x; ay[r] += xv.x * w0.y;
                ax[r] += xv.y * w1.x; ay[r] += xv.y * w1.y;
                ax[r] += xv.z * w2.x; ay[r] += xv.z * w2.y;
                ax[r] += xv.w * w3.x; ay[r] += xv.w * w3.y;
            }
        }
        #pragma unroll
        for (int r = 0; r < RW; ++r) {
            int row = IDX ? g_live[rbase + r] : (rbase + r);
            *(float2*)(h + (size_t)row * HC + c0) = make_float2(ax[r], ay[r]);
        }
    }

    #pragma unroll
    for (int r = 0; r < RW; ++r) {
        float ps = 0.f, pd = 0.f;
        if (act) {
            ps = ax[r] * asv[c0] + ay[r] * asv[c0 + 1];
            pd = ax[r] * adv[c0] + ay[r] * adv[c0 + 1];
        }
        if (C == 16) {
            #pragma unroll
            for (int o = 4; o; o >>= 1) {
                ps += __shfl_xor_sync(0xffffffffu, ps, o);
                pd += __shfl_xor_sync(0xffffffffu, pd, o);
            }
        } else {
            #pragma unroll
            for (int o = 16; o; o >>= 1) {
                ps += __shfl_xor_sync(0xffffffffu, ps, o);
                pd += __shfl_xor_sync(0xffffffffu, pd, o);
            }
        }
        float p1 = __shfl_sync(0xffffffffu, ps, 8);
        float p2 = __shfl_sync(0xffffffffu, ps, 16);
        float d1 = __shfl_sync(0xffffffffu, pd, 8);
        float d2 = __shfl_sync(0xffffffffu, pd, 16);
        if (lane == 0) {
            int rr = IDX ? g_live[rbase + r] : (rbase + r);
            int msk = IDX ? 1 : g_nmask[rr];
            if (H == 3) {
                g_alsv[rr] = msk ? make_float4(ps, p1, p2, 0.f)
                                 : make_float4(MASKV, MASKV, MASKV, 0.f);
                g_ald[rr * 3]     = pd;
                g_ald[rr * 3 + 1] = d1;
                g_ald[rr * 3 + 2] = d2;
            } else if (H == 2) {
                g_alsv[rr] = msk ? make_float4(ps, p1, 0.f, 0.f)
                                 : make_float4(MASKV, MASKV, 0.f, 0.f);
                g_ald[rr * 3]     = pd;
                g_ald[rr * 3 + 1] = d1;
            } else {
                g_alsv[rr] = msk ? make_float4(ps, 0.f, 0.f, 0.f)
                                 : make_float4(MASKV, 0.f, 0.f, 0.f);
                g_ald[rr * 3] = pd;
            }
        }
    }
}

// ---------------- fused attention softmax + aggregation ----------------
// warp per dst node (direct or via live list). Deferred-normalization softmax.
// MASKED: src may be dead -> ballot-compacted ex list.
// LIVE:   dsts come from g_live (all live; no dst-mask check).
template <int H, int C, bool MASKED, int NG, bool LIVE>
__global__ __launch_bounds__(256) void k_gat(const float* __restrict__ h,
                                             const float* __restrict__ b,
                                             float* __restrict__ out) {
    constexpr int HC = H * C;
    constexpr int CAP = 64;
    constexpr int GSZ = 32 / NG;
    __shared__ float sAl[8][CAP * H + 1];
    __shared__ int   sSr[8][CAP + 1];
    __shared__ float sAc[MASKED ? 8 : 1][MASKED ? (CAP * H + 1) : 1];
    __shared__ int   sSc[MASKED ? 8 : 1][MASKED ? (CAP + 1) : 1];
    int widx = (blockIdx.x * blockDim.x + threadIdx.x) >> 5;
    if (!LIVE && widx >= NTN) return;
    int d = LIVE ? g_live[widx] : widx;
    int lane = threadIdx.x & 31;
    int wid = (threadIdx.x >> 5) & 7;
    int grp = lane / GSZ;
    int lc  = lane & (GSZ - 1);
    int c0 = 2 * lc;
    bool act = (c0 < HC);
    bool wlane = (grp == 0) && act;

    if (!LIVE && MASKED && !g_nmask[d]) {
        if (wlane) *(float2*)(out + (size_t)d * HC + c0) = make_float2(b[c0], b[c0 + 1]);
        return;
    }

    int beg = g_off[d], end = g_off[d + 1];
    float ald_d[H], m[H];
    #pragma unroll
    for (int hh = 0; hh < H; ++hh) {
        ald_d[hh] = g_ald[d * 3 + hh];
        m[hh] = NEGV;
    }

    // phase A: gather logits, cache to smem, track max
    for (int i = beg + lane; i < end; i += 32) {
        int j = i - beg;
        int s = g_csrc[i];
        float4 av = g_alsv[s];
        float avh[3] = {av.x, av.y, av.z};
        if (j < CAP) sSr[wid][j] = s;
        #pragma unroll
        for (int hh = 0; hh < H; ++hh) {
            float v = lrelu(avh[hh] + ald_d[hh]);
            if (j < CAP) sAl[wid][j * H + hh] = v;
            m[hh] = fmaxf(m[hh], v);
        }
    }
    #pragma unroll
    for (int o = 16; o; o >>= 1) {
        #pragma unroll
        for (int hh = 0; hh < H; ++hh)
            m[hh] = fmaxf(m[hh], __shfl_xor_sync(0xffffffffu, m[hh], o));
    }

    int deg = end - beg;
    int cap = deg < CAP ? deg : CAP;
    int nk;
    float den[H];
    #pragma unroll
    for (int hh = 0; hh < H; ++hh) den[hh] = 0.f;

    if (MASKED) {
        nk = 0;
        for (int j0 = 0; j0 < cap; j0 += 32) {
            int j = j0 + lane;
            bool have = (j < cap);
            float exH[H]; int s = 0;
            bool keep = false;
            if (have) {
                s = sSr[wid][j];
                #pragma unroll
                for (int hh = 0; hh < H; ++hh) {
                    float ex = __expf(sAl[wid][j * H + hh] - m[hh]);
                    exH[hh] = ex;
                    den[hh] += ex;
                    keep = keep || (ex > 0.f);
                }
            }
            unsigned bal = __ballot_sync(0xffffffffu, keep);
            int pos = nk + __popc(bal & ((1u << lane) - 1u));
            if (keep) {
                sSc[wid][pos] = s;
                #pragma unroll
                for (int hh = 0; hh < H; ++hh) sAc[wid][pos * H + hh] = exH[hh];
            }
            nk += __popc(bal);
        }
    } else {
        for (int j = lane; j < cap; j += 32) {
            #pragma unroll
            for (int hh = 0; hh < H; ++hh) {
                float ex = __expf(sAl[wid][j * H + hh] - m[hh]);
                sAl[wid][j * H + hh] = ex;
                den[hh] += ex;
            }
        }
        nk = cap;
    }
    for (int i = beg + CAP + lane; i < end; i += 32) {
        int s = g_csrc[i];
        float4 av = g_alsv[s];
        float avh[3] = {av.x, av.y, av.z};
        #pragma unroll
        for (int hh = 0; hh < H; ++hh)
            den[hh] += __expf(lrelu(avh[hh] + ald_d[hh]) - m[hh]);
    }
    #pragma unroll
    for (int o = 16; o; o >>= 1) {
        #pragma unroll
        for (int hh = 0; hh < H; ++hh)
            den[hh] += __shfl_xor_sync(0xffffffffu, den[hh], o);
    }
    __syncwarp();

    int hh0 = c0 / C;
    float m_my = m[0], den_my = den[0];
    #pragma unroll
    for (int hh = 1; hh < H; ++hh)
        if (hh == hh0) { m_my = m[hh]; den_my = den[hh]; }
    float inv_my = 1.f / fmaxf(den_my, 1e-16f);
    float ald_my = ald_d[0];
    #pragma unroll
    for (int hh = 1; hh < H; ++hh)
        if (hh == hh0) ald_my = ald_d[hh];

    float accx = 0.f, accy = 0.f;
    if (act) {
        #pragma unroll 8
        for (int j = grp; j < nk; j += NG) {
            float a = MASKED ? sAc[wid][j * H + hh0] : sAl[wid][j * H + hh0];
            int s = MASKED ? sSc[wid][j] : sSr[wid][j];
            float2 hv = *(const float2*)(h + (size_t)s * HC + c0);
            accx += a * hv.x;
            accy += a * hv.y;
        }
    }
    for (int i = beg + CAP + grp; i < end; i += NG) {
        int s = g_csrc[i];
        float4 av = g_alsv[s];
        float avh[3] = {av.x, av.y, av.z};
        float a = __expf(lrelu(avh[hh0] + ald_my) - m_my);
        if (a > 0.f && act) {
            float2 hv = *(const float2*)(h + (size_t)s * HC + c0);
            accx += a * hv.x;
            accy += a * hv.y;
        }
    }
    #pragma unroll
    for (int o = GSZ; o < 32; o <<= 1) {
        accx += __shfl_xor_sync(0xffffffffu, accx, o);
        accy += __shfl_xor_sync(0xffffffffu, accy, o);
    }
    if (wlane) *(float2*)(out + (size_t)d * HC + c0) =
        make_float2(accx * inv_my + b[c0], accy * inv_my + b[c0 + 1]);
}

// ---------------- TopK pooling (float2-vectorized; F even) ----------------
// do_live: also emit compacted live list + MASKV alsv sentinel for dropped.
__global__ void k_topk(float* __restrict__ x, const float* __restrict__ p,
                       int F, int kkeep, int do_live) {
    __shared__ float ss[NPERG];
    __shared__ int   wsum[32];
    __shared__ int   wsex[32];
    __shared__ float s_thr;
    __shared__ int   s_need;
    int g = blockIdx.x;
    int base = g * NPERG;
    int tid = threadIdx.x;
    int lane = tid & 31, wid = tid >> 5;
    int F2 = F >> 1;
    const float2* p2 = (const float2*)p;

    float nrm = 0.f;
    for (int i = 0; i < F2; ++i) { float2 pv = p2[i]; nrm += pv.x * pv.x + pv.y * pv.y; }
    nrm = rsqrtf(nrm);

    for (int n = tid; n < NPERG; n += blockDim.x) {
        int node = base + n;
        const float2* xr = (const float2*)(x + (size_t)node * F);
        float sc = 0.f;
        for (int i = 0; i < F2; ++i) {
            float2 xv = xr[i], pv = p2[i];
            sc += xv.x * pv.x + xv.y * pv.y;
        }
        sc *= nrm;
        g_score[node] = sc;
        ss[n] = g_nmask[node] ? sc : NEGV;
    }
    __syncthreads();

    for (int kk = 2; kk <= NPERG; kk <<= 1) {
        for (int j = kk >> 1; j > 0; j >>= 1) {
            for (int i = tid; i < NPERG; i += blockDim.x) {
                int ixj = i ^ j;
                if (ixj > i) {
                    float a = ss[i], bb = ss[ixj];
                    bool up = ((i & kk) == 0);
                    if ((a > bb) == up) { ss[i] = bb; ss[ixj] = a; }
                }
            }
            __syncthreads();
        }
    }

    if (tid == 0) {
        float thr = ss[NPERG - kkeep];
        int lo = NPERG - kkeep, hi = NPERG;
        while (lo < hi) {
            int mid = (lo + hi) >> 1;
            if (ss[mid] > thr) hi = mid; else lo = mid + 1;
        }
        s_thr = thr;
        s_need = kkeep - (NPERG - lo);
    }
    __syncthreads();
    float thr = s_thr;
    int need_eq = s_need;

    int n0 = tid * 2, n1 = n0 + 1;
    float sc0 = g_nmask[base + n0] ? g_score[base + n0] : NEGV;
    float sc1 = g_nmask[base + n1] ? g_score[base + n1] : NEGV;
    int f0 = (sc0 == thr) ? 1 : 0;
    int f1 = (sc1 == thr) ? 1 : 0;
    int lsum = f0 + f1;
    int incl = lsum;
    #pragma unroll
    for (int o = 1; o < 32; o <<= 1) {
        int t = __shfl_up_sync(0xffffffffu, incl, o);
        if (lane >= o) incl += t;
    }
    if (lane == 31) wsum[wid] = incl;
    __syncthreads();
    if (wid == 0) {
        int v = wsum[lane];
        int inc2 = v;
        #pragma unroll
        for (int o = 1; o < 32; o <<= 1) {
            int t = __shfl_up_sync(0xffffffffu, inc2, o);
            if (lane >= o) inc2 += t;
        }
        wsex[lane] = inc2 - v;
    }
    __syncthreads();
    int rank0 = wsex[wid] + (incl - lsum);
    int rank1 = rank0 + f0;

    int keep0 = (sc0 > thr) || (f0 && rank0 < need_eq);
    int keep1 = (sc1 > thr) || (f1 && rank1 < need_eq);

    // second scan: compact kept nodes into g_live (node order)
    if (do_live) {
        int ksum = keep0 + keep1;
        int kincl = ksum;
        #pragma unroll
        for (int o = 1; o < 32; o <<= 1) {
            int t = __shfl_up_sync(0xffffffffu, kincl, o);
            if (lane >= o) kincl += t;
        }
        __syncthreads();              // everyone done reading wsex from scan 1
        if (lane == 31) wsum[wid] = kincl;
        __syncthreads();
        if (wid == 0) {
            int v = wsum[lane];
            int inc2 = v;
            #pragma unroll
            for (int o = 1; o < 32; o <<= 1) {
                int t = __shfl_up_sync(0xffffffffu, inc2, o);
                if (lane >= o) inc2 += t;
            }
            wsex[lane] = inc2 - v;
        }
        __syncthreads();
        int kr0 = wsex[wid] + (kincl - ksum);
        int kr1 = kr0 + keep0;
        if (keep0) g_live[g * kkeep + kr0] = base + n0;
        else       g_alsv[base + n0] = make_float4(MASKV, MASKV, MASKV, 0.f);
        if (keep1) g_live[g * kkeep + kr1] = base + n1;
        else       g_alsv[base + n1] = make_float4(MASKV, MASKV, MASKV, 0.f);
    }

    g_nmask[base + n0] = keep0;
    g_nmask[base + n1] = keep1;
    float t0 = keep0 ? tanhf(g_score[base + n0]) : 0.f;
    float t1 = keep1 ? tanhf(g_score[base + n1]) : 0.f;
    float2* xr0 = (float2*)(x + (size_t)(base + n0) * F);
    float2* xr1 = (float2*)(x + (size_t)(base + n1) * F);
    for (int i = 0; i < F2; ++i) { float2 v = xr0[i]; v.x *= t0; v.y *= t0; xr0[i] = v; }
    for (int i = 0; i < F2; ++i) { float2 v = xr1[i]; v.x *= t1; v.y *= t1; xr1[i] = v; }
}

// ---------------- final mean + log_softmax ----------------
__global__ void k_final(const float* __restrict__ x, float* __restrict__ out) {
    __shared__ float red[NCLS][9];
    int g = blockIdx.x;
    int base = g * NPERG;
    float acc[NCLS];
    for (int c = 0; c < NCLS; ++c) acc[c] = 0.f;
    for (int n = threadIdx.x; n < NPERG; n += blockDim.x) {
        const float2* xr = (const float2*)(x + (size_t)(base + n) * NCLS);
        #pragma unroll
        for (int c = 0; c < NCLS / 2; ++c) {
            float2 v = xr[c];
            acc[2 * c] += v.x;
            acc[2 * c + 1] += v.y;
        }
    }
    for (int off = 16; off; off >>= 1)
        for (int c = 0; c < NCLS; ++c)
            acc[c] += __shfl_down_sync(0xffffffffu, acc[c], off);
    int lane = threadIdx.x & 31, wid = threadIdx.x >> 5;
    if (lane == 0)
        for (int c = 0; c < NCLS; ++c) red[c][wid] = acc[c];
    __syncthreads();
    if (threadIdx.x == 0) {
        int nw = blockDim.x / 32;
        float z[NCLS];
        for (int c = 0; c < NCLS; ++c) {
            float s = 0.f;
            for (int w = 0; w < nw; ++w) s += red[c][w];
            z[c] = s * (1.f / (NPERG / 4));
        }
        float mx = z[0];
        for (int c = 1; c < NCLS; ++c) mx = fmaxf(mx, z[c]);
        float se = 0.f;
        for (int c = 0; c < NCLS; ++c) se += expf(z[c] - mx);
        float lse = logf(se) + mx;
        for (int c = 0; c < NCLS; ++c) out[g * NCLS + c] = z[c] - lse;
    }
}

// ---------------- host orchestration ----------------
extern "C" void kernel_launch(void* const* d_in, const int* in_sizes, int n_in,
                              void* d_out, int out_size) {
    const float* x     = (const float*)d_in[0];
    const int*   ei    = (const int*)  d_in[1];
    const float* gamma = (const float*)d_in[3];
    const float* beta  = (const float*)d_in[4];
    const float* W1  = (const float*)d_in[5];
    const float* as1 = (const float*)d_in[6];
    const float* ad1 = (const float*)d_in[7];
    const float* b1  = (const float*)d_in[8];
    const float* W2  = (const float*)d_in[9];
    const float* as2 = (const float*)d_in[10];
    const float* ad2 = (const float*)d_in[11];
    const float* b2  = (const float*)d_in[12];
    const float* W3  = (const float*)d_in[13];
    const float* as3 = (const float*)d_in[14];
    const float* ad3 = (const float*)d_in[15];
    const float* b3  = (const float*)d_in[16];
    const float* W4  = (const float*)d_in[17];
    const float* as4 = (const float*)d_in[18];
    const float* ad4 = (const float*)d_in[19];
    const float* b4  = (const float*)d_in[20];
    const float* p1  = (const float*)d_in[21];
    const float* p2  = (const float*)d_in[22];

    int E = in_sizes[1] / 2;
    const int* src = ei;
    const int* dst = ei + E;
    int Etot = E + NTN;
    int eb = (Etot + 255) / 256;

    float *h, *oa, *ob;
    cudaGetSymbolAddress((void**)&h,  g_h);
    cudaGetSymbolAddress((void**)&oa, g_oa);
    cudaGetSymbolAddress((void**)&ob, g_ob);

    int lingrid4 = NTN / 32;            // conv1: warp per 4 rows
    int lingrid8 = NTN / 64;            // conv2: warp per 8 rows
    int lingridL = NLIVE1 / 64;         // conv3/4: live rows, warp per 8
    int gatgrid  = NTN * 32 / 256;      // warp per dst node (all nodes)
    int gatgridL = NLIVE1 * 32 / 256;   // warp per LIVE dst node

    k_stats<<<128, 128>>>(x);                                      // 0
    k_deg_bnc<<<eb + 1, 256>>>(dst, E, Etot, gamma, beta);         // 1
    k_scan_block<<<256, 256>>>();                                  // 2
    k_lin<NFEAT, 3, 16, 4, true, false><<<lingrid4, 256>>>(x, W1, as1, ad1, h); // 3 <- ncu
    k_scan_add2<<<256, 256>>>(Etot);                               // 4
    k_scatter<<<eb, 256>>>(src, dst, E, Etot);                     // 5
    k_gat<3, 16, false, 1, false><<<gatgrid, 256>>>(h, b1, oa);    // 6

    k_lin<48, 3, 16, 8, false, false><<<lingrid8, 256>>>(oa, W2, as2, ad2, h);
    k_gat<3, 16, false, 1, false><<<gatgrid, 256>>>(h, b2, ob);
    k_topk<<<NBATCH, 1024>>>(ob, p1, 48, NPERG / 2, 1);            // emits g_live
    k_lin<48, 2, 16, 8, false, true><<<lingridL, 256>>>(ob, W3, as3, ad3, h);
    k_gat<2, 16, true, 2, true><<<gatgridL, 256>>>(h, b3, oa);
    k_lin<32, 1, 10, 8, false, true><<<lingridL, 256>>>(oa, W4, as4, ad4, h);
    k_gat<1, 10, true, 4, true><<<gatgridL, 256>>>(h, b4, ob);
    k_topk<<<NBATCH, 1024>>>(ob, p2, 10, NPERG / 4, 0);
    k_final<<<NBATCH, 256>>>(ob, (float*)d_out);
}